// round 1
// baseline (speedup 1.0000x reference)
#include <cuda_runtime.h>
#include <math.h>

#define BB 32
#define TT 10

// ---------------- scratch (device globals; no allocs allowed) ----------------
__device__ float g_e1[320 * 16 * 64 * 64];   // encoder conv1 out
__device__ float g_e2[320 * 64 * 32 * 32];   // encoder conv2 out (GRU input)
__device__ float g_h [BB * 64 * 1024];       // GRU hidden state
__device__ float g_zr[BB * 128 * 1024];      // sigmoid(zr) per step
__device__ float g_rh[BB * 64 * 1024];       // r * h per step
__device__ float g_hs[TT * BB * 64 * 1024];  // decoder hidden outputs
__device__ float g_y1[320 * 32 * 64 * 64];   // deconv1 out

// ---------------- init ----------------
__global__ void zero_h_kernel() {
    int i = blockIdx.x * blockDim.x + threadIdx.x;
    if (i < BB * 64 * 1024) g_h[i] = 0.f;
}

// ---------------- encoder conv1: 1->16 ch, 3x3 s2 p1, 128->64, lrelu ----------------
__global__ __launch_bounds__(256) void enc_conv1(const float* __restrict__ x,
                                                 const float* __restrict__ w,
                                                 const float* __restrict__ bias) {
    __shared__ float sw[144];
    __shared__ float sb[16];
    int tid = threadIdx.x;
    if (tid < 144) sw[tid] = w[tid];
    if (tid < 16)  sb[tid] = bias[tid];
    __syncthreads();
    int n = blockIdx.x;                      // image 0..319 (= b*10+t)
    int p = blockIdx.y * 256 + tid;          // out pixel 0..4095
    int oy = p >> 6, ox = p & 63;
    const float* xi = x + n * 16384;
    float win[9];
    int iy0 = 2 * oy - 1, ix0 = 2 * ox - 1;
#pragma unroll
    for (int ky = 0; ky < 3; ky++)
#pragma unroll
        for (int kx = 0; kx < 3; kx++) {
            int iy = iy0 + ky, ix = ix0 + kx;
            win[ky * 3 + kx] = ((unsigned)iy < 128u && (unsigned)ix < 128u) ? xi[iy * 128 + ix] : 0.f;
        }
#pragma unroll
    for (int oc = 0; oc < 16; oc++) {
        float a = sb[oc];
#pragma unroll
        for (int k = 0; k < 9; k++) a += sw[oc * 9 + k] * win[k];
        g_e1[(n * 16 + oc) * 4096 + p] = (a >= 0.f) ? a : 0.2f * a;
    }
}

// ---------------- encoder conv2: 16->64 ch, 3x3 s2 p1, 64->32, lrelu ----------------
__global__ __launch_bounds__(256) void enc_conv2(const float* __restrict__ w,
                                                 const float* __restrict__ bias) {
    __shared__ float sw[64 * 16 * 9];        // 36.9 KB
    int tid = threadIdx.x;
    for (int i = tid; i < 9216; i += 256) sw[i] = w[i];
    __syncthreads();
    int n = blockIdx.x;
    int p = blockIdx.y * 256 + tid;          // 0..1023
    int oy = p >> 5, ox = p & 31;
    const float* in = g_e1 + n * 65536;
    float acc[64];
#pragma unroll
    for (int oc = 0; oc < 64; oc++) acc[oc] = bias[oc];
    int iy0 = 2 * oy - 1, ix0 = 2 * ox - 1;
#pragma unroll 1
    for (int ic = 0; ic < 16; ic++) {
        float win[9];
#pragma unroll
        for (int ky = 0; ky < 3; ky++)
#pragma unroll
            for (int kx = 0; kx < 3; kx++) {
                int iy = iy0 + ky, ix = ix0 + kx;
                win[ky * 3 + kx] = ((unsigned)iy < 64u && (unsigned)ix < 64u)
                                       ? in[ic * 4096 + iy * 64 + ix] : 0.f;
            }
#pragma unroll
        for (int oc = 0; oc < 64; oc++) {
#pragma unroll
            for (int k = 0; k < 9; k++) acc[oc] += sw[(oc * 16 + ic) * 9 + k] * win[k];
        }
    }
#pragma unroll
    for (int oc = 0; oc < 64; oc++) {
        float a = acc[oc];
        g_e2[(n * 64 + oc) * 1024 + p] = (a >= 0.f) ? a : 0.2f * a;
    }
}

// ---------------- generic GRU 5x5 conv (pad 2) on 32x32, fused epilogues ----------------
// src_mode: 0 = enc zr   (in: e2[t] ++ h,   128ch)
//           1 = enc cand (in: e2[t] ++ rh,  128ch)
//           2 = dec zr   (in: h,             64ch)
//           3 = dec cand (in: rh,            64ch)
// act_mode: 0 = sigmoid -> write g_zr, and g_rh = s * h for oc<64
//           1 = tanh    -> hn = (1-z)h + z*c -> write g_h (+ g_hs if write_hs)
// Weights always laid out [OC][128][5][5]; w_ico selects in-channel offset (dec uses 64).
__global__ __launch_bounds__(128) void gru_conv(int t, int src_mode,
                                                const float* __restrict__ w, int w_ico,
                                                const float* __restrict__ bias,
                                                int act_mode, int write_hs) {
    __shared__ float s_in[4 * 36 * 37];      // 4 in-ch chunk, 36x36 tile, stride 37 (conflict-free)
    __shared__ float s_w[8 * 4 * 25];
    int b   = blockIdx.x;
    int ocg = blockIdx.y;
    int tid = threadIdx.x;
    int row  = tid >> 2;                     // 0..31
    int col0 = (tid & 3) << 3;               // 0,8,16,24

    const float* s0;
    const float* s1;
    int n_ic;
    if (src_mode <= 1) {
        s0 = g_e2 + (b * 10 + t) * 65536;
        s1 = (src_mode == 0 ? g_h : g_rh) + b * 65536;
        n_ic = 128;
    } else {
        s0 = (src_mode == 2 ? g_h : g_rh) + b * 65536;
        s1 = s0;
        n_ic = 64;
    }

    float acc[8][8];
#pragma unroll
    for (int i = 0; i < 8; i++)
#pragma unroll
        for (int j = 0; j < 8; j++) acc[i][j] = 0.f;

    int nchunk = n_ic >> 2;
#pragma unroll 1
    for (int cc = 0; cc < nchunk; cc++) {
        int c0 = cc << 2;
        // stage input chunk (4 ch x 36x36 halo tile)
        for (int idx = tid; idx < 4 * 1296; idx += 128) {
            int ic  = idx / 1296;
            int rem = idx - ic * 1296;
            int r   = rem / 36;
            int cl  = rem - r * 36;
            int iy = r - 2, ix = cl - 2;
            float v = 0.f;
            if ((unsigned)iy < 32u && (unsigned)ix < 32u) {
                int c = c0 + ic;
                v = (c < 64) ? s0[c * 1024 + iy * 32 + ix]
                             : s1[(c - 64) * 1024 + iy * 32 + ix];
            }
            s_in[ic * 1332 + r * 37 + cl] = v;
        }
        // stage weights for 8 oc x 4 ic
        for (int idx = tid; idx < 800; idx += 128) {
            int oc  = idx / 100;
            int rem = idx - oc * 100;
            int ic  = rem / 25;
            int k   = rem - ic * 25;
            s_w[idx] = w[((ocg * 8 + oc) * 128 + w_ico + c0 + ic) * 25 + k];
        }
        __syncthreads();
#pragma unroll 1
        for (int ic = 0; ic < 4; ic++) {
#pragma unroll
            for (int ky = 0; ky < 5; ky++) {
                float seg[12];
                const float* rp = &s_in[ic * 1332 + (row + ky) * 37 + col0];
#pragma unroll
                for (int j = 0; j < 12; j++) seg[j] = rp[j];
#pragma unroll
                for (int kx = 0; kx < 5; kx++) {
#pragma unroll
                    for (int oc = 0; oc < 8; oc++) {
                        float wv = s_w[(oc * 4 + ic) * 25 + ky * 5 + kx];
#pragma unroll
                        for (int k = 0; k < 8; k++) acc[oc][k] += wv * seg[kx + k];
                    }
                }
            }
        }
        __syncthreads();
    }

    // fused epilogue
    int px0 = row * 32 + col0;
#pragma unroll
    for (int oc = 0; oc < 8; oc++) {
        int ocG = ocg * 8 + oc;
        float bv = bias[ocG];
#pragma unroll
        for (int k = 0; k < 8; k++) {
            float v  = acc[oc][k] + bv;
            int   px = px0 + k;
            if (act_mode == 0) {
                float s = 1.f / (1.f + expf(-v));
                g_zr[(b * 128 + ocG) * 1024 + px] = s;
                if (ocG < 64) {
                    int hi = (b * 64 + ocG) * 1024 + px;
                    g_rh[hi] = s * g_h[hi];      // r * h
                }
            } else {
                float c  = tanhf(v);
                int   hi = (b * 64 + ocG) * 1024 + px;
                float z  = g_zr[(b * 128 + 64 + ocG) * 1024 + px];
                float hp = g_h[hi];
                float hn = (1.f - z) * hp + z * c;
                g_h[hi] = hn;
                if (write_hs) g_hs[t * 2097152 + hi] = hn;
            }
        }
    }
}

// ---------------- deconv1: 64->32 ch, 4x4 lhs_dilation 2 pad 2, 32->64, lrelu ----------------
// gather form: out(oy,ox) gets 4 taps; ky parity == oy parity, kx parity == ox parity
__global__ __launch_bounds__(256) void deconv1(const float* __restrict__ w,
                                               const float* __restrict__ bias) {
    __shared__ float s_in[8 * 1024];         // 8 in-ch chunk of 32x32
    __shared__ float s_w[4 * 8 * 16];        // 4 oc x 8 ic x 16 taps
    int n   = blockIdx.x;                    // image 0..319 (= t*32+b)
    int ocg = blockIdx.y;                    // 4 oc per block
    int tid = threadIdx.x;
    int oy  = tid >> 2;                      // 0..63
    int ox0 = (tid & 3) << 4;                // 0,16,32,48

    float acc[4][16];
#pragma unroll
    for (int i = 0; i < 4; i++)
#pragma unroll
        for (int j = 0; j < 16; j++) acc[i][j] = 0.f;

    int ky0 = oy & 1;
    int iyA = (oy + ky0 - 2) >> 1;           // arithmetic shift handles -2,-1
    int iyB = iyA + 1;
    const float* in = g_hs + n * 65536;
    int ixbase = (ox0 >> 1) - 1;

#pragma unroll 1
    for (int cc = 0; cc < 8; cc++) {
        int ic0 = cc * 8;
        for (int idx = tid; idx < 8192; idx += 256) s_in[idx] = in[ic0 * 1024 + idx];
        for (int idx = tid; idx < 512; idx += 256) {
            int oc  = idx >> 7;
            int rem = idx & 127;
            int ic  = rem >> 4;
            int k   = rem & 15;
            s_w[idx] = w[((ocg * 4 + oc) * 64 + ic0 + ic) * 16 + k];
        }
        __syncthreads();
#pragma unroll 1
        for (int ic = 0; ic < 8; ic++) {
            float segA[10], segB[10];
#pragma unroll
            for (int m = 0; m < 10; m++) {
                int ix = ixbase + m;
                bool xok = (unsigned)ix < 32u;
                segA[m] = (xok && (unsigned)iyA < 32u) ? s_in[ic * 1024 + iyA * 32 + ix] : 0.f;
                segB[m] = (xok && (unsigned)iyB < 32u) ? s_in[ic * 1024 + iyB * 32 + ix] : 0.f;
            }
#pragma unroll
            for (int j = 0; j < 16; j++) {
                int kx0 = j & 1;
                int mA  = (j + kx0) >> 1;
                int mB  = mA + 1;
                float vAA = segA[mA], vAB = segA[mB];
                float vBA = segB[mA], vBB = segB[mB];
#pragma unroll
                for (int oc = 0; oc < 4; oc++) {
                    const float* wp = &s_w[(oc * 8 + ic) * 16];
                    acc[oc][j] += wp[ky0 * 4 + kx0]       * vAA
                                + wp[ky0 * 4 + kx0 + 2]   * vAB
                                + wp[(ky0 + 2) * 4 + kx0] * vBA
                                + wp[(ky0 + 2) * 4 + kx0 + 2] * vBB;
                }
            }
        }
        __syncthreads();
    }
#pragma unroll
    for (int oc = 0; oc < 4; oc++) {
        int ocG = ocg * 4 + oc;
        float bv = bias[ocG];
#pragma unroll
        for (int j = 0; j < 16; j++) {
            float a = acc[oc][j] + bv;
            g_y1[(n * 32 + ocG) * 4096 + oy * 64 + ox0 + j] = (a >= 0.f) ? a : 0.2f * a;
        }
    }
}

// ---------------- deconv2: 32->1 ch, 4x4 lhs_dilation 2 pad 2, 64->128, + output transpose ----------------
__global__ __launch_bounds__(256) void deconv2(const float* __restrict__ w,
                                               const float* __restrict__ bias,
                                               float* __restrict__ out) {
    __shared__ float sw[512];                // 32 ic x 16 taps
    int tid = threadIdx.x;
    for (int i = tid; i < 512; i += 256) sw[i] = w[i];
    __syncthreads();
    int n = blockIdx.x;                      // t*32+b
    int p = blockIdx.y * 256 + tid;          // 0..16383
    int oy = p >> 7, ox = p & 127;
    int ky0 = oy & 1, kx0 = ox & 1;
    int iyA = (oy + ky0 - 2) >> 1, iyB = iyA + 1;
    int ixA = (ox + kx0 - 2) >> 1, ixB = ixA + 1;
    bool yA = (unsigned)iyA < 64u, yB = (unsigned)iyB < 64u;
    bool xA = (unsigned)ixA < 64u, xB = (unsigned)ixB < 64u;
    const float* in = g_y1 + n * 131072;
    float acc = bias[0];
#pragma unroll 1
    for (int ic = 0; ic < 32; ic++) {
        const float* ip = in + ic * 4096;
        float vAA = (yA && xA) ? ip[iyA * 64 + ixA] : 0.f;
        float vAB = (yA && xB) ? ip[iyA * 64 + ixB] : 0.f;
        float vBA = (yB && xA) ? ip[iyB * 64 + ixA] : 0.f;
        float vBB = (yB && xB) ? ip[iyB * 64 + ixB] : 0.f;
        const float* wp = &sw[ic * 16];
        acc += wp[ky0 * 4 + kx0]           * vAA
             + wp[ky0 * 4 + kx0 + 2]       * vAB
             + wp[(ky0 + 2) * 4 + kx0]     * vBA
             + wp[(ky0 + 2) * 4 + kx0 + 2] * vBB;
    }
    int t = n >> 5, b = n & 31;              // n = t*32+b
    out[(b * 10 + t) * 16384 + p] = acc;     // (B, T_OUT, 1, 128, 128)
}

// ---------------- launch ----------------
extern "C" void kernel_launch(void* const* d_in, const int* in_sizes, int n_in,
                              void* d_out, int out_size) {
    const float* x            = (const float*)d_in[0];
    const float* enc_w1       = (const float*)d_in[1];
    const float* enc_b1       = (const float*)d_in[2];
    const float* enc_w2       = (const float*)d_in[3];
    const float* enc_b2       = (const float*)d_in[4];
    const float* enc_gru_wzr  = (const float*)d_in[5];
    const float* enc_gru_bzr  = (const float*)d_in[6];
    const float* enc_gru_wc   = (const float*)d_in[7];
    const float* enc_gru_bc   = (const float*)d_in[8];
    const float* dec_gru_wzr  = (const float*)d_in[9];
    const float* dec_gru_bzr  = (const float*)d_in[10];
    const float* dec_gru_wc   = (const float*)d_in[11];
    const float* dec_gru_bc   = (const float*)d_in[12];
    const float* dec_w1       = (const float*)d_in[13];
    const float* dec_b1       = (const float*)d_in[14];
    const float* dec_w2       = (const float*)d_in[15];
    const float* dec_b2       = (const float*)d_in[16];
    float* out = (float*)d_out;

    zero_h_kernel<<<8192, 256>>>();
    enc_conv1<<<dim3(320, 16), 256>>>(x, enc_w1, enc_b1);
    enc_conv2<<<dim3(320, 4), 256>>>(enc_w2, enc_b2);

    // encoder GRU: 10 steps
    for (int t = 0; t < 10; t++) {
        gru_conv<<<dim3(32, 16), 128>>>(t, 0, enc_gru_wzr, 0, enc_gru_bzr, 0, 0); // zr + rh
        gru_conv<<<dim3(32, 8), 128>>>(t, 1, enc_gru_wc, 0, enc_gru_bc, 1, 0);    // cand + update h
    }
    // decoder GRU: 10 steps (hidden-only weights: in-channel offset 64)
    for (int t = 0; t < 10; t++) {
        gru_conv<<<dim3(32, 16), 128>>>(t, 2, dec_gru_wzr, 64, dec_gru_bzr, 0, 0);
        gru_conv<<<dim3(32, 8), 128>>>(t, 3, dec_gru_wc, 64, dec_gru_bc, 1, 1);   // + write hs
    }

    deconv1<<<dim3(320, 8), 256>>>(dec_w1, dec_b1);
    deconv2<<<dim3(320, 64), 256>>>(dec_w2, dec_b2, out);
}

// round 2
// speedup vs baseline: 1.8862x; 1.8862x over previous
#include <cuda_runtime.h>
#include <cuda_bf16.h>
#include <math.h>

#define BB 32
#define TT 10

// ---------------- scratch (device globals; no allocs allowed) ----------------
__device__ float g_e1[320 * 16 * 64 * 64];   // encoder conv1 out
__device__ float g_e2[320 * 64 * 32 * 32];   // encoder conv2 out (GRU input)
__device__ float g_h [BB * 64 * 1024];       // GRU hidden state
__device__ float g_zr[BB * 128 * 1024];      // sigmoid(zr) per step
__device__ float g_rh[BB * 64 * 1024];       // r * h per step
__device__ float g_hs[TT * BB * 64 * 1024];  // decoder hidden outputs
__device__ float g_y1[320 * 32 * 64 * 64];   // deconv1 out
__device__ __nv_bfloat16 g_wh[921600];       // packed conv weights, hi bf16, [tap][oc][ic]
__device__ __nv_bfloat16 g_wl[921600];       // packed conv weights, lo bf16

// ---------------- init ----------------
__global__ void zero_h_kernel() {
    int i = blockIdx.x * blockDim.x + threadIdx.x;
    if (i < BB * 64 * 1024) g_h[i] = 0.f;
}

// ---------------- weight packing: fp32 [oc][128 ic][5][5] -> bf16 hi/lo [tap][oc][ICdst] ----------------
__global__ void pack_w(const float* __restrict__ w, int OC, int ICdst, int icoff, int dofs) {
    int idx = blockIdx.x * 256 + threadIdx.x;
    int tot = 25 * OC * ICdst;
    if (idx >= tot) return;
    int per = OC * ICdst;
    int tap = idx / per;
    int rem = idx - tap * per;
    int oc  = rem / ICdst;
    int ic  = rem - oc * ICdst;
    float v = w[(oc * 128 + icoff + ic) * 25 + tap];
    __nv_bfloat16 hh = __float2bfloat16(v);
    g_wh[dofs + idx] = hh;
    g_wl[dofs + idx] = __float2bfloat16(v - __bfloat162float(hh));
}

// ---------------- mma helpers ----------------
__device__ __forceinline__ void mma_bf16(float (&d)[4], const unsigned (&a)[4], const unsigned (&b)[2]) {
    asm volatile(
        "mma.sync.aligned.m16n8k16.row.col.f32.bf16.bf16.f32 "
        "{%0,%1,%2,%3}, {%4,%5,%6,%7}, {%8,%9}, {%0,%1,%2,%3};\n"
        : "+f"(d[0]), "+f"(d[1]), "+f"(d[2]), "+f"(d[3])
        : "r"(a[0]), "r"(a[1]), "r"(a[2]), "r"(a[3]), "r"(b[0]), "r"(b[1]));
}

__device__ __forceinline__ void ldm4(unsigned (&a)[4], const __nv_bfloat16* p) {
    unsigned addr = (unsigned)__cvta_generic_to_shared(p);
    asm volatile("ldmatrix.sync.aligned.m8n8.x4.shared.b16 {%0,%1,%2,%3}, [%4];"
                 : "=r"(a[0]), "=r"(a[1]), "=r"(a[2]), "=r"(a[3])
                 : "r"(addr));
}

// ---------------- GRU 5x5 conv via mma.sync bf16 split (3-term), fused epilogues ----------------
// src_mode: 0=enc zr (e2[t]++h, 128ic)  1=enc cand (e2[t]++rh, 128ic)
//           2=dec zr (h, 64ic)          3=dec cand (rh, 64ic)
// act_mode: 0=sigmoid -> g_zr (+ g_rh=r*h for oc<64); 1=tanh -> h update (+ g_hs)
// MT: 4 -> OC=128, 2 -> OC=64.  CTA = (image b, 4-row strip).  8 warps: 2(M) x 4(N).
template <int MT>
__global__ __launch_bounds__(256) void gru_mma(int t, int src_mode, int IC, int wofs,
                                               const float* __restrict__ bias,
                                               int act_mode, int write_hs) {
    extern __shared__ __nv_bfloat16 sm[];
    const int ICP = IC + 8;
    const int OC  = MT * 32;
    __nv_bfloat16* Xh = sm;                    // [288 px][ICP]
    __nv_bfloat16* Xl = Xh + 288 * ICP;
    __nv_bfloat16* Wh = Xl + 288 * ICP;        // [OC][ICP]
    __nv_bfloat16* Wl = Wh + OC * ICP;

    int b   = blockIdx.x;
    int y0  = blockIdx.y * 4;
    int tid = threadIdx.x;
    int w   = tid >> 5, lane = tid & 31;
    int g   = lane >> 2, tg = lane & 3;
    int mw  = w >> 2, nw = w & 3;              // nw = output row within strip

    const float* s0;
    const float* s1;
    if (src_mode <= 1) {
        s0 = g_e2 + (b * 10 + t) * 65536;
        s1 = (src_mode == 0 ? g_h : g_rh) + b * 65536;
    } else {
        s0 = (src_mode == 2 ? g_h : g_rh) + b * 65536;
        s1 = s0;
    }

    // ---- stage X: [sy 0..7][sx 0..35][ic], channel-last, bf16 hi/lo ----
    int tot = IC * 288;
    for (int idx = tid; idx < tot; idx += 256) {
        int c   = idx / 288;
        int rem = idx - c * 288;
        int sy  = rem / 36, sx = rem - sy * 36;
        int yy  = y0 - 2 + sy, xx = sx - 2;
        float v = 0.f;
        if ((unsigned)yy < 32u && (unsigned)xx < 32u) {
            const float* p = (IC == 128 && c >= 64) ? (s1 + (c - 64) * 1024) : (s0 + c * 1024);
            v = p[yy * 32 + xx];
        }
        __nv_bfloat16 hh = __float2bfloat16(v);
        Xh[rem * ICP + c] = hh;
        Xl[rem * ICP + c] = __float2bfloat16(v - __bfloat162float(hh));
    }
    __syncthreads();

    float D[MT][4][4];
#pragma unroll
    for (int mt = 0; mt < MT; mt++)
#pragma unroll
        for (int nt = 0; nt < 4; nt++)
#pragma unroll
            for (int i = 0; i < 4; i++) D[mt][nt][i] = 0.f;

    const __nv_bfloat16* gwh = g_wh + wofs;
    const __nv_bfloat16* gwl = g_wl + wofs;
    int lrow = ((lane >> 3) & 1) * 8 + (lane & 7);   // ldmatrix row within 16
    int lcol = (lane >> 4) * 8;                      // ldmatrix col within 16

    for (int tap = 0; tap < 25; tap++) {
        int dy = tap / 5, dx = tap - 5 * dy;
        // stage W tap
        int wt = OC * IC;
        const __nv_bfloat16* th = gwh + tap * wt;
        const __nv_bfloat16* tl = gwl + tap * wt;
        for (int idx = tid; idx < wt; idx += 256) {
            int oc = idx / IC, ic = idx - oc * IC;
            Wh[oc * ICP + ic] = th[idx];
            Wl[oc * ICP + ic] = tl[idx];
        }
        __syncthreads();

        int rowbase = ((nw + dy) * 36 + dx) * ICP;
        int KC = IC >> 4;
#pragma unroll 2
        for (int kc = 0; kc < KC; kc++) {
            unsigned Ah[MT][4], Al[MT][4];
#pragma unroll
            for (int mt = 0; mt < MT; mt++) {
                const __nv_bfloat16* pa = Wh + (mw * MT * 16 + mt * 16 + lrow) * ICP + kc * 16 + lcol;
                ldm4(Ah[mt], pa);
                const __nv_bfloat16* pl = Wl + (mw * MT * 16 + mt * 16 + lrow) * ICP + kc * 16 + lcol;
                ldm4(Al[mt], pl);
            }
            unsigned Bh[4][2], Bl[4][2];
#pragma unroll
            for (int nt = 0; nt < 4; nt++) {
                int off = rowbase + (nt * 8 + g) * ICP + kc * 16 + 2 * tg;
                Bh[nt][0] = *(const unsigned*)(Xh + off);
                Bh[nt][1] = *(const unsigned*)(Xh + off + 8);
                Bl[nt][0] = *(const unsigned*)(Xl + off);
                Bl[nt][1] = *(const unsigned*)(Xl + off + 8);
            }
#pragma unroll
            for (int mt = 0; mt < MT; mt++)
#pragma unroll
                for (int nt = 0; nt < 4; nt++) mma_bf16(D[mt][nt], Ah[mt], Bh[nt]);
#pragma unroll
            for (int mt = 0; mt < MT; mt++)
#pragma unroll
                for (int nt = 0; nt < 4; nt++) mma_bf16(D[mt][nt], Ah[mt], Bl[nt]);
#pragma unroll
            for (int mt = 0; mt < MT; mt++)
#pragma unroll
                for (int nt = 0; nt < 4; nt++) mma_bf16(D[mt][nt], Al[mt], Bh[nt]);
        }
        __syncthreads();
    }

    // ---- fused epilogue ----
    int y = y0 + nw;
#pragma unroll
    for (int mt = 0; mt < MT; mt++) {
#pragma unroll
        for (int ci2 = 0; ci2 < 2; ci2++) {
            int   ocG = mw * MT * 16 + mt * 16 + g + 8 * ci2;
            float bv  = bias[ocG];
#pragma unroll
            for (int nt = 0; nt < 4; nt++) {
#pragma unroll
                for (int j = 0; j < 2; j++) {
                    float v  = D[mt][nt][ci2 * 2 + j] + bv;
                    int   x  = nt * 8 + 2 * tg + j;
                    int   px = y * 32 + x;
                    if (act_mode == 0) {
                        float s = 1.f / (1.f + expf(-v));
                        g_zr[(b * 128 + ocG) * 1024 + px] = s;
                        if (ocG < 64) {
                            int hi = (b * 64 + ocG) * 1024 + px;
                            g_rh[hi] = s * g_h[hi];
                        }
                    } else {
                        float c  = tanhf(v);
                        int   hi = (b * 64 + ocG) * 1024 + px;
                        float z  = g_zr[(b * 128 + 64 + ocG) * 1024 + px];
                        float hp = g_h[hi];
                        float hn = (1.f - z) * hp + z * c;
                        g_h[hi] = hn;
                        if (write_hs) g_hs[t * 2097152 + hi] = hn;
                    }
                }
            }
        }
    }
}

// ---------------- encoder conv1: 1->16 ch, 3x3 s2 p1, 128->64, lrelu ----------------
__global__ __launch_bounds__(256) void enc_conv1(const float* __restrict__ x,
                                                 const float* __restrict__ w,
                                                 const float* __restrict__ bias) {
    __shared__ float sw[144];
    __shared__ float sb[16];
    int tid = threadIdx.x;
    if (tid < 144) sw[tid] = w[tid];
    if (tid < 16)  sb[tid] = bias[tid];
    __syncthreads();
    int n = blockIdx.x;
    int p = blockIdx.y * 256 + tid;
    int oy = p >> 6, ox = p & 63;
    const float* xi = x + n * 16384;
    float win[9];
    int iy0 = 2 * oy - 1, ix0 = 2 * ox - 1;
#pragma unroll
    for (int ky = 0; ky < 3; ky++)
#pragma unroll
        for (int kx = 0; kx < 3; kx++) {
            int iy = iy0 + ky, ix = ix0 + kx;
            win[ky * 3 + kx] = ((unsigned)iy < 128u && (unsigned)ix < 128u) ? xi[iy * 128 + ix] : 0.f;
        }
#pragma unroll
    for (int oc = 0; oc < 16; oc++) {
        float a = sb[oc];
#pragma unroll
        for (int k = 0; k < 9; k++) a += sw[oc * 9 + k] * win[k];
        g_e1[(n * 16 + oc) * 4096 + p] = (a >= 0.f) ? a : 0.2f * a;
    }
}

// ---------------- encoder conv2: 16->64 ch, 3x3 s2 p1, 64->32, lrelu ----------------
__global__ __launch_bounds__(256) void enc_conv2(const float* __restrict__ w,
                                                 const float* __restrict__ bias) {
    __shared__ float sw[64 * 16 * 9];
    int tid = threadIdx.x;
    for (int i = tid; i < 9216; i += 256) sw[i] = w[i];
    __syncthreads();
    int n = blockIdx.x;
    int p = blockIdx.y * 256 + tid;
    int oy = p >> 5, ox = p & 31;
    const float* in = g_e1 + n * 65536;
    float acc[64];
#pragma unroll
    for (int oc = 0; oc < 64; oc++) acc[oc] = bias[oc];
    int iy0 = 2 * oy - 1, ix0 = 2 * ox - 1;
#pragma unroll 1
    for (int ic = 0; ic < 16; ic++) {
        float win[9];
#pragma unroll
        for (int ky = 0; ky < 3; ky++)
#pragma unroll
            for (int kx = 0; kx < 3; kx++) {
                int iy = iy0 + ky, ix = ix0 + kx;
                win[ky * 3 + kx] = ((unsigned)iy < 64u && (unsigned)ix < 64u)
                                       ? in[ic * 4096 + iy * 64 + ix] : 0.f;
            }
#pragma unroll
        for (int oc = 0; oc < 64; oc++) {
#pragma unroll
            for (int k = 0; k < 9; k++) acc[oc] += sw[(oc * 16 + ic) * 9 + k] * win[k];
        }
    }
#pragma unroll
    for (int oc = 0; oc < 64; oc++) {
        float a = acc[oc];
        g_e2[(n * 64 + oc) * 1024 + p] = (a >= 0.f) ? a : 0.2f * a;
    }
}

// ---------------- deconv1: 64->32 ch, 4x4 lhs_dilation 2 pad 2, 32->64, lrelu ----------------
__global__ __launch_bounds__(256) void deconv1(const float* __restrict__ w,
                                               const float* __restrict__ bias) {
    __shared__ float s_in[8 * 1024];
    __shared__ float s_w[4 * 8 * 16];
    int n   = blockIdx.x;
    int ocg = blockIdx.y;
    int tid = threadIdx.x;
    int oy  = tid >> 2;
    int ox0 = (tid & 3) << 4;

    float acc[4][16];
#pragma unroll
    for (int i = 0; i < 4; i++)
#pragma unroll
        for (int j = 0; j < 16; j++) acc[i][j] = 0.f;

    int ky0 = oy & 1;
    int iyA = (oy + ky0 - 2) >> 1;
    int iyB = iyA + 1;
    const float* in = g_hs + n * 65536;
    int ixbase = (ox0 >> 1) - 1;

#pragma unroll 1
    for (int cc = 0; cc < 8; cc++) {
        int ic0 = cc * 8;
        for (int idx = tid; idx < 8192; idx += 256) s_in[idx] = in[ic0 * 1024 + idx];
        for (int idx = tid; idx < 512; idx += 256) {
            int oc  = idx >> 7;
            int rem = idx & 127;
            int ic  = rem >> 4;
            int k   = rem & 15;
            s_w[idx] = w[((ocg * 4 + oc) * 64 + ic0 + ic) * 16 + k];
        }
        __syncthreads();
#pragma unroll 1
        for (int ic = 0; ic < 8; ic++) {
            float segA[10], segB[10];
#pragma unroll
            for (int m = 0; m < 10; m++) {
                int ix = ixbase + m;
                bool xok = (unsigned)ix < 32u;
                segA[m] = (xok && (unsigned)iyA < 32u) ? s_in[ic * 1024 + iyA * 32 + ix] : 0.f;
                segB[m] = (xok && (unsigned)iyB < 32u) ? s_in[ic * 1024 + iyB * 32 + ix] : 0.f;
            }
#pragma unroll
            for (int j = 0; j < 16; j++) {
                int kx0 = j & 1;
                int mA  = (j + kx0) >> 1;
                int mB  = mA + 1;
                float vAA = segA[mA], vAB = segA[mB];
                float vBA = segB[mA], vBB = segB[mB];
#pragma unroll
                for (int oc = 0; oc < 4; oc++) {
                    const float* wp = &s_w[(oc * 8 + ic) * 16];
                    acc[oc][j] += wp[ky0 * 4 + kx0]       * vAA
                                + wp[ky0 * 4 + kx0 + 2]   * vAB
                                + wp[(ky0 + 2) * 4 + kx0] * vBA
                                + wp[(ky0 + 2) * 4 + kx0 + 2] * vBB;
                }
            }
        }
        __syncthreads();
    }
#pragma unroll
    for (int oc = 0; oc < 4; oc++) {
        int ocG = ocg * 4 + oc;
        float bv = bias[ocG];
#pragma unroll
        for (int j = 0; j < 16; j++) {
            float a = acc[oc][j] + bv;
            g_y1[(n * 32 + ocG) * 4096 + oy * 64 + ox0 + j] = (a >= 0.f) ? a : 0.2f * a;
        }
    }
}

// ---------------- deconv2: 32->1 ch, 4x4 lhs_dilation 2 pad 2, 64->128, + transpose ----------------
__global__ __launch_bounds__(256) void deconv2(const float* __restrict__ w,
                                               const float* __restrict__ bias,
                                               float* __restrict__ out) {
    __shared__ float sw[512];
    int tid = threadIdx.x;
    for (int i = tid; i < 512; i += 256) sw[i] = w[i];
    __syncthreads();
    int n = blockIdx.x;
    int p = blockIdx.y * 256 + tid;
    int oy = p >> 7, ox = p & 127;
    int ky0 = oy & 1, kx0 = ox & 1;
    int iyA = (oy + ky0 - 2) >> 1, iyB = iyA + 1;
    int ixA = (ox + kx0 - 2) >> 1, ixB = ixA + 1;
    bool yA = (unsigned)iyA < 64u, yB = (unsigned)iyB < 64u;
    bool xA = (unsigned)ixA < 64u, xB = (unsigned)ixB < 64u;
    const float* in = g_y1 + n * 131072;
    float acc = bias[0];
#pragma unroll 1
    for (int ic = 0; ic < 32; ic++) {
        const float* ip = in + ic * 4096;
        float vAA = (yA && xA) ? ip[iyA * 64 + ixA] : 0.f;
        float vAB = (yA && xB) ? ip[iyA * 64 + ixB] : 0.f;
        float vBA = (yB && xA) ? ip[iyB * 64 + ixA] : 0.f;
        float vBB = (yB && xB) ? ip[iyB * 64 + ixB] : 0.f;
        const float* wp = &sw[ic * 16];
        acc += wp[ky0 * 4 + kx0]           * vAA
             + wp[ky0 * 4 + kx0 + 2]       * vAB
             + wp[(ky0 + 2) * 4 + kx0]     * vBA
             + wp[(ky0 + 2) * 4 + kx0 + 2] * vBB;
    }
    int t = n >> 5, b = n & 31;
    out[(b * 10 + t) * 16384 + p] = acc;
}

// ---------------- launch ----------------
extern "C" void kernel_launch(void* const* d_in, const int* in_sizes, int n_in,
                              void* d_out, int out_size) {
    const float* x            = (const float*)d_in[0];
    const float* enc_w1       = (const float*)d_in[1];
    const float* enc_b1       = (const float*)d_in[2];
    const float* enc_w2       = (const float*)d_in[3];
    const float* enc_b2       = (const float*)d_in[4];
    const float* enc_gru_wzr  = (const float*)d_in[5];
    const float* enc_gru_bzr  = (const float*)d_in[6];
    const float* enc_gru_wc   = (const float*)d_in[7];
    const float* enc_gru_bc   = (const float*)d_in[8];
    const float* dec_gru_wzr  = (const float*)d_in[9];
    const float* dec_gru_bzr  = (const float*)d_in[10];
    const float* dec_gru_wc   = (const float*)d_in[11];
    const float* dec_gru_bc   = (const float*)d_in[12];
    const float* dec_w1       = (const float*)d_in[13];
    const float* dec_b1       = (const float*)d_in[14];
    const float* dec_w2       = (const float*)d_in[15];
    const float* dec_b2       = (const float*)d_in[16];
    float* out = (float*)d_out;

    // smem sizes: 2*288*ICP + 2*OC*ICP bf16 elems, *2 bytes
    const int SM_EZR = (2 * 288 * 136 + 2 * 128 * 136) * 2;  // 226304
    const int SM_EC  = (2 * 288 * 136 + 2 * 64 * 136) * 2;   // 191488
    const int SM_DZR = (2 * 288 * 72 + 2 * 128 * 72) * 2;    // 119808
    const int SM_DC  = (2 * 288 * 72 + 2 * 64 * 72) * 2;     // 101376
    cudaFuncSetAttribute(gru_mma<4>, cudaFuncAttributeMaxDynamicSharedMemorySize, SM_EZR);
    cudaFuncSetAttribute(gru_mma<2>, cudaFuncAttributeMaxDynamicSharedMemorySize, SM_EC);

    zero_h_kernel<<<8192, 256>>>();

    // pack weights to bf16 hi/lo (per-call; cheap)
    pack_w<<<(25 * 128 * 128 + 255) / 256, 256>>>(enc_gru_wzr, 128, 128, 0, 0);
    pack_w<<<(25 * 64 * 128 + 255) / 256, 256>>>(enc_gru_wc, 64, 128, 0, 409600);
    pack_w<<<(25 * 128 * 64 + 255) / 256, 256>>>(dec_gru_wzr, 128, 64, 64, 614400);
    pack_w<<<(25 * 64 * 64 + 255) / 256, 256>>>(dec_gru_wc, 64, 64, 64, 819200);

    enc_conv1<<<dim3(320, 16), 256>>>(x, enc_w1, enc_b1);
    enc_conv2<<<dim3(320, 4), 256>>>(enc_w2, enc_b2);

    for (int t = 0; t < 10; t++) {
        gru_mma<4><<<dim3(32, 8), 256, SM_EZR>>>(t, 0, 128, 0, enc_gru_bzr, 0, 0);
        gru_mma<2><<<dim3(32, 8), 256, SM_EC>>>(t, 1, 128, 409600, enc_gru_bc, 1, 0);
    }
    for (int t = 0; t < 10; t++) {
        gru_mma<4><<<dim3(32, 8), 256, SM_DZR>>>(t, 2, 64, 614400, dec_gru_bzr, 0, 0);
        gru_mma<2><<<dim3(32, 8), 256, SM_DC>>>(t, 3, 64, 819200, dec_gru_bc, 1, 1);
    }

    deconv1<<<dim3(320, 8), 256>>>(dec_w1, dec_b1);
    deconv2<<<dim3(320, 64), 256>>>(dec_w2, dec_b2, out);
}

// round 3
// speedup vs baseline: 1.8955x; 1.0049x over previous
#include <cuda_runtime.h>
#include <cuda_bf16.h>
#include <math.h>

#define BB 32
#define TT 10

// ---------------- scratch (device globals; no allocs allowed) ----------------
__device__ float g_e1[320 * 16 * 64 * 64];   // encoder conv1 out
__device__ float g_e2[320 * 64 * 32 * 32];   // encoder conv2 out (GRU input)
__device__ float g_h [BB * 64 * 1024];       // GRU hidden state
__device__ float g_zr[BB * 128 * 1024];      // sigmoid(zr) per step
__device__ float g_rh[BB * 64 * 1024];       // r * h per step
__device__ float g_hs[TT * BB * 64 * 1024];  // decoder hidden outputs
__device__ float g_y1[320 * 32 * 64 * 64];   // deconv1 out
__device__ __nv_bfloat16 g_wh[921600];       // packed conv weights, hi bf16, [tap][oc][ic]
__device__ __nv_bfloat16 g_wl[921600];       // packed conv weights, lo bf16

// ---------------- init ----------------
__global__ void zero_h_kernel() {
    int i = blockIdx.x * blockDim.x + threadIdx.x;
    if (i < BB * 64 * 1024) g_h[i] = 0.f;
}

// ---------------- weight packing: fp32 [oc][128 ic][5][5] -> bf16 hi/lo [tap][oc][ICdst] ----------------
__global__ void pack_w(const float* __restrict__ w, int OC, int ICdst, int icoff, int dofs) {
    int idx = blockIdx.x * 256 + threadIdx.x;
    int tot = 25 * OC * ICdst;
    if (idx >= tot) return;
    int per = OC * ICdst;
    int tap = idx / per;
    int rem = idx - tap * per;
    int oc  = rem / ICdst;
    int ic  = rem - oc * ICdst;
    float v = w[(oc * 128 + icoff + ic) * 25 + tap];
    __nv_bfloat16 hh = __float2bfloat16(v);
    g_wh[dofs + idx] = hh;
    g_wl[dofs + idx] = __float2bfloat16(v - __bfloat162float(hh));
}

// ---------------- mma helpers ----------------
__device__ __forceinline__ void mma_bf16(float (&d)[4], const unsigned (&a)[4], const unsigned (&b)[2]) {
    asm volatile(
        "mma.sync.aligned.m16n8k16.row.col.f32.bf16.bf16.f32 "
        "{%0,%1,%2,%3}, {%4,%5,%6,%7}, {%8,%9}, {%0,%1,%2,%3};\n"
        : "+f"(d[0]), "+f"(d[1]), "+f"(d[2]), "+f"(d[3])
        : "r"(a[0]), "r"(a[1]), "r"(a[2]), "r"(a[3]), "r"(b[0]), "r"(b[1]));
}

__device__ __forceinline__ void ldm4(unsigned (&a)[4], const __nv_bfloat16* p) {
    unsigned addr = (unsigned)__cvta_generic_to_shared(p);
    asm volatile("ldmatrix.sync.aligned.m8n8.x4.shared.b16 {%0,%1,%2,%3}, [%4];"
                 : "=r"(a[0]), "=r"(a[1]), "=r"(a[2]), "=r"(a[3])
                 : "r"(addr));
}

// ---------------- GRU 5x5 conv via mma.sync bf16 split (3-term), fused epilogues ----------------
// src_mode: 0=enc zr (e2[t]++h, 128ic)  1=enc cand (e2[t]++rh, 128ic)
//           2=dec zr (h, 64ic)          3=dec cand (rh, 64ic)
// act_mode: 0=sigmoid -> g_zr (+ g_rh=r*h for oc<64); 1=tanh -> h update (+ g_hs)
// MT: 4 -> OC=128, 2 -> OC=64.  CTA = (image b, 4-row strip).  8 warps: 2(M) x 4(N).
template <int MT>
__global__ __launch_bounds__(256) void gru_mma(int t, int src_mode, int IC, int wofs,
                                               const float* __restrict__ bias,
                                               int act_mode, int write_hs) {
    extern __shared__ __nv_bfloat16 sm[];
    const int ICP = IC + 8;
    const int OC  = MT * 32;
    __nv_bfloat16* Xh = sm;                    // [288 px][ICP]
    __nv_bfloat16* Xl = Xh + 288 * ICP;
    __nv_bfloat16* Wh = Xl + 288 * ICP;        // [OC][ICP]
    __nv_bfloat16* Wl = Wh + OC * ICP;

    int b   = blockIdx.x;
    int y0  = blockIdx.y * 4;
    int tid = threadIdx.x;
    int w   = tid >> 5, lane = tid & 31;
    int g   = lane >> 2, tg = lane & 3;
    int mw  = w >> 2, nw = w & 3;              // nw = output row within strip

    const float* s0;
    const float* s1;
    if (src_mode <= 1) {
        s0 = g_e2 + (b * 10 + t) * 65536;
        s1 = (src_mode == 0 ? g_h : g_rh) + b * 65536;
    } else {
        s0 = (src_mode == 2 ? g_h : g_rh) + b * 65536;
        s1 = s0;
    }

    // ---- stage X: [sy 0..7][sx 0..35][ic], channel-last, bf16 hi/lo ----
    int tot = IC * 288;
    for (int idx = tid; idx < tot; idx += 256) {
        int c   = idx / 288;
        int rem = idx - c * 288;
        int sy  = rem / 36, sx = rem - sy * 36;
        int yy  = y0 - 2 + sy, xx = sx - 2;
        float v = 0.f;
        if ((unsigned)yy < 32u && (unsigned)xx < 32u) {
            const float* p = (IC == 128 && c >= 64) ? (s1 + (c - 64) * 1024) : (s0 + c * 1024);
            v = p[yy * 32 + xx];
        }
        __nv_bfloat16 hh = __float2bfloat16(v);
        Xh[rem * ICP + c] = hh;
        Xl[rem * ICP + c] = __float2bfloat16(v - __bfloat162float(hh));
    }
    __syncthreads();

    float D[MT][4][4];
#pragma unroll
    for (int mt = 0; mt < MT; mt++)
#pragma unroll
        for (int nt = 0; nt < 4; nt++)
#pragma unroll
            for (int i = 0; i < 4; i++) D[mt][nt][i] = 0.f;

    const __nv_bfloat16* gwh = g_wh + wofs;
    const __nv_bfloat16* gwl = g_wl + wofs;
    int lrow = ((lane >> 3) & 1) * 8 + (lane & 7);   // ldmatrix row within 16
    int lcol = (lane >> 4) * 8;                      // ldmatrix col within 16

    for (int tap = 0; tap < 25; tap++) {
        int dy = tap / 5, dx = tap - 5 * dy;
        // stage W tap
        int wt = OC * IC;
        const __nv_bfloat16* th = gwh + tap * wt;
        const __nv_bfloat16* tl = gwl + tap * wt;
        for (int idx = tid; idx < wt; idx += 256) {
            int oc = idx / IC, ic = idx - oc * IC;
            Wh[oc * ICP + ic] = th[idx];
            Wl[oc * ICP + ic] = tl[idx];
        }
        __syncthreads();

        int rowbase = ((nw + dy) * 36 + dx) * ICP;
        int KC = IC >> 4;
#pragma unroll 2
        for (int kc = 0; kc < KC; kc++) {
            unsigned Ah[MT][4], Al[MT][4];
#pragma unroll
            for (int mt = 0; mt < MT; mt++) {
                const __nv_bfloat16* pa = Wh + (mw * MT * 16 + mt * 16 + lrow) * ICP + kc * 16 + lcol;
                ldm4(Ah[mt], pa);
                const __nv_bfloat16* pl = Wl + (mw * MT * 16 + mt * 16 + lrow) * ICP + kc * 16 + lcol;
                ldm4(Al[mt], pl);
            }
            unsigned Bh[4][2], Bl[4][2];
#pragma unroll
            for (int nt = 0; nt < 4; nt++) {
                int off = rowbase + (nt * 8 + g) * ICP + kc * 16 + 2 * tg;
                Bh[nt][0] = *(const unsigned*)(Xh + off);
                Bh[nt][1] = *(const unsigned*)(Xh + off + 8);
                Bl[nt][0] = *(const unsigned*)(Xl + off);
                Bl[nt][1] = *(const unsigned*)(Xl + off + 8);
            }
#pragma unroll
            for (int mt = 0; mt < MT; mt++)
#pragma unroll
                for (int nt = 0; nt < 4; nt++) mma_bf16(D[mt][nt], Ah[mt], Bh[nt]);
#pragma unroll
            for (int mt = 0; mt < MT; mt++)
#pragma unroll
                for (int nt = 0; nt < 4; nt++) mma_bf16(D[mt][nt], Ah[mt], Bl[nt]);
#pragma unroll
            for (int mt = 0; mt < MT; mt++)
#pragma unroll
                for (int nt = 0; nt < 4; nt++) mma_bf16(D[mt][nt], Al[mt], Bh[nt]);
        }
        __syncthreads();
    }

    // ---- fused epilogue ----
    int y = y0 + nw;
#pragma unroll
    for (int mt = 0; mt < MT; mt++) {
#pragma unroll
        for (int ci2 = 0; ci2 < 2; ci2++) {
            int   ocG = mw * MT * 16 + mt * 16 + g + 8 * ci2;
            float bv  = bias[ocG];
#pragma unroll
            for (int nt = 0; nt < 4; nt++) {
#pragma unroll
                for (int j = 0; j < 2; j++) {
                    float v  = D[mt][nt][ci2 * 2 + j] + bv;
                    int   x  = nt * 8 + 2 * tg + j;
                    int   px = y * 32 + x;
                    if (act_mode == 0) {
                        float s = 1.f / (1.f + expf(-v));
                        g_zr[(b * 128 + ocG) * 1024 + px] = s;
                        if (ocG < 64) {
                            int hi = (b * 64 + ocG) * 1024 + px;
                            g_rh[hi] = s * g_h[hi];
                        }
                    } else {
                        float c  = tanhf(v);
                        int   hi = (b * 64 + ocG) * 1024 + px;
                        float z  = g_zr[(b * 128 + 64 + ocG) * 1024 + px];
                        float hp = g_h[hi];
                        float hn = (1.f - z) * hp + z * c;
                        g_h[hi] = hn;
                        if (write_hs) g_hs[t * 2097152 + hi] = hn;
                    }
                }
            }
        }
    }
}

// ---------------- encoder conv1: 1->16 ch, 3x3 s2 p1, 128->64, lrelu ----------------
__global__ __launch_bounds__(256) void enc_conv1(const float* __restrict__ x,
                                                 const float* __restrict__ w,
                                                 const float* __restrict__ bias) {
    __shared__ float sw[144];
    __shared__ float sb[16];
    int tid = threadIdx.x;
    if (tid < 144) sw[tid] = w[tid];
    if (tid < 16)  sb[tid] = bias[tid];
    __syncthreads();
    int n = blockIdx.x;
    int p = blockIdx.y * 256 + tid;
    int oy = p >> 6, ox = p & 63;
    const float* xi = x + n * 16384;
    float win[9];
    int iy0 = 2 * oy - 1, ix0 = 2 * ox - 1;
#pragma unroll
    for (int ky = 0; ky < 3; ky++)
#pragma unroll
        for (int kx = 0; kx < 3; kx++) {
            int iy = iy0 + ky, ix = ix0 + kx;
            win[ky * 3 + kx] = ((unsigned)iy < 128u && (unsigned)ix < 128u) ? xi[iy * 128 + ix] : 0.f;
        }
#pragma unroll
    for (int oc = 0; oc < 16; oc++) {
        float a = sb[oc];
#pragma unroll
        for (int k = 0; k < 9; k++) a += sw[oc * 9 + k] * win[k];
        g_e1[(n * 16 + oc) * 4096 + p] = (a >= 0.f) ? a : 0.2f * a;
    }
}

// ---------------- encoder conv2: 16->64 ch, 3x3 s2 p1, 64->32, lrelu ----------------
__global__ __launch_bounds__(256) void enc_conv2(const float* __restrict__ w,
                                                 const float* __restrict__ bias) {
    __shared__ float sw[64 * 16 * 9];
    int tid = threadIdx.x;
    for (int i = tid; i < 9216; i += 256) sw[i] = w[i];
    __syncthreads();
    int n = blockIdx.x;
    int p = blockIdx.y * 256 + tid;
    int oy = p >> 5, ox = p & 31;
    const float* in = g_e1 + n * 65536;
    float acc[64];
#pragma unroll
    for (int oc = 0; oc < 64; oc++) acc[oc] = bias[oc];
    int iy0 = 2 * oy - 1, ix0 = 2 * ox - 1;
#pragma unroll 1
    for (int ic = 0; ic < 16; ic++) {
        float win[9];
#pragma unroll
        for (int ky = 0; ky < 3; ky++)
#pragma unroll
            for (int kx = 0; kx < 3; kx++) {
                int iy = iy0 + ky, ix = ix0 + kx;
                win[ky * 3 + kx] = ((unsigned)iy < 64u && (unsigned)ix < 64u)
                                       ? in[ic * 4096 + iy * 64 + ix] : 0.f;
            }
#pragma unroll
        for (int oc = 0; oc < 64; oc++) {
#pragma unroll
            for (int k = 0; k < 9; k++) acc[oc] += sw[(oc * 16 + ic) * 9 + k] * win[k];
        }
    }
#pragma unroll
    for (int oc = 0; oc < 64; oc++) {
        float a = acc[oc];
        g_e2[(n * 64 + oc) * 1024 + p] = (a >= 0.f) ? a : 0.2f * a;
    }
}

// ---------------- deconv1: 64->32 ch, 4x4 lhs_dilation 2 pad 2, 32->64, lrelu ----------------
__global__ __launch_bounds__(256) void deconv1(const float* __restrict__ w,
                                               const float* __restrict__ bias) {
    __shared__ float s_in[8 * 1024];
    __shared__ float s_w[4 * 8 * 16];
    int n   = blockIdx.x;
    int ocg = blockIdx.y;
    int tid = threadIdx.x;
    int oy  = tid >> 2;
    int ox0 = (tid & 3) << 4;

    float acc[4][16];
#pragma unroll
    for (int i = 0; i < 4; i++)
#pragma unroll
        for (int j = 0; j < 16; j++) acc[i][j] = 0.f;

    int ky0 = oy & 1;
    int iyA = (oy + ky0 - 2) >> 1;
    int iyB = iyA + 1;
    const float* in = g_hs + n * 65536;
    int ixbase = (ox0 >> 1) - 1;

#pragma unroll 1
    for (int cc = 0; cc < 8; cc++) {
        int ic0 = cc * 8;
        for (int idx = tid; idx < 8192; idx += 256) s_in[idx] = in[ic0 * 1024 + idx];
        for (int idx = tid; idx < 512; idx += 256) {
            int oc  = idx >> 7;
            int rem = idx & 127;
            int ic  = rem >> 4;
            int k   = rem & 15;
            s_w[idx] = w[((ocg * 4 + oc) * 64 + ic0 + ic) * 16 + k];
        }
        __syncthreads();
#pragma unroll 1
        for (int ic = 0; ic < 8; ic++) {
            float segA[10], segB[10];
#pragma unroll
            for (int m = 0; m < 10; m++) {
                int ix = ixbase + m;
                bool xok = (unsigned)ix < 32u;
                segA[m] = (xok && (unsigned)iyA < 32u) ? s_in[ic * 1024 + iyA * 32 + ix] : 0.f;
                segB[m] = (xok && (unsigned)iyB < 32u) ? s_in[ic * 1024 + iyB * 32 + ix] : 0.f;
            }
#pragma unroll
            for (int j = 0; j < 16; j++) {
                int kx0 = j & 1;
                int mA  = (j + kx0) >> 1;
                int mB  = mA + 1;
                float vAA = segA[mA], vAB = segA[mB];
                float vBA = segB[mA], vBB = segB[mB];
#pragma unroll
                for (int oc = 0; oc < 4; oc++) {
                    const float* wp = &s_w[(oc * 8 + ic) * 16];
                    acc[oc][j] += wp[ky0 * 4 + kx0]       * vAA
                                + wp[ky0 * 4 + kx0 + 2]   * vAB
                                + wp[(ky0 + 2) * 4 + kx0] * vBA
                                + wp[(ky0 + 2) * 4 + kx0 + 2] * vBB;
                }
            }
        }
        __syncthreads();
    }
#pragma unroll
    for (int oc = 0; oc < 4; oc++) {
        int ocG = ocg * 4 + oc;
        float bv = bias[ocG];
#pragma unroll
        for (int j = 0; j < 16; j++) {
            float a = acc[oc][j] + bv;
            g_y1[(n * 32 + ocG) * 4096 + oy * 64 + ox0 + j] = (a >= 0.f) ? a : 0.2f * a;
        }
    }
}

// ---------------- deconv2: 32->1 ch, 4x4 lhs_dilation 2 pad 2, 64->128, + transpose ----------------
__global__ __launch_bounds__(256) void deconv2(const float* __restrict__ w,
                                               const float* __restrict__ bias,
                                               float* __restrict__ out) {
    __shared__ float sw[512];
    int tid = threadIdx.x;
    for (int i = tid; i < 512; i += 256) sw[i] = w[i];
    __syncthreads();
    int n = blockIdx.x;
    int p = blockIdx.y * 256 + tid;
    int oy = p >> 7, ox = p & 127;
    int ky0 = oy & 1, kx0 = ox & 1;
    int iyA = (oy + ky0 - 2) >> 1, iyB = iyA + 1;
    int ixA = (ox + kx0 - 2) >> 1, ixB = ixA + 1;
    bool yA = (unsigned)iyA < 64u, yB = (unsigned)iyB < 64u;
    bool xA = (unsigned)ixA < 64u, xB = (unsigned)ixB < 64u;
    const float* in = g_y1 + n * 131072;
    float acc = bias[0];
#pragma unroll 1
    for (int ic = 0; ic < 32; ic++) {
        const float* ip = in + ic * 4096;
        float vAA = (yA && xA) ? ip[iyA * 64 + ixA] : 0.f;
        float vAB = (yA && xB) ? ip[iyA * 64 + ixB] : 0.f;
        float vBA = (yB && xA) ? ip[iyB * 64 + ixA] : 0.f;
        float vBB = (yB && xB) ? ip[iyB * 64 + ixB] : 0.f;
        const float* wp = &sw[ic * 16];
        acc += wp[ky0 * 4 + kx0]           * vAA
             + wp[ky0 * 4 + kx0 + 2]       * vAB
             + wp[(ky0 + 2) * 4 + kx0]     * vBA
             + wp[(ky0 + 2) * 4 + kx0 + 2] * vBB;
    }
    int t = n >> 5, b = n & 31;
    out[(b * 10 + t) * 16384 + p] = acc;
}

// ---------------- launch ----------------
extern "C" void kernel_launch(void* const* d_in, const int* in_sizes, int n_in,
                              void* d_out, int out_size) {
    const float* x            = (const float*)d_in[0];
    const float* enc_w1       = (const float*)d_in[1];
    const float* enc_b1       = (const float*)d_in[2];
    const float* enc_w2       = (const float*)d_in[3];
    const float* enc_b2       = (const float*)d_in[4];
    const float* enc_gru_wzr  = (const float*)d_in[5];
    const float* enc_gru_bzr  = (const float*)d_in[6];
    const float* enc_gru_wc   = (const float*)d_in[7];
    const float* enc_gru_bc   = (const float*)d_in[8];
    const float* dec_gru_wzr  = (const float*)d_in[9];
    const float* dec_gru_bzr  = (const float*)d_in[10];
    const float* dec_gru_wc   = (const float*)d_in[11];
    const float* dec_gru_bc   = (const float*)d_in[12];
    const float* dec_w1       = (const float*)d_in[13];
    const float* dec_b1       = (const float*)d_in[14];
    const float* dec_w2       = (const float*)d_in[15];
    const float* dec_b2       = (const float*)d_in[16];
    float* out = (float*)d_out;

    // smem sizes: 2*288*ICP + 2*OC*ICP bf16 elems, *2 bytes
    const int SM_EZR = (2 * 288 * 136 + 2 * 128 * 136) * 2;  // 226304
    const int SM_EC  = (2 * 288 * 136 + 2 * 64 * 136) * 2;   // 191488
    const int SM_DZR = (2 * 288 * 72 + 2 * 128 * 72) * 2;    // 119808
    const int SM_DC  = (2 * 288 * 72 + 2 * 64 * 72) * 2;     // 101376
    cudaFuncSetAttribute(gru_mma<4>, cudaFuncAttributeMaxDynamicSharedMemorySize, SM_EZR);
    cudaFuncSetAttribute(gru_mma<2>, cudaFuncAttributeMaxDynamicSharedMemorySize, SM_EC);

    zero_h_kernel<<<8192, 256>>>();

    // pack weights to bf16 hi/lo (per-call; cheap)
    pack_w<<<(25 * 128 * 128 + 255) / 256, 256>>>(enc_gru_wzr, 128, 128, 0, 0);
    pack_w<<<(25 * 64 * 128 + 255) / 256, 256>>>(enc_gru_wc, 64, 128, 0, 409600);
    pack_w<<<(25 * 128 * 64 + 255) / 256, 256>>>(dec_gru_wzr, 128, 64, 64, 614400);
    pack_w<<<(25 * 64 * 64 + 255) / 256, 256>>>(dec_gru_wc, 64, 64, 64, 819200);

    enc_conv1<<<dim3(320, 16), 256>>>(x, enc_w1, enc_b1);
    enc_conv2<<<dim3(320, 4), 256>>>(enc_w2, enc_b2);

    for (int t = 0; t < 10; t++) {
        gru_mma<4><<<dim3(32, 8), 256, SM_EZR>>>(t, 0, 128, 0, enc_gru_bzr, 0, 0);
        gru_mma<2><<<dim3(32, 8), 256, SM_EC>>>(t, 1, 128, 409600, enc_gru_bc, 1, 0);
    }
    for (int t = 0; t < 10; t++) {
        gru_mma<4><<<dim3(32, 8), 256, SM_DZR>>>(t, 2, 64, 614400, dec_gru_bzr, 0, 0);
        gru_mma<2><<<dim3(32, 8), 256, SM_DC>>>(t, 3, 64, 819200, dec_gru_bc, 1, 1);
    }

    deconv1<<<dim3(320, 8), 256>>>(dec_w1, dec_b1);
    deconv2<<<dim3(320, 64), 256>>>(dec_w2, dec_b2, out);
}

// round 4
// speedup vs baseline: 2.5105x; 1.3244x over previous
#include <cuda_runtime.h>
#include <cuda_bf16.h>
#include <math.h>

#define BB 32
#define TT 10

// ---------------- scratch (device globals; no allocs allowed) ----------------
__device__ float g_e1[320 * 16 * 64 * 64];   // encoder conv1 out
__device__ float g_e2[320 * 64 * 32 * 32];   // encoder conv2 out (GRU input)
__device__ float g_h [BB * 64 * 1024];       // GRU hidden state
__device__ float g_zr[BB * 128 * 1024];      // sigmoid(zr) per step
__device__ float g_rh[BB * 64 * 1024];       // r * h per step
__device__ float g_hs[TT * BB * 64 * 1024];  // decoder hidden outputs
__device__ float g_y1[320 * 32 * 64 * 64];   // deconv1 out
__device__ __nv_bfloat16 g_wp[1843200];      // fragment-packed weights hi/lo interleaved

// ---------------- init ----------------
__global__ void zero_h_kernel() {
    int i = blockIdx.x * blockDim.x + threadIdx.x;
    if (i < BB * 64 * 1024) g_h[i] = 0.f;
}

// ---------------- weight packing: fp32 [oc][128][5][5] -> mma-fragment order ----------------
// layout: [tap][kc][ob][lane][hl][r][e]  (e fastest), bf16
// fragment mapping (mma.m16n8k16 A, from ldmatrix.x4 semantics):
//   g=lane>>2, t=lane&3; reg r: row = g + 8*(r&1), colbase = 2t + 8*(r>>1); elem e: col=colbase+e
__global__ void pack_w(const float* __restrict__ w, int OC, int IC, int icoff, int dofs) {
    int idx = blockIdx.x * 256 + threadIdx.x;
    int KC = IC >> 4, NOB = OC >> 4;
    int tot = 25 * OC * IC * 2;
    if (idx >= tot) return;
    int e    = idx & 1;
    int r    = (idx >> 1) & 3;
    int hl   = (idx >> 3) & 1;
    int lane = (idx >> 4) & 31;
    int v    = idx >> 9;
    int ob   = v % NOB;
    int v2   = v / NOB;
    int kc   = v2 % KC;
    int tap  = v2 / KC;
    int g = lane >> 2, t = lane & 3;
    int oc = ob * 16 + g + 8 * (r & 1);
    int ic = kc * 16 + 2 * t + 8 * (r >> 1) + e;
    float val = w[(oc * 128 + icoff + ic) * 25 + tap];
    __nv_bfloat16 hi = __float2bfloat16(val);
    g_wp[dofs + idx] = hl ? __float2bfloat16(val - __bfloat162float(hi)) : hi;
}

// ---------------- mma helper ----------------
__device__ __forceinline__ void mma_bf16(float (&d)[4], const uint4& a, const unsigned (&b)[2]) {
    asm volatile(
        "mma.sync.aligned.m16n8k16.row.col.f32.bf16.bf16.f32 "
        "{%0,%1,%2,%3}, {%4,%5,%6,%7}, {%8,%9}, {%0,%1,%2,%3};\n"
        : "+f"(d[0]), "+f"(d[1]), "+f"(d[2]), "+f"(d[3])
        : "r"(a.x), "r"(a.y), "r"(a.z), "r"(a.w), "r"(b[0]), "r"(b[1]));
}

// ---------------- GRU 5x5 conv via mma.sync, A fragments direct from GMEM ----------------
// src_mode: 0=enc zr (e2[t]++h)  1=enc cand (e2[t]++rh)  2=dec zr (h)  3=dec cand (rh)
// act_mode: 0=sigmoid -> g_zr (+ g_rh=r*h for oc<64); 1=tanh -> h update (+ g_hs)
template <int MT>
__global__ __launch_bounds__(256) void gru_mma(int t, int src_mode, int IC, int wofs,
                                               const float* __restrict__ bias,
                                               int act_mode, int write_hs) {
    extern __shared__ __nv_bfloat16 sm[];
    const int ICP = IC + 8;
    const int NOB = MT * 2;                    // OC/16
    __nv_bfloat16* Xh = sm;                    // [288 px][ICP]
    __nv_bfloat16* Xl = Xh + 288 * ICP;

    int b   = blockIdx.x;
    int y0  = blockIdx.y * 4;
    int tid = threadIdx.x;
    int w   = tid >> 5, lane = tid & 31;
    int g   = lane >> 2, tg = lane & 3;
    int mw  = w >> 2, nw = w & 3;

    const float* s0;
    const float* s1;
    if (src_mode <= 1) {
        s0 = g_e2 + (b * 10 + t) * 65536;
        s1 = (src_mode == 0 ? g_h : g_rh) + b * 65536;
    } else {
        s0 = (src_mode == 2 ? g_h : g_rh) + b * 65536;
        s1 = s0;
    }

    // ---- stage X: [sy 0..7][sx 0..35][ic], channel-last, bf16 hi/lo ----
    int tot = IC * 288;
    for (int idx = tid; idx < tot; idx += 256) {
        int c   = idx / 288;
        int rem = idx - c * 288;
        int sy  = rem / 36, sx = rem - sy * 36;
        int yy  = y0 - 2 + sy, xx = sx - 2;
        float v = 0.f;
        if ((unsigned)yy < 32u && (unsigned)xx < 32u) {
            const float* p = (IC == 128 && c >= 64) ? (s1 + (c - 64) * 1024) : (s0 + c * 1024);
            v = p[yy * 32 + xx];
        }
        __nv_bfloat16 hh = __float2bfloat16(v);
        Xh[rem * ICP + c] = hh;
        Xl[rem * ICP + c] = __float2bfloat16(v - __bfloat162float(hh));
    }
    __syncthreads();

    float D[MT][4][4];
#pragma unroll
    for (int mt = 0; mt < MT; mt++)
#pragma unroll
        for (int nt = 0; nt < 4; nt++)
#pragma unroll
            for (int i = 0; i < 4; i++) D[mt][nt][i] = 0.f;

    const int KC = IC >> 4;
    const uint4* pw = reinterpret_cast<const uint4*>(g_wp) + (wofs >> 3);
    const int FSTEP = NOB * 32;                // frag-index step per kc (also carries across taps)
    const int FLAST = 25 * KC * FSTEP;         // one-past-end frag base

    // preload kc=0 of tap=0
    int fbase = mw * MT * 32 + lane;
    uint4 ah[MT], al[MT];
#pragma unroll
    for (int mt = 0; mt < MT; mt++) {
        int f = 2 * (fbase + mt * 32);
        ah[mt] = pw[f];
        al[mt] = pw[f + 1];
    }

    for (int tap = 0; tap < 25; tap++) {
        int dy = tap / 5, dx = tap - 5 * dy;
        int rowbase = ((nw + dy) * 36 + dx) * ICP;
#pragma unroll 2
        for (int kc = 0; kc < KC; kc++) {
            // prefetch next fragment set (flat across tap boundary; clamp at very end)
            int fn = fbase + FSTEP;
            if (fn >= FLAST + mw * MT * 32 + lane) fn = fbase;
            uint4 nah[MT], nal[MT];
#pragma unroll
            for (int mt = 0; mt < MT; mt++) {
                int f = 2 * (fn + mt * 32);
                nah[mt] = pw[f];
                nal[mt] = pw[f + 1];
            }
            // B fragments from X smem
            unsigned Bh[4][2], Bl[4][2];
#pragma unroll
            for (int nt = 0; nt < 4; nt++) {
                int off = rowbase + (nt * 8 + g) * ICP + kc * 16 + 2 * tg;
                Bh[nt][0] = *(const unsigned*)(Xh + off);
                Bh[nt][1] = *(const unsigned*)(Xh + off + 8);
                Bl[nt][0] = *(const unsigned*)(Xl + off);
                Bl[nt][1] = *(const unsigned*)(Xl + off + 8);
            }
#pragma unroll
            for (int mt = 0; mt < MT; mt++)
#pragma unroll
                for (int nt = 0; nt < 4; nt++) mma_bf16(D[mt][nt], ah[mt], Bh[nt]);
#pragma unroll
            for (int mt = 0; mt < MT; mt++)
#pragma unroll
                for (int nt = 0; nt < 4; nt++) mma_bf16(D[mt][nt], ah[mt], Bl[nt]);
#pragma unroll
            for (int mt = 0; mt < MT; mt++)
#pragma unroll
                for (int nt = 0; nt < 4; nt++) mma_bf16(D[mt][nt], al[mt], Bh[nt]);
#pragma unroll
            for (int mt = 0; mt < MT; mt++) { ah[mt] = nah[mt]; al[mt] = nal[mt]; }
            fbase = fn;
        }
    }

    // ---- fused epilogue ----
    int y = y0 + nw;
#pragma unroll
    for (int mt = 0; mt < MT; mt++) {
#pragma unroll
        for (int ci2 = 0; ci2 < 2; ci2++) {
            int   ocG = mw * MT * 16 + mt * 16 + g + 8 * ci2;
            float bv  = bias[ocG];
#pragma unroll
            for (int nt = 0; nt < 4; nt++) {
#pragma unroll
                for (int j = 0; j < 2; j++) {
                    float v  = D[mt][nt][ci2 * 2 + j] + bv;
                    int   x  = nt * 8 + 2 * tg + j;
                    int   px = y * 32 + x;
                    if (act_mode == 0) {
                        float s = 1.f / (1.f + expf(-v));
                        g_zr[(b * 128 + ocG) * 1024 + px] = s;
                        if (ocG < 64) {
                            int hi = (b * 64 + ocG) * 1024 + px;
                            g_rh[hi] = s * g_h[hi];
                        }
                    } else {
                        float c  = tanhf(v);
                        int   hi = (b * 64 + ocG) * 1024 + px;
                        float z  = g_zr[(b * 128 + 64 + ocG) * 1024 + px];
                        float hp = g_h[hi];
                        float hn = (1.f - z) * hp + z * c;
                        g_h[hi] = hn;
                        if (write_hs) g_hs[t * 2097152 + hi] = hn;
                    }
                }
            }
        }
    }
}

// ---------------- encoder conv1: 1->16 ch, 3x3 s2 p1, 128->64, lrelu ----------------
__global__ __launch_bounds__(256) void enc_conv1(const float* __restrict__ x,
                                                 const float* __restrict__ w,
                                                 const float* __restrict__ bias) {
    __shared__ float sw[144];
    __shared__ float sb[16];
    int tid = threadIdx.x;
    if (tid < 144) sw[tid] = w[tid];
    if (tid < 16)  sb[tid] = bias[tid];
    __syncthreads();
    int n = blockIdx.x;
    int p = blockIdx.y * 256 + tid;
    int oy = p >> 6, ox = p & 63;
    const float* xi = x + n * 16384;
    float win[9];
    int iy0 = 2 * oy - 1, ix0 = 2 * ox - 1;
#pragma unroll
    for (int ky = 0; ky < 3; ky++)
#pragma unroll
        for (int kx = 0; kx < 3; kx++) {
            int iy = iy0 + ky, ix = ix0 + kx;
            win[ky * 3 + kx] = ((unsigned)iy < 128u && (unsigned)ix < 128u) ? xi[iy * 128 + ix] : 0.f;
        }
#pragma unroll
    for (int oc = 0; oc < 16; oc++) {
        float a = sb[oc];
#pragma unroll
        for (int k = 0; k < 9; k++) a += sw[oc * 9 + k] * win[k];
        g_e1[(n * 16 + oc) * 4096 + p] = (a >= 0.f) ? a : 0.2f * a;
    }
}

// ---------------- encoder conv2: 16->64 ch, 3x3 s2 p1, 64->32, lrelu ----------------
__global__ __launch_bounds__(256) void enc_conv2(const float* __restrict__ w,
                                                 const float* __restrict__ bias) {
    __shared__ float sw[64 * 16 * 9];
    int tid = threadIdx.x;
    for (int i = tid; i < 9216; i += 256) sw[i] = w[i];
    __syncthreads();
    int n = blockIdx.x;
    int p = blockIdx.y * 256 + tid;
    int oy = p >> 5, ox = p & 31;
    const float* in = g_e1 + n * 65536;
    float acc[64];
#pragma unroll
    for (int oc = 0; oc < 64; oc++) acc[oc] = bias[oc];
    int iy0 = 2 * oy - 1, ix0 = 2 * ox - 1;
#pragma unroll 1
    for (int ic = 0; ic < 16; ic++) {
        float win[9];
#pragma unroll
        for (int ky = 0; ky < 3; ky++)
#pragma unroll
            for (int kx = 0; kx < 3; kx++) {
                int iy = iy0 + ky, ix = ix0 + kx;
                win[ky * 3 + kx] = ((unsigned)iy < 64u && (unsigned)ix < 64u)
                                       ? in[ic * 4096 + iy * 64 + ix] : 0.f;
            }
#pragma unroll
        for (int oc = 0; oc < 64; oc++) {
#pragma unroll
            for (int k = 0; k < 9; k++) acc[oc] += sw[(oc * 16 + ic) * 9 + k] * win[k];
        }
    }
#pragma unroll
    for (int oc = 0; oc < 64; oc++) {
        float a = acc[oc];
        g_e2[(n * 64 + oc) * 1024 + p] = (a >= 0.f) ? a : 0.2f * a;
    }
}

// ---------------- deconv1: 64->32 ch, 4x4 lhs_dilation 2 pad 2, 32->64, lrelu ----------------
__global__ __launch_bounds__(256) void deconv1(const float* __restrict__ w,
                                               const float* __restrict__ bias) {
    __shared__ float s_in[8 * 1024];
    __shared__ float s_w[4 * 8 * 16];
    int n   = blockIdx.x;
    int ocg = blockIdx.y;
    int tid = threadIdx.x;
    int oy  = tid >> 2;
    int ox0 = (tid & 3) << 4;

    float acc[4][16];
#pragma unroll
    for (int i = 0; i < 4; i++)
#pragma unroll
        for (int j = 0; j < 16; j++) acc[i][j] = 0.f;

    int ky0 = oy & 1;
    int iyA = (oy + ky0 - 2) >> 1;
    int iyB = iyA + 1;
    const float* in = g_hs + n * 65536;
    int ixbase = (ox0 >> 1) - 1;

#pragma unroll 1
    for (int cc = 0; cc < 8; cc++) {
        int ic0 = cc * 8;
        for (int idx = tid; idx < 8192; idx += 256) s_in[idx] = in[ic0 * 1024 + idx];
        for (int idx = tid; idx < 512; idx += 256) {
            int oc  = idx >> 7;
            int rem = idx & 127;
            int ic  = rem >> 4;
            int k   = rem & 15;
            s_w[idx] = w[((ocg * 4 + oc) * 64 + ic0 + ic) * 16 + k];
        }
        __syncthreads();
#pragma unroll 1
        for (int ic = 0; ic < 8; ic++) {
            float segA[10], segB[10];
#pragma unroll
            for (int m = 0; m < 10; m++) {
                int ix = ixbase + m;
                bool xok = (unsigned)ix < 32u;
                segA[m] = (xok && (unsigned)iyA < 32u) ? s_in[ic * 1024 + iyA * 32 + ix] : 0.f;
                segB[m] = (xok && (unsigned)iyB < 32u) ? s_in[ic * 1024 + iyB * 32 + ix] : 0.f;
            }
#pragma unroll
            for (int j = 0; j < 16; j++) {
                int kx0 = j & 1;
                int mA  = (j + kx0) >> 1;
                int mB  = mA + 1;
                float vAA = segA[mA], vAB = segA[mB];
                float vBA = segB[mA], vBB = segB[mB];
#pragma unroll
                for (int oc = 0; oc < 4; oc++) {
                    const float* wp = &s_w[(oc * 8 + ic) * 16];
                    acc[oc][j] += wp[ky0 * 4 + kx0]       * vAA
                                + wp[ky0 * 4 + kx0 + 2]   * vAB
                                + wp[(ky0 + 2) * 4 + kx0] * vBA
                                + wp[(ky0 + 2) * 4 + kx0 + 2] * vBB;
                }
            }
        }
        __syncthreads();
    }
#pragma unroll
    for (int oc = 0; oc < 4; oc++) {
        int ocG = ocg * 4 + oc;
        float bv = bias[ocG];
#pragma unroll
        for (int j = 0; j < 16; j++) {
            float a = acc[oc][j] + bv;
            g_y1[(n * 32 + ocG) * 4096 + oy * 64 + ox0 + j] = (a >= 0.f) ? a : 0.2f * a;
        }
    }
}

// ---------------- deconv2: 32->1 ch, 4x4 lhs_dilation 2 pad 2, 64->128, + transpose ----------------
__global__ __launch_bounds__(256) void deconv2(const float* __restrict__ w,
                                               const float* __restrict__ bias,
                                               float* __restrict__ out) {
    __shared__ float sw[512];
    int tid = threadIdx.x;
    for (int i = tid; i < 512; i += 256) sw[i] = w[i];
    __syncthreads();
    int n = blockIdx.x;
    int p = blockIdx.y * 256 + tid;
    int oy = p >> 7, ox = p & 127;
    int ky0 = oy & 1, kx0 = ox & 1;
    int iyA = (oy + ky0 - 2) >> 1, iyB = iyA + 1;
    int ixA = (ox + kx0 - 2) >> 1, ixB = ixA + 1;
    bool yA = (unsigned)iyA < 64u, yB = (unsigned)iyB < 64u;
    bool xA = (unsigned)ixA < 64u, xB = (unsigned)ixB < 64u;
    const float* in = g_y1 + n * 131072;
    float acc = bias[0];
#pragma unroll 1
    for (int ic = 0; ic < 32; ic++) {
        const float* ip = in + ic * 4096;
        float vAA = (yA && xA) ? ip[iyA * 64 + ixA] : 0.f;
        float vAB = (yA && xB) ? ip[iyA * 64 + ixB] : 0.f;
        float vBA = (yB && xA) ? ip[iyB * 64 + ixA] : 0.f;
        float vBB = (yB && xB) ? ip[iyB * 64 + ixB] : 0.f;
        const float* wp = &sw[ic * 16];
        acc += wp[ky0 * 4 + kx0]           * vAA
             + wp[ky0 * 4 + kx0 + 2]       * vAB
             + wp[(ky0 + 2) * 4 + kx0]     * vBA
             + wp[(ky0 + 2) * 4 + kx0 + 2] * vBB;
    }
    int t = n >> 5, b = n & 31;
    out[(b * 10 + t) * 16384 + p] = acc;
}

// ---------------- launch ----------------
extern "C" void kernel_launch(void* const* d_in, const int* in_sizes, int n_in,
                              void* d_out, int out_size) {
    const float* x            = (const float*)d_in[0];
    const float* enc_w1       = (const float*)d_in[1];
    const float* enc_b1       = (const float*)d_in[2];
    const float* enc_w2       = (const float*)d_in[3];
    const float* enc_b2       = (const float*)d_in[4];
    const float* enc_gru_wzr  = (const float*)d_in[5];
    const float* enc_gru_bzr  = (const float*)d_in[6];
    const float* enc_gru_wc   = (const float*)d_in[7];
    const float* enc_gru_bc   = (const float*)d_in[8];
    const float* dec_gru_wzr  = (const float*)d_in[9];
    const float* dec_gru_bzr  = (const float*)d_in[10];
    const float* dec_gru_wc   = (const float*)d_in[11];
    const float* dec_gru_bc   = (const float*)d_in[12];
    const float* dec_w1       = (const float*)d_in[13];
    const float* dec_b1       = (const float*)d_in[14];
    const float* dec_w2       = (const float*)d_in[15];
    const float* dec_b2       = (const float*)d_in[16];
    float* out = (float*)d_out;

    // X-only smem: 2 * 288 * ICP * 2B
    const int SM_ENC = 2 * 288 * 136 * 2;  // 156672 (IC=128)
    const int SM_DEC = 2 * 288 * 72 * 2;   //  82944 (IC=64) -> 2 CTAs/SM
    cudaFuncSetAttribute(gru_mma<4>, cudaFuncAttributeMaxDynamicSharedMemorySize, SM_ENC);
    cudaFuncSetAttribute(gru_mma<2>, cudaFuncAttributeMaxDynamicSharedMemorySize, SM_ENC);

    zero_h_kernel<<<8192, 256>>>();

    // pack weights into fragment order (hi/lo interleaved)
    pack_w<<<(25 * 128 * 128 * 2 + 255) / 256, 256>>>(enc_gru_wzr, 128, 128, 0, 0);
    pack_w<<<(25 * 64 * 128 * 2 + 255) / 256, 256>>>(enc_gru_wc, 64, 128, 0, 819200);
    pack_w<<<(25 * 128 * 64 * 2 + 255) / 256, 256>>>(dec_gru_wzr, 128, 64, 64, 1228800);
    pack_w<<<(25 * 64 * 64 * 2 + 255) / 256, 256>>>(dec_gru_wc, 64, 64, 64, 1638400);

    enc_conv1<<<dim3(320, 16), 256>>>(x, enc_w1, enc_b1);
    enc_conv2<<<dim3(320, 4), 256>>>(enc_w2, enc_b2);

    for (int t = 0; t < 10; t++) {
        gru_mma<4><<<dim3(32, 8), 256, SM_ENC>>>(t, 0, 128, 0, enc_gru_bzr, 0, 0);
        gru_mma<2><<<dim3(32, 8), 256, SM_ENC>>>(t, 1, 128, 819200, enc_gru_bc, 1, 0);
    }
    for (int t = 0; t < 10; t++) {
        gru_mma<4><<<dim3(32, 8), 256, SM_DEC>>>(t, 2, 64, 1228800, dec_gru_bzr, 0, 0);
        gru_mma<2><<<dim3(32, 8), 256, SM_DEC>>>(t, 3, 64, 1638400, dec_gru_bc, 1, 1);
    }

    deconv1<<<dim3(320, 8), 256>>>(dec_w1, dec_b1);
    deconv2<<<dim3(320, 64), 256>>>(dec_w2, dec_b2, out);
}

// round 5
// speedup vs baseline: 3.1994x; 1.2744x over previous
#include <cuda_runtime.h>
#include <cuda_bf16.h>
#include <math.h>

#define BB 32
#define TT 10

// ---------------- scratch (device globals; no allocs allowed) ----------------
__device__ float g_e1[320 * 16 * 64 * 64];   // encoder conv1 out
__device__ float g_e2[320 * 64 * 32 * 32];   // encoder conv2 out (GRU input)
__device__ float g_h [BB * 64 * 1024];       // GRU hidden state
__device__ float g_zr[BB * 128 * 1024];      // sigmoid(zr) per step
__device__ float g_rh[BB * 64 * 1024];       // r * h per step
__device__ float g_hs[TT * BB * 64 * 1024];  // decoder hidden outputs
__device__ float g_y1[320 * 32 * 64 * 64];   // deconv1 out
__device__ __nv_bfloat16 g_wp[1843200];      // fragment-packed weights hi/lo interleaved

// ---------------- init ----------------
__global__ void zero_h_kernel() {
    int i = blockIdx.x * blockDim.x + threadIdx.x;
    if (i < BB * 64 * 1024) g_h[i] = 0.f;
}

// ---------------- weight packing: fp32 [oc][128][5][5] -> mma-fragment order ----------------
// layout: [tap][kc][ob][lane][hl][r][e]  (e fastest), bf16
__global__ void pack_w(const float* __restrict__ w, int OC, int IC, int icoff, int dofs) {
    int idx = blockIdx.x * 256 + threadIdx.x;
    int KC = IC >> 4, NOB = OC >> 4;
    int tot = 25 * OC * IC * 2;
    if (idx >= tot) return;
    int e    = idx & 1;
    int r    = (idx >> 1) & 3;
    int hl   = (idx >> 3) & 1;
    int lane = (idx >> 4) & 31;
    int v    = idx >> 9;
    int ob   = v % NOB;
    int v2   = v / NOB;
    int kc   = v2 % KC;
    int tap  = v2 / KC;
    int g = lane >> 2, t = lane & 3;
    int oc = ob * 16 + g + 8 * (r & 1);
    int ic = kc * 16 + 2 * t + 8 * (r >> 1) + e;
    float val = w[(oc * 128 + icoff + ic) * 25 + tap];
    __nv_bfloat16 hi = __float2bfloat16(val);
    g_wp[dofs + idx] = hl ? __float2bfloat16(val - __bfloat162float(hi)) : hi;
}

// ---------------- mma helper ----------------
__device__ __forceinline__ void mma_bf16(float (&d)[4], const uint4& a, const unsigned (&b)[2]) {
    asm volatile(
        "mma.sync.aligned.m16n8k16.row.col.f32.bf16.bf16.f32 "
        "{%0,%1,%2,%3}, {%4,%5,%6,%7}, {%8,%9}, {%0,%1,%2,%3};\n"
        : "+f"(d[0]), "+f"(d[1]), "+f"(d[2]), "+f"(d[3])
        : "r"(a.x), "r"(a.y), "r"(a.z), "r"(a.w), "r"(b[0]), "r"(b[1]));
}

// ---------------- GRU 5x5 conv via mma.sync; IC processed in 64-ch halves ----------------
// CTA: 256 thr (8 warps: mw=w>>2 in {0,1}, nw=w&3), covers 64 oc (blockIdx.z selects oc-half)
// src_mode: 0=enc zr (e2[t] ++ h)  1=enc cand (e2[t] ++ rh)  2=dec zr (h)  3=dec cand (rh)
// act_mode: 0=sigmoid -> g_zr (+ g_rh=r*h for oc<64); 1=tanh -> h update (+ g_hs)
template <int NH>
__global__ __launch_bounds__(256, 2) void gru2(int t, int src_mode, int nob, int wofs,
                                               const float* __restrict__ bias,
                                               int act_mode, int write_hs) {
    extern __shared__ __nv_bfloat16 sm[];
    __nv_bfloat16* Xh = sm;                 // [288 px][72]
    __nv_bfloat16* Xl = sm + 288 * 72;

    int b   = blockIdx.x;
    int y0  = blockIdx.y * 4;
    int och = blockIdx.z;
    int tid = threadIdx.x;
    int w   = tid >> 5, lane = tid & 31;
    int g   = lane >> 2, tg = lane & 3;
    int mw  = w >> 2, nw = w & 3;

    const float* s0;
    const float* s1;
    if (src_mode <= 1) {
        s0 = g_e2 + (b * 10 + t) * 65536;
        s1 = (src_mode == 0 ? g_h : g_rh) + b * 65536;
    } else {
        s0 = (src_mode == 2 ? g_h : g_rh) + b * 65536;
        s1 = s0;
    }

    float D[2][4][4];
#pragma unroll
    for (int mt = 0; mt < 2; mt++)
#pragma unroll
        for (int nt = 0; nt < 4; nt++)
#pragma unroll
            for (int i = 0; i < 4; i++) D[mt][nt][i] = 0.f;

    const uint4* pw = reinterpret_cast<const uint4*>(g_wp) + (wofs >> 3);
    const int KC = NH * 4;
    const int S1 = nob * 32;
    const int S2 = (KC - 3) * nob * 32;
    const int ob0 = och * 4 + mw * 2;

#pragma unroll 1
    for (int h = 0; h < NH; h++) {
        if (h) __syncthreads();             // all reads of prev half done before overwrite
        // ---- stage 64-channel half: [sy 0..7][sx 0..35][c 0..63], bf16 hi/lo ----
        const float* base = (h == 0) ? s0 : s1;
        int c = tid & 63;
#pragma unroll
        for (int it = 0; it < 2; it++) {
            int sy = (tid >> 6) | (it << 2);
            int yy = y0 - 2 + sy;
            bool rv = (unsigned)yy < 32u;
            const float4* src = (const float4*)(base + c * 1024 + yy * 32);
            float4 q[8];
            if (rv) {
#pragma unroll
                for (int k2 = 0; k2 < 8; k2++) q[k2] = src[k2];
            } else {
#pragma unroll
                for (int k2 = 0; k2 < 8; k2++) q[k2] = make_float4(0.f, 0.f, 0.f, 0.f);
            }
            int rb = sy * 36;
#pragma unroll
            for (int sx = 0; sx < 36; sx++) {
                float v;
                if (sx < 2 || sx >= 34) v = 0.f;
                else {
                    int x = sx - 2;
                    float4 qq = q[x >> 2];
                    v = ((x & 3) == 0) ? qq.x : ((x & 3) == 1) ? qq.y : ((x & 3) == 2) ? qq.z : qq.w;
                }
                __nv_bfloat16 hi = __float2bfloat16(v);
                Xh[(rb + sx) * 72 + c] = hi;
                Xl[(rb + sx) * 72 + c] = __float2bfloat16(v - __bfloat162float(hi));
            }
        }
        __syncthreads();

        // ---- MMA over taps x 4 k-chunks of this half ----
        int fb = (h * 4 * nob + ob0) * 32 + lane;
        uint4 ah[2], al[2];
#pragma unroll
        for (int mt = 0; mt < 2; mt++) {
            ah[mt] = pw[2 * (fb + mt * 32)];
            al[mt] = pw[2 * (fb + mt * 32) + 1];
        }
#pragma unroll 1
        for (int tap = 0; tap < 25; tap++) {
            int dy = tap / 5, dx = tap - 5 * dy;
            int rowbase = ((nw + dy) * 36 + dx) * 72;
#pragma unroll
            for (int kch = 0; kch < 4; kch++) {
                int fn = (tap == 24 && kch == 3) ? fb : fb + (kch < 3 ? S1 : S2);
                uint4 nah[2], nal[2];
#pragma unroll
                for (int mt = 0; mt < 2; mt++) {
                    nah[mt] = pw[2 * (fn + mt * 32)];
                    nal[mt] = pw[2 * (fn + mt * 32) + 1];
                }
                unsigned Bh[4][2], Bl[4][2];
#pragma unroll
                for (int nt = 0; nt < 4; nt++) {
                    int off = rowbase + (nt * 8 + g) * 72 + kch * 16 + 2 * tg;
                    Bh[nt][0] = *(const unsigned*)(Xh + off);
                    Bh[nt][1] = *(const unsigned*)(Xh + off + 8);
                    Bl[nt][0] = *(const unsigned*)(Xl + off);
                    Bl[nt][1] = *(const unsigned*)(Xl + off + 8);
                }
#pragma unroll
                for (int mt = 0; mt < 2; mt++)
#pragma unroll
                    for (int nt = 0; nt < 4; nt++) mma_bf16(D[mt][nt], ah[mt], Bh[nt]);
#pragma unroll
                for (int mt = 0; mt < 2; mt++)
#pragma unroll
                    for (int nt = 0; nt < 4; nt++) mma_bf16(D[mt][nt], ah[mt], Bl[nt]);
#pragma unroll
                for (int mt = 0; mt < 2; mt++)
#pragma unroll
                    for (int nt = 0; nt < 4; nt++) mma_bf16(D[mt][nt], al[mt], Bh[nt]);
#pragma unroll
                for (int mt = 0; mt < 2; mt++) { ah[mt] = nah[mt]; al[mt] = nal[mt]; }
                fb = fn;
            }
        }
    }

    // ---- fused epilogue ----
    int y = y0 + nw;
#pragma unroll
    for (int mt = 0; mt < 2; mt++) {
#pragma unroll
        for (int ci2 = 0; ci2 < 2; ci2++) {
            int   ocG = och * 64 + mw * 32 + mt * 16 + g + 8 * ci2;
            float bv  = bias[ocG];
#pragma unroll
            for (int nt = 0; nt < 4; nt++) {
#pragma unroll
                for (int j = 0; j < 2; j++) {
                    float v  = D[mt][nt][ci2 * 2 + j] + bv;
                    int   x  = nt * 8 + 2 * tg + j;
                    int   px = y * 32 + x;
                    if (act_mode == 0) {
                        float s = 1.f / (1.f + expf(-v));
                        g_zr[(b * 128 + ocG) * 1024 + px] = s;
                        if (ocG < 64) {
                            int hi = (b * 64 + ocG) * 1024 + px;
                            g_rh[hi] = s * g_h[hi];
                        }
                    } else {
                        float c  = tanhf(v);
                        int   hi = (b * 64 + ocG) * 1024 + px;
                        float z  = g_zr[(b * 128 + 64 + ocG) * 1024 + px];
                        float hp = g_h[hi];
                        float hn = (1.f - z) * hp + z * c;
                        g_h[hi] = hn;
                        if (write_hs) g_hs[t * 2097152 + hi] = hn;
                    }
                }
            }
        }
    }
}

// ---------------- encoder conv1: 1->16 ch, 3x3 s2 p1, 128->64, lrelu ----------------
__global__ __launch_bounds__(256) void enc_conv1(const float* __restrict__ x,
                                                 const float* __restrict__ w,
                                                 const float* __restrict__ bias) {
    __shared__ float sw[144];
    __shared__ float sb[16];
    int tid = threadIdx.x;
    if (tid < 144) sw[tid] = w[tid];
    if (tid < 16)  sb[tid] = bias[tid];
    __syncthreads();
    int n = blockIdx.x;
    int p = blockIdx.y * 256 + tid;
    int oy = p >> 6, ox = p & 63;
    const float* xi = x + n * 16384;
    float win[9];
    int iy0 = 2 * oy - 1, ix0 = 2 * ox - 1;
#pragma unroll
    for (int ky = 0; ky < 3; ky++)
#pragma unroll
        for (int kx = 0; kx < 3; kx++) {
            int iy = iy0 + ky, ix = ix0 + kx;
            win[ky * 3 + kx] = ((unsigned)iy < 128u && (unsigned)ix < 128u) ? xi[iy * 128 + ix] : 0.f;
        }
#pragma unroll
    for (int oc = 0; oc < 16; oc++) {
        float a = sb[oc];
#pragma unroll
        for (int k = 0; k < 9; k++) a += sw[oc * 9 + k] * win[k];
        g_e1[(n * 16 + oc) * 4096 + p] = (a >= 0.f) ? a : 0.2f * a;
    }
}

// ---------------- encoder conv2: 16->64 ch, 3x3 s2 p1, 64->32, lrelu ----------------
__global__ __launch_bounds__(256) void enc_conv2(const float* __restrict__ w,
                                                 const float* __restrict__ bias) {
    __shared__ float sw[64 * 16 * 9];
    int tid = threadIdx.x;
    for (int i = tid; i < 9216; i += 256) sw[i] = w[i];
    __syncthreads();
    int n = blockIdx.x;
    int p = blockIdx.y * 256 + tid;
    int oy = p >> 5, ox = p & 31;
    const float* in = g_e1 + n * 65536;
    float acc[64];
#pragma unroll
    for (int oc = 0; oc < 64; oc++) acc[oc] = bias[oc];
    int iy0 = 2 * oy - 1, ix0 = 2 * ox - 1;
#pragma unroll 1
    for (int ic = 0; ic < 16; ic++) {
        float win[9];
#pragma unroll
        for (int ky = 0; ky < 3; ky++)
#pragma unroll
            for (int kx = 0; kx < 3; kx++) {
                int iy = iy0 + ky, ix = ix0 + kx;
                win[ky * 3 + kx] = ((unsigned)iy < 64u && (unsigned)ix < 64u)
                                       ? in[ic * 4096 + iy * 64 + ix] : 0.f;
            }
#pragma unroll
        for (int oc = 0; oc < 64; oc++) {
#pragma unroll
            for (int k = 0; k < 9; k++) acc[oc] += sw[(oc * 16 + ic) * 9 + k] * win[k];
        }
    }
#pragma unroll
    for (int oc = 0; oc < 64; oc++) {
        float a = acc[oc];
        g_e2[(n * 64 + oc) * 1024 + p] = (a >= 0.f) ? a : 0.2f * a;
    }
}

// ---------------- deconv1: 64->32 ch, 4x4 lhs_dilation 2 pad 2, 32->64, lrelu ----------------
__global__ __launch_bounds__(256) void deconv1(const float* __restrict__ w,
                                               const float* __restrict__ bias) {
    __shared__ float s_in[8 * 1024];
    __shared__ float s_w[4 * 8 * 16];
    int n   = blockIdx.x;
    int ocg = blockIdx.y;
    int tid = threadIdx.x;
    int oy  = tid >> 2;
    int ox0 = (tid & 3) << 4;

    float acc[4][16];
#pragma unroll
    for (int i = 0; i < 4; i++)
#pragma unroll
        for (int j = 0; j < 16; j++) acc[i][j] = 0.f;

    int ky0 = oy & 1;
    int iyA = (oy + ky0 - 2) >> 1;
    int iyB = iyA + 1;
    const float* in = g_hs + n * 65536;
    int ixbase = (ox0 >> 1) - 1;

#pragma unroll 1
    for (int cc = 0; cc < 8; cc++) {
        int ic0 = cc * 8;
        for (int idx = tid; idx < 8192; idx += 256) s_in[idx] = in[ic0 * 1024 + idx];
        for (int idx = tid; idx < 512; idx += 256) {
            int oc  = idx >> 7;
            int rem = idx & 127;
            int ic  = rem >> 4;
            int k   = rem & 15;
            s_w[idx] = w[((ocg * 4 + oc) * 64 + ic0 + ic) * 16 + k];
        }
        __syncthreads();
#pragma unroll 1
        for (int ic = 0; ic < 8; ic++) {
            float segA[10], segB[10];
#pragma unroll
            for (int m = 0; m < 10; m++) {
                int ix = ixbase + m;
                bool xok = (unsigned)ix < 32u;
                segA[m] = (xok && (unsigned)iyA < 32u) ? s_in[ic * 1024 + iyA * 32 + ix] : 0.f;
                segB[m] = (xok && (unsigned)iyB < 32u) ? s_in[ic * 1024 + iyB * 32 + ix] : 0.f;
            }
#pragma unroll
            for (int j = 0; j < 16; j++) {
                int kx0 = j & 1;
                int mA  = (j + kx0) >> 1;
                int mB  = mA + 1;
                float vAA = segA[mA], vAB = segA[mB];
                float vBA = segB[mA], vBB = segB[mB];
#pragma unroll
                for (int oc = 0; oc < 4; oc++) {
                    const float* wp = &s_w[(oc * 8 + ic) * 16];
                    acc[oc][j] += wp[ky0 * 4 + kx0]       * vAA
                                + wp[ky0 * 4 + kx0 + 2]   * vAB
                                + wp[(ky0 + 2) * 4 + kx0] * vBA
                                + wp[(ky0 + 2) * 4 + kx0 + 2] * vBB;
                }
            }
        }
        __syncthreads();
    }
#pragma unroll
    for (int oc = 0; oc < 4; oc++) {
        int ocG = ocg * 4 + oc;
        float bv = bias[ocG];
#pragma unroll
        for (int j = 0; j < 16; j++) {
            float a = acc[oc][j] + bv;
            g_y1[(n * 32 + ocG) * 4096 + oy * 64 + ox0 + j] = (a >= 0.f) ? a : 0.2f * a;
        }
    }
}

// ---------------- deconv2: 32->1 ch, 4x4 lhs_dilation 2 pad 2, 64->128, + transpose ----------------
__global__ __launch_bounds__(256) void deconv2(const float* __restrict__ w,
                                               const float* __restrict__ bias,
                                               float* __restrict__ out) {
    __shared__ float sw[512];
    int tid = threadIdx.x;
    for (int i = tid; i < 512; i += 256) sw[i] = w[i];
    __syncthreads();
    int n = blockIdx.x;
    int p = blockIdx.y * 256 + tid;
    int oy = p >> 7, ox = p & 127;
    int ky0 = oy & 1, kx0 = ox & 1;
    int iyA = (oy + ky0 - 2) >> 1, iyB = iyA + 1;
    int ixA = (ox + kx0 - 2) >> 1, ixB = ixA + 1;
    bool yA = (unsigned)iyA < 64u, yB = (unsigned)iyB < 64u;
    bool xA = (unsigned)ixA < 64u, xB = (unsigned)ixB < 64u;
    const float* in = g_y1 + n * 131072;
    float acc = bias[0];
#pragma unroll 1
    for (int ic = 0; ic < 32; ic++) {
        const float* ip = in + ic * 4096;
        float vAA = (yA && xA) ? ip[iyA * 64 + ixA] : 0.f;
        float vAB = (yA && xB) ? ip[iyA * 64 + ixB] : 0.f;
        float vBA = (yB && xA) ? ip[iyB * 64 + ixA] : 0.f;
        float vBB = (yB && xB) ? ip[iyB * 64 + ixB] : 0.f;
        const float* wp = &sw[ic * 16];
        acc += wp[ky0 * 4 + kx0]           * vAA
             + wp[ky0 * 4 + kx0 + 2]       * vAB
             + wp[(ky0 + 2) * 4 + kx0]     * vBA
             + wp[(ky0 + 2) * 4 + kx0 + 2] * vBB;
    }
    int t = n >> 5, b = n & 31;
    out[(b * 10 + t) * 16384 + p] = acc;
}

// ---------------- launch ----------------
extern "C" void kernel_launch(void* const* d_in, const int* in_sizes, int n_in,
                              void* d_out, int out_size) {
    const float* x            = (const float*)d_in[0];
    const float* enc_w1       = (const float*)d_in[1];
    const float* enc_b1       = (const float*)d_in[2];
    const float* enc_w2       = (const float*)d_in[3];
    const float* enc_b2       = (const float*)d_in[4];
    const float* enc_gru_wzr  = (const float*)d_in[5];
    const float* enc_gru_bzr  = (const float*)d_in[6];
    const float* enc_gru_wc   = (const float*)d_in[7];
    const float* enc_gru_bc   = (const float*)d_in[8];
    const float* dec_gru_wzr  = (const float*)d_in[9];
    const float* dec_gru_bzr  = (const float*)d_in[10];
    const float* dec_gru_wc   = (const float*)d_in[11];
    const float* dec_gru_bc   = (const float*)d_in[12];
    const float* dec_w1       = (const float*)d_in[13];
    const float* dec_b1       = (const float*)d_in[14];
    const float* dec_w2       = (const float*)d_in[15];
    const float* dec_b2       = (const float*)d_in[16];
    float* out = (float*)d_out;

    const int SMB = 2 * 288 * 72 * 2;   // 82944 bytes -> 2 CTAs/SM
    cudaFuncSetAttribute(gru2<2>, cudaFuncAttributeMaxDynamicSharedMemorySize, SMB);
    cudaFuncSetAttribute(gru2<1>, cudaFuncAttributeMaxDynamicSharedMemorySize, SMB);

    zero_h_kernel<<<8192, 256>>>();

    pack_w<<<(25 * 128 * 128 * 2 + 255) / 256, 256>>>(enc_gru_wzr, 128, 128, 0, 0);
    pack_w<<<(25 * 64 * 128 * 2 + 255) / 256, 256>>>(enc_gru_wc, 64, 128, 0, 819200);
    pack_w<<<(25 * 128 * 64 * 2 + 255) / 256, 256>>>(dec_gru_wzr, 128, 64, 64, 1228800);
    pack_w<<<(25 * 64 * 64 * 2 + 255) / 256, 256>>>(dec_gru_wc, 64, 64, 64, 1638400);

    enc_conv1<<<dim3(320, 16), 256>>>(x, enc_w1, enc_b1);
    enc_conv2<<<dim3(320, 4), 256>>>(enc_w2, enc_b2);

    for (int t = 0; t < 10; t++) {
        gru2<2><<<dim3(32, 8, 2), 256, SMB>>>(t, 0, 8, 0, enc_gru_bzr, 0, 0);
        gru2<2><<<dim3(32, 8, 1), 256, SMB>>>(t, 1, 4, 819200, enc_gru_bc, 1, 0);
    }
    for (int t = 0; t < 10; t++) {
        gru2<1><<<dim3(32, 8, 2), 256, SMB>>>(t, 2, 8, 1228800, dec_gru_bzr, 0, 0);
        gru2<1><<<dim3(32, 8, 1), 256, SMB>>>(t, 3, 4, 1638400, dec_gru_bc, 1, 1);
    }

    deconv1<<<dim3(320, 8), 256>>>(dec_w1, dec_b1);
    deconv2<<<dim3(320, 64), 256>>>(dec_w2, dec_b2, out);
}

// round 6
// speedup vs baseline: 3.2728x; 1.0230x over previous
#include <cuda_runtime.h>
#include <cuda_bf16.h>
#include <math.h>

#define BB 32
#define TT 10

// ---------------- scratch (device globals; no allocs allowed) ----------------
__device__ float g_e1[320 * 16 * 64 * 64];   // encoder conv1 out
__device__ float g_e2[320 * 64 * 32 * 32];   // encoder conv2 out (GRU input)
__device__ float g_h [BB * 64 * 1024];       // GRU hidden state
__device__ float g_zr[BB * 128 * 1024];      // sigmoid(zr) per step
__device__ float g_rh[BB * 64 * 1024];       // r * h per step
__device__ float g_hs[TT * BB * 64 * 1024];  // decoder hidden outputs
__device__ float g_y1[320 * 32 * 64 * 64];   // deconv1 out
__device__ __nv_bfloat16 g_wp[1843200];      // fragment-packed weights hi/lo interleaved

// ---------------- init ----------------
__global__ void zero_h_kernel() {
    int i = blockIdx.x * blockDim.x + threadIdx.x;
    if (i < BB * 64 * 1024) g_h[i] = 0.f;
}

// ---------------- weight packing: fp32 [oc][128][5][5] -> mma-fragment order ----------------
// layout: [tap][kc][ob][lane][hl][r][e]  (e fastest), bf16
__global__ void pack_w(const float* __restrict__ w, int OC, int IC, int icoff, int dofs) {
    int idx = blockIdx.x * 256 + threadIdx.x;
    int KC = IC >> 4, NOB = OC >> 4;
    int tot = 25 * OC * IC * 2;
    if (idx >= tot) return;
    int e    = idx & 1;
    int r    = (idx >> 1) & 3;
    int hl   = (idx >> 3) & 1;
    int lane = (idx >> 4) & 31;
    int v    = idx >> 9;
    int ob   = v % NOB;
    int v2   = v / NOB;
    int kc   = v2 % KC;
    int tap  = v2 / KC;
    int g = lane >> 2, t = lane & 3;
    int oc = ob * 16 + g + 8 * (r & 1);
    int ic = kc * 16 + 2 * t + 8 * (r >> 1) + e;
    float val = w[(oc * 128 + icoff + ic) * 25 + tap];
    __nv_bfloat16 hi = __float2bfloat16(val);
    g_wp[dofs + idx] = hl ? __float2bfloat16(val - __bfloat162float(hi)) : hi;
}

// ---------------- mma helper ----------------
__device__ __forceinline__ void mma_bf16(float (&d)[4], const uint4& a, const unsigned (&b)[2]) {
    asm volatile(
        "mma.sync.aligned.m16n8k16.row.col.f32.bf16.bf16.f32 "
        "{%0,%1,%2,%3}, {%4,%5,%6,%7}, {%8,%9}, {%0,%1,%2,%3};\n"
        : "+f"(d[0]), "+f"(d[1]), "+f"(d[2]), "+f"(d[3])
        : "r"(a.x), "r"(a.y), "r"(a.z), "r"(a.w), "r"(b[0]), "r"(b[1]));
}

// ---------------- GRU 5x5 conv via mma.sync; IC processed in 64-ch halves ----------------
// CTA: 256 thr (8 warps: mw=w>>2 in {0,1}, nw=w&3), covers 64 oc (blockIdx.z selects oc-half)
// src_mode: 0=enc zr (e2[t] ++ h)  1=enc cand (e2[t] ++ rh)  2=dec zr (h)  3=dec cand (rh)
// act_mode: 0=sigmoid -> g_zr (+ g_rh=r*h for oc<64); 1=tanh -> h update (+ g_hs)
template <int NH>
__global__ __launch_bounds__(256, 2) void gru2(int t, int src_mode, int nob, int wofs,
                                               const float* __restrict__ bias,
                                               int act_mode, int write_hs) {
    extern __shared__ __nv_bfloat16 sm[];
    __nv_bfloat16* Xh = sm;                 // [288 px][72]
    __nv_bfloat16* Xl = sm + 288 * 72;

    int b   = blockIdx.x;
    int y0  = blockIdx.y * 4;
    int och = blockIdx.z;
    int tid = threadIdx.x;
    int w   = tid >> 5, lane = tid & 31;
    int g   = lane >> 2, tg = lane & 3;
    int mw  = w >> 2, nw = w & 3;

    const float* s0;
    const float* s1;
    if (src_mode <= 1) {
        s0 = g_e2 + (b * 10 + t) * 65536;
        s1 = (src_mode == 0 ? g_h : g_rh) + b * 65536;
    } else {
        s0 = (src_mode == 2 ? g_h : g_rh) + b * 65536;
        s1 = s0;
    }

    float D[2][4][4];
#pragma unroll
    for (int mt = 0; mt < 2; mt++)
#pragma unroll
        for (int nt = 0; nt < 4; nt++)
#pragma unroll
            for (int i = 0; i < 4; i++) D[mt][nt][i] = 0.f;

    const uint4* pw = reinterpret_cast<const uint4*>(g_wp) + (wofs >> 3);
    const int KC = NH * 4;
    const int S1 = nob * 32;
    const int S2 = (KC - 3) * nob * 32;
    const int ob0 = och * 4 + mw * 2;

#pragma unroll 1
    for (int h = 0; h < NH; h++) {
        if (h) __syncthreads();             // all reads of prev half done before overwrite
        // ---- stage 64-channel half: [sy 0..7][sx 0..35][c 0..63], bf16 hi/lo ----
        const float* base = (h == 0) ? s0 : s1;
        int c = tid & 63;
#pragma unroll
        for (int it = 0; it < 2; it++) {
            int sy = (tid >> 6) | (it << 2);
            int yy = y0 - 2 + sy;
            bool rv = (unsigned)yy < 32u;
            const float4* src = (const float4*)(base + c * 1024 + yy * 32);
            float4 q[8];
            if (rv) {
#pragma unroll
                for (int k2 = 0; k2 < 8; k2++) q[k2] = src[k2];
            } else {
#pragma unroll
                for (int k2 = 0; k2 < 8; k2++) q[k2] = make_float4(0.f, 0.f, 0.f, 0.f);
            }
            int rb = sy * 36;
#pragma unroll
            for (int sx = 0; sx < 36; sx++) {
                float v;
                if (sx < 2 || sx >= 34) v = 0.f;
                else {
                    int x = sx - 2;
                    float4 qq = q[x >> 2];
                    v = ((x & 3) == 0) ? qq.x : ((x & 3) == 1) ? qq.y : ((x & 3) == 2) ? qq.z : qq.w;
                }
                __nv_bfloat16 hi = __float2bfloat16(v);
                Xh[(rb + sx) * 72 + c] = hi;
                Xl[(rb + sx) * 72 + c] = __float2bfloat16(v - __bfloat162float(hi));
            }
        }
        __syncthreads();

        // ---- MMA over taps x 4 k-chunks of this half ----
        int fb = (h * 4 * nob + ob0) * 32 + lane;
        uint4 ah[2], al[2];
#pragma unroll
        for (int mt = 0; mt < 2; mt++) {
            ah[mt] = pw[2 * (fb + mt * 32)];
            al[mt] = pw[2 * (fb + mt * 32) + 1];
        }
#pragma unroll 1
        for (int tap = 0; tap < 25; tap++) {
            int dy = tap / 5, dx = tap - 5 * dy;
            int rowbase = ((nw + dy) * 36 + dx) * 72;
#pragma unroll
            for (int kch = 0; kch < 4; kch++) {
                int fn = (tap == 24 && kch == 3) ? fb : fb + (kch < 3 ? S1 : S2);
                uint4 nah[2], nal[2];
#pragma unroll
                for (int mt = 0; mt < 2; mt++) {
                    nah[mt] = pw[2 * (fn + mt * 32)];
                    nal[mt] = pw[2 * (fn + mt * 32) + 1];
                }
                unsigned Bh[4][2], Bl[4][2];
#pragma unroll
                for (int nt = 0; nt < 4; nt++) {
                    int off = rowbase + (nt * 8 + g) * 72 + kch * 16 + 2 * tg;
                    Bh[nt][0] = *(const unsigned*)(Xh + off);
                    Bh[nt][1] = *(const unsigned*)(Xh + off + 8);
                    Bl[nt][0] = *(const unsigned*)(Xl + off);
                    Bl[nt][1] = *(const unsigned*)(Xl + off + 8);
                }
#pragma unroll
                for (int mt = 0; mt < 2; mt++)
#pragma unroll
                    for (int nt = 0; nt < 4; nt++) mma_bf16(D[mt][nt], ah[mt], Bh[nt]);
#pragma unroll
                for (int mt = 0; mt < 2; mt++)
#pragma unroll
                    for (int nt = 0; nt < 4; nt++) mma_bf16(D[mt][nt], ah[mt], Bl[nt]);
#pragma unroll
                for (int mt = 0; mt < 2; mt++)
#pragma unroll
                    for (int nt = 0; nt < 4; nt++) mma_bf16(D[mt][nt], al[mt], Bh[nt]);
#pragma unroll
                for (int mt = 0; mt < 2; mt++) { ah[mt] = nah[mt]; al[mt] = nal[mt]; }
                fb = fn;
            }
        }
    }

    // ---- fused epilogue ----
    int y = y0 + nw;
#pragma unroll
    for (int mt = 0; mt < 2; mt++) {
#pragma unroll
        for (int ci2 = 0; ci2 < 2; ci2++) {
            int   ocG = och * 64 + mw * 32 + mt * 16 + g + 8 * ci2;
            float bv  = bias[ocG];
#pragma unroll
            for (int nt = 0; nt < 4; nt++) {
#pragma unroll
                for (int j = 0; j < 2; j++) {
                    float v  = D[mt][nt][ci2 * 2 + j] + bv;
                    int   x  = nt * 8 + 2 * tg + j;
                    int   px = y * 32 + x;
                    if (act_mode == 0) {
                        float s = 1.f / (1.f + expf(-v));
                        g_zr[(b * 128 + ocG) * 1024 + px] = s;
                        if (ocG < 64) {
                            int hi = (b * 64 + ocG) * 1024 + px;
                            g_rh[hi] = s * g_h[hi];
                        }
                    } else {
                        float c  = tanhf(v);
                        int   hi = (b * 64 + ocG) * 1024 + px;
                        float z  = g_zr[(b * 128 + 64 + ocG) * 1024 + px];
                        float hp = g_h[hi];
                        float hn = (1.f - z) * hp + z * c;
                        g_h[hi] = hn;
                        if (write_hs) g_hs[t * 2097152 + hi] = hn;
                    }
                }
            }
        }
    }
}

// ---------------- encoder conv1: 1->16 ch, 3x3 s2 p1, 128->64, lrelu ----------------
__global__ __launch_bounds__(256) void enc_conv1(const float* __restrict__ x,
                                                 const float* __restrict__ w,
                                                 const float* __restrict__ bias) {
    __shared__ float sw[144];
    __shared__ float sb[16];
    int tid = threadIdx.x;
    if (tid < 144) sw[tid] = w[tid];
    if (tid < 16)  sb[tid] = bias[tid];
    __syncthreads();
    int n = blockIdx.x;
    int p = blockIdx.y * 256 + tid;
    int oy = p >> 6, ox = p & 63;
    const float* xi = x + n * 16384;
    float win[9];
    int iy0 = 2 * oy - 1, ix0 = 2 * ox - 1;
#pragma unroll
    for (int ky = 0; ky < 3; ky++)
#pragma unroll
        for (int kx = 0; kx < 3; kx++) {
            int iy = iy0 + ky, ix = ix0 + kx;
            win[ky * 3 + kx] = ((unsigned)iy < 128u && (unsigned)ix < 128u) ? xi[iy * 128 + ix] : 0.f;
        }
#pragma unroll
    for (int oc = 0; oc < 16; oc++) {
        float a = sb[oc];
#pragma unroll
        for (int k = 0; k < 9; k++) a += sw[oc * 9 + k] * win[k];
        g_e1[(n * 16 + oc) * 4096 + p] = (a >= 0.f) ? a : 0.2f * a;
    }
}

// ---------------- encoder conv2: 16->64 ch, 3x3 s2 p1, 64->32, lrelu ----------------
__global__ __launch_bounds__(256) void enc_conv2(const float* __restrict__ w,
                                                 const float* __restrict__ bias) {
    __shared__ float sw[64 * 16 * 9];
    int tid = threadIdx.x;
    for (int i = tid; i < 9216; i += 256) sw[i] = w[i];
    __syncthreads();
    int n = blockIdx.x;
    int p = blockIdx.y * 256 + tid;
    int oy = p >> 5, ox = p & 31;
    const float* in = g_e1 + n * 65536;
    float acc[64];
#pragma unroll
    for (int oc = 0; oc < 64; oc++) acc[oc] = bias[oc];
    int iy0 = 2 * oy - 1, ix0 = 2 * ox - 1;
#pragma unroll 1
    for (int ic = 0; ic < 16; ic++) {
        float win[9];
#pragma unroll
        for (int ky = 0; ky < 3; ky++)
#pragma unroll
            for (int kx = 0; kx < 3; kx++) {
                int iy = iy0 + ky, ix = ix0 + kx;
                win[ky * 3 + kx] = ((unsigned)iy < 64u && (unsigned)ix < 64u)
                                       ? in[ic * 4096 + iy * 64 + ix] : 0.f;
            }
#pragma unroll
        for (int oc = 0; oc < 64; oc++) {
#pragma unroll
            for (int k = 0; k < 9; k++) acc[oc] += sw[(oc * 16 + ic) * 9 + k] * win[k];
        }
    }
#pragma unroll
    for (int oc = 0; oc < 64; oc++) {
        float a = acc[oc];
        g_e2[(n * 64 + oc) * 1024 + p] = (a >= 0.f) ? a : 0.2f * a;
    }
}

// ---------------- deconv1: 64->32 ch, 4x4 lhs_dilation 2 pad 2, 32->64, lrelu ----------------
__global__ __launch_bounds__(256) void deconv1(const float* __restrict__ w,
                                               const float* __restrict__ bias) {
    __shared__ float s_in[8 * 1024];
    __shared__ float s_w[4 * 8 * 16];
    int n   = blockIdx.x;
    int ocg = blockIdx.y;
    int tid = threadIdx.x;
    int oy  = tid >> 2;
    int ox0 = (tid & 3) << 4;

    float acc[4][16];
#pragma unroll
    for (int i = 0; i < 4; i++)
#pragma unroll
        for (int j = 0; j < 16; j++) acc[i][j] = 0.f;

    int ky0 = oy & 1;
    int iyA = (oy + ky0 - 2) >> 1;
    int iyB = iyA + 1;
    const float* in = g_hs + n * 65536;
    int ixbase = (ox0 >> 1) - 1;

#pragma unroll 1
    for (int cc = 0; cc < 8; cc++) {
        int ic0 = cc * 8;
        for (int idx = tid; idx < 8192; idx += 256) s_in[idx] = in[ic0 * 1024 + idx];
        for (int idx = tid; idx < 512; idx += 256) {
            int oc  = idx >> 7;
            int rem = idx & 127;
            int ic  = rem >> 4;
            int k   = rem & 15;
            s_w[idx] = w[((ocg * 4 + oc) * 64 + ic0 + ic) * 16 + k];
        }
        __syncthreads();
#pragma unroll 1
        for (int ic = 0; ic < 8; ic++) {
            float segA[10], segB[10];
#pragma unroll
            for (int m = 0; m < 10; m++) {
                int ix = ixbase + m;
                bool xok = (unsigned)ix < 32u;
                segA[m] = (xok && (unsigned)iyA < 32u) ? s_in[ic * 1024 + iyA * 32 + ix] : 0.f;
                segB[m] = (xok && (unsigned)iyB < 32u) ? s_in[ic * 1024 + iyB * 32 + ix] : 0.f;
            }
#pragma unroll
            for (int j = 0; j < 16; j++) {
                int kx0 = j & 1;
                int mA  = (j + kx0) >> 1;
                int mB  = mA + 1;
                float vAA = segA[mA], vAB = segA[mB];
                float vBA = segB[mA], vBB = segB[mB];
#pragma unroll
                for (int oc = 0; oc < 4; oc++) {
                    const float* wp = &s_w[(oc * 8 + ic) * 16];
                    acc[oc][j] += wp[ky0 * 4 + kx0]       * vAA
                                + wp[ky0 * 4 + kx0 + 2]   * vAB
                                + wp[(ky0 + 2) * 4 + kx0] * vBA
                                + wp[(ky0 + 2) * 4 + kx0 + 2] * vBB;
                }
            }
        }
        __syncthreads();
    }
#pragma unroll
    for (int oc = 0; oc < 4; oc++) {
        int ocG = ocg * 4 + oc;
        float bv = bias[ocG];
#pragma unroll
        for (int j = 0; j < 16; j++) {
            float a = acc[oc][j] + bv;
            g_y1[(n * 32 + ocG) * 4096 + oy * 64 + ox0 + j] = (a >= 0.f) ? a : 0.2f * a;
        }
    }
}

// ---------------- deconv2: 32->1 ch, 4x4 lhs_dilation 2 pad 2, 64->128, + transpose ----------------
__global__ __launch_bounds__(256) void deconv2(const float* __restrict__ w,
                                               const float* __restrict__ bias,
                                               float* __restrict__ out) {
    __shared__ float sw[512];
    int tid = threadIdx.x;
    for (int i = tid; i < 512; i += 256) sw[i] = w[i];
    __syncthreads();
    int n = blockIdx.x;
    int p = blockIdx.y * 256 + tid;
    int oy = p >> 7, ox = p & 127;
    int ky0 = oy & 1, kx0 = ox & 1;
    int iyA = (oy + ky0 - 2) >> 1, iyB = iyA + 1;
    int ixA = (ox + kx0 - 2) >> 1, ixB = ixA + 1;
    bool yA = (unsigned)iyA < 64u, yB = (unsigned)iyB < 64u;
    bool xA = (unsigned)ixA < 64u, xB = (unsigned)ixB < 64u;
    const float* in = g_y1 + n * 131072;
    float acc = bias[0];
#pragma unroll 1
    for (int ic = 0; ic < 32; ic++) {
        const float* ip = in + ic * 4096;
        float vAA = (yA && xA) ? ip[iyA * 64 + ixA] : 0.f;
        float vAB = (yA && xB) ? ip[iyA * 64 + ixB] : 0.f;
        float vBA = (yB && xA) ? ip[iyB * 64 + ixA] : 0.f;
        float vBB = (yB && xB) ? ip[iyB * 64 + ixB] : 0.f;
        const float* wp = &sw[ic * 16];
        acc += wp[ky0 * 4 + kx0]           * vAA
             + wp[ky0 * 4 + kx0 + 2]       * vAB
             + wp[(ky0 + 2) * 4 + kx0]     * vBA
             + wp[(ky0 + 2) * 4 + kx0 + 2] * vBB;
    }
    int t = n >> 5, b = n & 31;
    out[(b * 10 + t) * 16384 + p] = acc;
}

// ---------------- launch ----------------
extern "C" void kernel_launch(void* const* d_in, const int* in_sizes, int n_in,
                              void* d_out, int out_size) {
    const float* x            = (const float*)d_in[0];
    const float* enc_w1       = (const float*)d_in[1];
    const float* enc_b1       = (const float*)d_in[2];
    const float* enc_w2       = (const float*)d_in[3];
    const float* enc_b2       = (const float*)d_in[4];
    const float* enc_gru_wzr  = (const float*)d_in[5];
    const float* enc_gru_bzr  = (const float*)d_in[6];
    const float* enc_gru_wc   = (const float*)d_in[7];
    const float* enc_gru_bc   = (const float*)d_in[8];
    const float* dec_gru_wzr  = (const float*)d_in[9];
    const float* dec_gru_bzr  = (const float*)d_in[10];
    const float* dec_gru_wc   = (const float*)d_in[11];
    const float* dec_gru_bc   = (const float*)d_in[12];
    const float* dec_w1       = (const float*)d_in[13];
    const float* dec_b1       = (const float*)d_in[14];
    const float* dec_w2       = (const float*)d_in[15];
    const float* dec_b2       = (const float*)d_in[16];
    float* out = (float*)d_out;

    const int SMB = 2 * 288 * 72 * 2;   // 82944 bytes -> 2 CTAs/SM
    cudaFuncSetAttribute(gru2<2>, cudaFuncAttributeMaxDynamicSharedMemorySize, SMB);
    cudaFuncSetAttribute(gru2<1>, cudaFuncAttributeMaxDynamicSharedMemorySize, SMB);

    zero_h_kernel<<<8192, 256>>>();

    pack_w<<<(25 * 128 * 128 * 2 + 255) / 256, 256>>>(enc_gru_wzr, 128, 128, 0, 0);
    pack_w<<<(25 * 64 * 128 * 2 + 255) / 256, 256>>>(enc_gru_wc, 64, 128, 0, 819200);
    pack_w<<<(25 * 128 * 64 * 2 + 255) / 256, 256>>>(dec_gru_wzr, 128, 64, 64, 1228800);
    pack_w<<<(25 * 64 * 64 * 2 + 255) / 256, 256>>>(dec_gru_wc, 64, 64, 64, 1638400);

    enc_conv1<<<dim3(320, 16), 256>>>(x, enc_w1, enc_b1);
    enc_conv2<<<dim3(320, 4), 256>>>(enc_w2, enc_b2);

    for (int t = 0; t < 10; t++) {
        gru2<2><<<dim3(32, 8, 2), 256, SMB>>>(t, 0, 8, 0, enc_gru_bzr, 0, 0);
        gru2<2><<<dim3(32, 8, 1), 256, SMB>>>(t, 1, 4, 819200, enc_gru_bc, 1, 0);
    }
    for (int t = 0; t < 10; t++) {
        gru2<1><<<dim3(32, 8, 2), 256, SMB>>>(t, 2, 8, 1228800, dec_gru_bzr, 0, 0);
        gru2<1><<<dim3(32, 8, 1), 256, SMB>>>(t, 3, 4, 1638400, dec_gru_bc, 1, 1);
    }

    deconv1<<<dim3(320, 8), 256>>>(dec_w1, dec_b1);
    deconv2<<<dim3(320, 64), 256>>>(dec_w2, dec_b2, out);
}

// round 8
// speedup vs baseline: 3.8957x; 1.1903x over previous
#include <cuda_runtime.h>
#include <cuda_bf16.h>
#include <stdint.h>
#include <math.h>

#define BB 32
#define TT 10

// ---------------- scratch (device globals; no allocs allowed) ----------------
__device__ float    g_e1 [320 * 16 * 64 * 64];   // encoder conv1 out (fp32)
__device__ unsigned g_e2p[320 * 64 * 1024];      // encoder conv2 out, packed bf16 hi|lo
__device__ float    g_h  [BB * 64 * 1024];       // GRU hidden (fp32, for update math)
__device__ unsigned g_hp [BB * 64 * 1024];       // h packed bf16 hi|lo
__device__ float    g_z  [BB * 64 * 1024];       // z gate (fp32, read by cand epilogue)
__device__ unsigned g_rhp[BB * 64 * 1024];       // r*h packed bf16 hi|lo
__device__ float    g_hs [TT * BB * 64 * 1024];  // decoder hidden outputs (fp32)
__device__ float    g_y1 [320 * 32 * 64 * 64];   // deconv1 out
__device__ __nv_bfloat16 g_wp[1843200];          // fragment-packed weights hi/lo interleaved

__device__ __forceinline__ unsigned pack2(float v) {
    __nv_bfloat16 h = __float2bfloat16(v);
    __nv_bfloat16 l = __float2bfloat16(v - __bfloat162float(h));
    return (unsigned)__bfloat16_as_ushort(h) | ((unsigned)__bfloat16_as_ushort(l) << 16);
}

// ---------------- fused init: zero h/hp + pack all 4 weight regions ----------------
// pack layout (unchanged from R5): [tap][kc][ob][lane][hl][r][e], bf16
__global__ void init_all(const float* __restrict__ ewzr, const float* __restrict__ ewc,
                         const float* __restrict__ dwzr, const float* __restrict__ dwc) {
    long idx = (long)blockIdx.x * 256 + threadIdx.x;
    if (idx < 2097152) { g_h[idx] = 0.f; g_hp[idx] = 0u; return; }
    idx -= 2097152;
    const float* w; int OC, IC, icoff, dofs;
    if (idx < 819200)       { w = ewzr; OC = 128; IC = 128; icoff = 0;  dofs = 0; }
    else if (idx < 1228800) { idx -= 819200;  w = ewc;  OC = 64;  IC = 128; icoff = 0;  dofs = 819200; }
    else if (idx < 1638400) { idx -= 1228800; w = dwzr; OC = 128; IC = 64;  icoff = 64; dofs = 1228800; }
    else if (idx < 1843200) { idx -= 1638400; w = dwc;  OC = 64;  IC = 64;  icoff = 64; dofs = 1638400; }
    else return;
    int KC = IC >> 4, NOB = OC >> 4;
    int e    = idx & 1;
    int r    = ((int)idx >> 1) & 3;
    int hl   = ((int)idx >> 3) & 1;
    int lane = ((int)idx >> 4) & 31;
    int v    = (int)idx >> 9;
    int ob   = v % NOB;
    int v2   = v / NOB;
    int kc   = v2 % KC;
    int tap  = v2 / KC;
    int g = lane >> 2, t = lane & 3;
    int oc = ob * 16 + g + 8 * (r & 1);
    int ic = kc * 16 + 2 * t + 8 * (r >> 1) + e;
    float val = w[(oc * 128 + icoff + ic) * 25 + tap];
    __nv_bfloat16 hi = __float2bfloat16(val);
    g_wp[dofs + idx] = hl ? __float2bfloat16(val - __bfloat162float(hi)) : hi;
}

// ---------------- mma helper ----------------
__device__ __forceinline__ void mma_bf16(float (&d)[4], const uint4& a, const unsigned (&b)[2]) {
    asm volatile(
        "mma.sync.aligned.m16n8k16.row.col.f32.bf16.bf16.f32 "
        "{%0,%1,%2,%3}, {%4,%5,%6,%7}, {%8,%9}, {%0,%1,%2,%3};\n"
        : "+f"(d[0]), "+f"(d[1]), "+f"(d[2]), "+f"(d[3])
        : "r"(a.x), "r"(a.y), "r"(a.z), "r"(a.w), "r"(b[0]), "r"(b[1]));
}

// ---------------- GRU 5x5 conv via mma.sync; packed bf16 inputs; IC in 64-ch halves ----------------
// mode: 0=enc zr (e2p ++ hp)  1=enc cand (e2p ++ rhp)  2=dec zr (hp)  3=dec cand (rhp)
// act_mode 0: sigmoid -> r-CTA writes g_rhp, z-CTA writes g_z; act_mode 1: tanh -> h update (+hs)
template <int NH>
__global__ __launch_bounds__(256, 2) void gru2(int t, int mode, int nob, int wofs,
                                               const float* __restrict__ bias,
                                               int act_mode, int write_hs) {
    extern __shared__ unsigned short sm[];
    unsigned short* Xh = sm;                 // [288 px][72]
    unsigned short* Xl = sm + 288 * 72;

    int b   = blockIdx.x;
    int y0  = blockIdx.y * 4;
    int och = blockIdx.z;
    int tid = threadIdx.x;
    int w   = tid >> 5, lane = tid & 31;
    int g   = lane >> 2, tg = lane & 3;
    int mw  = w >> 2, nw = w & 3;

    const unsigned* s0p;
    const unsigned* s1p;
    if (mode <= 1) {
        s0p = g_e2p + (b * 10 + t) * 65536;
        s1p = (mode == 0 ? g_hp : g_rhp) + b * 65536;
    } else {
        s0p = (mode == 2 ? g_hp : g_rhp) + b * 65536;
        s1p = s0p;
    }

    float D[2][4][4];
#pragma unroll
    for (int mt = 0; mt < 2; mt++)
#pragma unroll
        for (int nt = 0; nt < 4; nt++)
#pragma unroll
            for (int i = 0; i < 4; i++) D[mt][nt][i] = 0.f;

    const uint4* pw = reinterpret_cast<const uint4*>(g_wp) + (wofs >> 3);
    const int KC = NH * 4;
    const int S1 = nob * 32;
    const int S2 = (KC - 3) * nob * 32;
    const int ob0 = och * 4 + mw * 2;

#pragma unroll 1
    for (int h = 0; h < NH; h++) {
        if (h) __syncthreads();
        // ---- stage 64-ch half: packed u32 -> hi/lo halfword arrays ----
        const unsigned* base = (h == 0) ? s0p : s1p;
        int c = tid & 63;
#pragma unroll
        for (int it = 0; it < 2; it++) {
            int sy = (tid >> 6) | (it << 2);
            int yy = y0 - 2 + sy;
            bool rv = (unsigned)yy < 32u;
            const uint4* src = (const uint4*)(base + c * 1024 + yy * 32);
            uint4 q[8];
            if (rv) {
#pragma unroll
                for (int k2 = 0; k2 < 8; k2++) q[k2] = src[k2];
            } else {
#pragma unroll
                for (int k2 = 0; k2 < 8; k2++) q[k2] = make_uint4(0u, 0u, 0u, 0u);
            }
            int rb = sy * 36;
#pragma unroll
            for (int sx = 0; sx < 36; sx++) {
                unsigned v;
                if (sx < 2 || sx >= 34) v = 0u;
                else {
                    int x = sx - 2;
                    uint4 qq = q[x >> 2];
                    v = ((x & 3) == 0) ? qq.x : ((x & 3) == 1) ? qq.y : ((x & 3) == 2) ? qq.z : qq.w;
                }
                Xh[(rb + sx) * 72 + c] = (unsigned short)(v & 0xffffu);
                Xl[(rb + sx) * 72 + c] = (unsigned short)(v >> 16);
            }
        }
        __syncthreads();

        // ---- MMA over taps x 4 k-chunks of this half ----
        int fb = (h * 4 * nob + ob0) * 32 + lane;
        uint4 ah[2], al[2];
#pragma unroll
        for (int mt = 0; mt < 2; mt++) {
            ah[mt] = pw[2 * (fb + mt * 32)];
            al[mt] = pw[2 * (fb + mt * 32) + 1];
        }
#pragma unroll 1
        for (int tap = 0; tap < 25; tap++) {
            int dy = tap / 5, dx = tap - 5 * dy;
            int rowbase = ((nw + dy) * 36 + dx) * 72;
#pragma unroll
            for (int kch = 0; kch < 4; kch++) {
                int fn = (tap == 24 && kch == 3) ? fb : fb + (kch < 3 ? S1 : S2);
                uint4 nah[2], nal[2];
#pragma unroll
                for (int mt = 0; mt < 2; mt++) {
                    nah[mt] = pw[2 * (fn + mt * 32)];
                    nal[mt] = pw[2 * (fn + mt * 32) + 1];
                }
                unsigned Bh[4][2], Bl[4][2];
#pragma unroll
                for (int nt = 0; nt < 4; nt++) {
                    int off = rowbase + (nt * 8 + g) * 72 + kch * 16 + 2 * tg;
                    Bh[nt][0] = *(const unsigned*)(Xh + off);
                    Bh[nt][1] = *(const unsigned*)(Xh + off + 8);
                    Bl[nt][0] = *(const unsigned*)(Xl + off);
                    Bl[nt][1] = *(const unsigned*)(Xl + off + 8);
                }
#pragma unroll
                for (int mt = 0; mt < 2; mt++)
#pragma unroll
                    for (int nt = 0; nt < 4; nt++) mma_bf16(D[mt][nt], ah[mt], Bh[nt]);
#pragma unroll
                for (int mt = 0; mt < 2; mt++)
#pragma unroll
                    for (int nt = 0; nt < 4; nt++) mma_bf16(D[mt][nt], ah[mt], Bl[nt]);
#pragma unroll
                for (int mt = 0; mt < 2; mt++)
#pragma unroll
                    for (int nt = 0; nt < 4; nt++) mma_bf16(D[mt][nt], al[mt], Bh[nt]);
#pragma unroll
                for (int mt = 0; mt < 2; mt++) { ah[mt] = nah[mt]; al[mt] = nal[mt]; }
                fb = fn;
            }
        }
    }

    // ---- fused epilogue ----
    int y = y0 + nw;
#pragma unroll
    for (int mt = 0; mt < 2; mt++) {
#pragma unroll
        for (int ci2 = 0; ci2 < 2; ci2++) {
            int   ocG = och * 64 + mw * 32 + mt * 16 + g + 8 * ci2;
            float bv  = bias[ocG];
#pragma unroll
            for (int nt = 0; nt < 4; nt++) {
#pragma unroll
                for (int j = 0; j < 2; j++) {
                    float v  = D[mt][nt][ci2 * 2 + j] + bv;
                    int   x  = nt * 8 + 2 * tg + j;
                    int   px = y * 32 + x;
                    if (act_mode == 0) {
                        float s = 1.f / (1.f + expf(-v));
                        if (ocG < 64) {
                            int hi = (b * 64 + ocG) * 1024 + px;
                            g_rhp[hi] = pack2(s * g_h[hi]);
                        } else {
                            g_z[(b * 64 + ocG - 64) * 1024 + px] = s;
                        }
                    } else {
                        float c  = tanhf(v);
                        int   hi = (b * 64 + ocG) * 1024 + px;
                        float z  = g_z[hi];
                        float hp = g_h[hi];
                        float hn = (1.f - z) * hp + z * c;
                        g_h[hi]  = hn;
                        g_hp[hi] = pack2(hn);
                        if (write_hs) g_hs[t * 2097152 + hi] = hn;
                    }
                }
            }
        }
    }
}

// ---------------- encoder conv1: 1->16 ch, 3x3 s2 p1, 128->64, lrelu ----------------
__global__ __launch_bounds__(256) void enc_conv1(const float* __restrict__ x,
                                                 const float* __restrict__ w,
                                                 const float* __restrict__ bias) {
    __shared__ float sw[144], sb[16];
    int tid = threadIdx.x;
    if (tid < 144) sw[tid] = w[tid];
    if (tid < 16)  sb[tid] = bias[tid];
    __syncthreads();
    int n = blockIdx.x, p = blockIdx.y * 256 + tid;
    int oy = p >> 6, ox = p & 63;
    const float* xi = x + n * 16384;
    float win[9];
    int iy0 = 2 * oy - 1, ix0 = 2 * ox - 1;
#pragma unroll
    for (int ky = 0; ky < 3; ky++)
#pragma unroll
        for (int kx = 0; kx < 3; kx++) {
            int iy = iy0 + ky, ix = ix0 + kx;
            win[ky * 3 + kx] = ((unsigned)iy < 128u && (unsigned)ix < 128u) ? xi[iy * 128 + ix] : 0.f;
        }
#pragma unroll
    for (int oc = 0; oc < 16; oc++) {
        float a = sb[oc];
#pragma unroll
        for (int k = 0; k < 9; k++) a += sw[oc * 9 + k] * win[k];
        g_e1[(n * 16 + oc) * 4096 + p] = (a >= 0.f) ? a : 0.2f * a;
    }
}

// ---------------- encoder conv2: 16->64 ch, 3x3 s2 p1, 64->32, lrelu, emit packed bf16 ----------------
__global__ __launch_bounds__(256) void enc_conv2(const float* __restrict__ w,
                                                 const float* __restrict__ bias) {
    __shared__ float sw[9216];
    int tid = threadIdx.x;
    for (int i = tid; i < 9216; i += 256) sw[i] = w[i];
    __syncthreads();
    int n = blockIdx.x, p = blockIdx.y * 256 + tid;
    int oy = p >> 5, ox = p & 31;
    const float* in = g_e1 + n * 65536;
    float acc[64];
#pragma unroll
    for (int oc = 0; oc < 64; oc++) acc[oc] = bias[oc];
    int iy0 = 2 * oy - 1, ix0 = 2 * ox - 1;
#pragma unroll 1
    for (int ic = 0; ic < 16; ic++) {
        float win[9];
#pragma unroll
        for (int ky = 0; ky < 3; ky++)
#pragma unroll
            for (int kx = 0; kx < 3; kx++) {
                int iy = iy0 + ky, ix = ix0 + kx;
                win[ky * 3 + kx] = ((unsigned)iy < 64u && (unsigned)ix < 64u)
                                       ? in[ic * 4096 + iy * 64 + ix] : 0.f;
            }
#pragma unroll
        for (int oc = 0; oc < 64; oc++)
#pragma unroll
            for (int k = 0; k < 9; k++) acc[oc] += sw[(oc * 16 + ic) * 9 + k] * win[k];
    }
#pragma unroll
    for (int oc = 0; oc < 64; oc++) {
        float a = acc[oc];
        a = (a >= 0.f) ? a : 0.2f * a;
        g_e2p[(n * 64 + oc) * 1024 + p] = pack2(a);
    }
}

// ---------------- deconv1: 64->32 ch, 4x4 lhs_dil 2 pad 2, 32->64, lrelu ----------------
__global__ __launch_bounds__(256) void deconv1(const float* __restrict__ w,
                                               const float* __restrict__ bias) {
    __shared__ float s_in[8192], s_w[512];
    int n = blockIdx.x, ocg = blockIdx.y, tid = threadIdx.x;
    int oy = tid >> 2, ox0 = (tid & 3) << 4;
    float acc[4][16];
#pragma unroll
    for (int i = 0; i < 4; i++)
#pragma unroll
        for (int j = 0; j < 16; j++) acc[i][j] = 0.f;
    int ky0 = oy & 1;
    int iyA = (oy + ky0 - 2) >> 1, iyB = iyA + 1;
    const float* in = g_hs + n * 65536;
    int ixbase = (ox0 >> 1) - 1;
#pragma unroll 1
    for (int cc = 0; cc < 8; cc++) {
        int ic0 = cc * 8;
        for (int idx = tid; idx < 8192; idx += 256) s_in[idx] = in[ic0 * 1024 + idx];
        for (int idx = tid; idx < 512; idx += 256) {
            int oc = idx >> 7, rem = idx & 127, ic = rem >> 4, k = rem & 15;
            s_w[idx] = w[((ocg * 4 + oc) * 64 + ic0 + ic) * 16 + k];
        }
        __syncthreads();
#pragma unroll 1
        for (int ic = 0; ic < 8; ic++) {
            float segA[10], segB[10];
#pragma unroll
            for (int m = 0; m < 10; m++) {
                int ix = ixbase + m;
                bool xok = (unsigned)ix < 32u;
                segA[m] = (xok && (unsigned)iyA < 32u) ? s_in[ic * 1024 + iyA * 32 + ix] : 0.f;
                segB[m] = (xok && (unsigned)iyB < 32u) ? s_in[ic * 1024 + iyB * 32 + ix] : 0.f;
            }
#pragma unroll
            for (int j = 0; j < 16; j++) {
                int kx0 = j & 1, mA = (j + kx0) >> 1, mB = mA + 1;
#pragma unroll
                for (int oc = 0; oc < 4; oc++) {
                    const float* wp = &s_w[(oc * 8 + ic) * 16];
                    acc[oc][j] += wp[ky0 * 4 + kx0] * segA[mA] + wp[ky0 * 4 + kx0 + 2] * segA[mB]
                                + wp[(ky0 + 2) * 4 + kx0] * segB[mA] + wp[(ky0 + 2) * 4 + kx0 + 2] * segB[mB];
                }
            }
        }
        __syncthreads();
    }
#pragma unroll
    for (int oc = 0; oc < 4; oc++) {
        int ocG = ocg * 4 + oc;
        float bv = bias[ocG];
#pragma unroll
        for (int j = 0; j < 16; j++) {
            float a = acc[oc][j] + bv;
            g_y1[(n * 32 + ocG) * 4096 + oy * 64 + ox0 + j] = (a >= 0.f) ? a : 0.2f * a;
        }
    }
}

// ---------------- deconv2: 32->1 ch, 4x4 lhs_dil 2 pad 2, 64->128, + transpose ----------------
__global__ __launch_bounds__(256) void deconv2(const float* __restrict__ w,
                                               const float* __restrict__ bias,
                                               float* __restrict__ out) {
    __shared__ float sw[512];
    int tid = threadIdx.x;
    for (int i = tid; i < 512; i += 256) sw[i] = w[i];
    __syncthreads();
    int n = blockIdx.x, p = blockIdx.y * 256 + tid;
    int oy = p >> 7, ox = p & 127;
    int ky0 = oy & 1, kx0 = ox & 1;
    int iyA = (oy + ky0 - 2) >> 1, iyB = iyA + 1;
    int ixA = (ox + kx0 - 2) >> 1, ixB = ixA + 1;
    bool yA = (unsigned)iyA < 64u, yB = (unsigned)iyB < 64u;
    bool xA = (unsigned)ixA < 64u, xB = (unsigned)ixB < 64u;
    const float* in = g_y1 + n * 131072;
    float acc = bias[0];
#pragma unroll 1
    for (int ic = 0; ic < 32; ic++) {
        const float* ip = in + ic * 4096;
        float vAA = (yA && xA) ? ip[iyA * 64 + ixA] : 0.f;
        float vAB = (yA && xB) ? ip[iyA * 64 + ixB] : 0.f;
        float vBA = (yB && xA) ? ip[iyB * 64 + ixA] : 0.f;
        float vBB = (yB && xB) ? ip[iyB * 64 + ixB] : 0.f;
        const float* wp = &sw[ic * 16];
        acc += wp[ky0 * 4 + kx0] * vAA + wp[ky0 * 4 + kx0 + 2] * vAB
             + wp[(ky0 + 2) * 4 + kx0] * vBA + wp[(ky0 + 2) * 4 + kx0 + 2] * vBB;
    }
    int t = n >> 5, b = n & 31;
    out[(b * 10 + t) * 16384 + p] = acc;
}

// ---------------- launch ----------------
extern "C" void kernel_launch(void* const* d_in, const int* in_sizes, int n_in,
                              void* d_out, int out_size) {
    const float* x           = (const float*)d_in[0];
    const float* enc_w1      = (const float*)d_in[1];
    const float* enc_b1      = (const float*)d_in[2];
    const float* enc_w2      = (const float*)d_in[3];
    const float* enc_b2      = (const float*)d_in[4];
    const float* enc_gru_wzr = (const float*)d_in[5];
    const float* enc_gru_bzr = (const float*)d_in[6];
    const float* enc_gru_wc  = (const float*)d_in[7];
    const float* enc_gru_bc  = (const float*)d_in[8];
    const float* dec_gru_wzr = (const float*)d_in[9];
    const float* dec_gru_bzr = (const float*)d_in[10];
    const float* dec_gru_wc  = (const float*)d_in[11];
    const float* dec_gru_bc  = (const float*)d_in[12];
    const float* dec_w1      = (const float*)d_in[13];
    const float* dec_b1      = (const float*)d_in[14];
    const float* dec_w2      = (const float*)d_in[15];
    const float* dec_b2      = (const float*)d_in[16];
    float* out = (float*)d_out;

    const int SMB = 2 * 288 * 72 * 2;   // 82944 bytes -> 2 CTAs/SM
    cudaFuncSetAttribute(gru2<2>, cudaFuncAttributeMaxDynamicSharedMemorySize, SMB);
    cudaFuncSetAttribute(gru2<1>, cudaFuncAttributeMaxDynamicSharedMemorySize, SMB);

    // launch #1: fused zero + all weight packing (makes launch #6 a gru2 zr kernel for ncu)
    init_all<<<(2097152 + 1843200 + 255) / 256, 256>>>(enc_gru_wzr, enc_gru_wc,
                                                       dec_gru_wzr, dec_gru_wc);
    enc_conv1<<<dim3(320, 16), 256>>>(x, enc_w1, enc_b1);   // #2
    enc_conv2<<<dim3(320, 4), 256>>>(enc_w2, enc_b2);       // #3

    for (int t = 0; t < 10; t++) {                          // #4, #5, #6 (captured), ...
        gru2<2><<<dim3(32, 8, 2), 256, SMB>>>(t, 0, 8, 0, enc_gru_bzr, 0, 0);
        gru2<2><<<dim3(32, 8, 1), 256, SMB>>>(t, 1, 4, 819200, enc_gru_bc, 1, 0);
    }
    for (int t = 0; t < 10; t++) {
        gru2<1><<<dim3(32, 8, 2), 256, SMB>>>(t, 2, 8, 1228800, dec_gru_bzr, 0, 0);
        gru2<1><<<dim3(32, 8, 1), 256, SMB>>>(t, 3, 4, 1638400, dec_gru_bc, 1, 1);
    }

    deconv1<<<dim3(320, 8), 256>>>(dec_w1, dec_b1);
    deconv2<<<dim3(320, 64), 256>>>(dec_w2, dec_b2, out);
}

// round 9
// speedup vs baseline: 4.8300x; 1.2398x over previous
#include <cuda_runtime.h>
#include <cuda_fp16.h>
#include <stdint.h>
#include <math.h>

#define BB 32
#define TT 10

// ---------------- scratch (device globals; no allocs allowed) ----------------
__device__ float          g_e1 [320 * 16 * 64 * 64];   // encoder conv1 out (fp32)
__device__ unsigned short g_e2p[320 * 64 * 1024];      // encoder conv2 out (fp16 bits)
__device__ float          g_h  [BB * 64 * 1024];       // GRU hidden (fp32 master)
__device__ unsigned short g_hp [BB * 64 * 1024];       // h (fp16 bits)
__device__ float          g_z  [BB * 64 * 1024];       // z gate (fp32)
__device__ unsigned short g_rhp[BB * 64 * 1024];       // r*h (fp16 bits)
__device__ float          g_hs [TT * BB * 64 * 1024];  // decoder hidden outputs (fp32)
__device__ float          g_y1 [320 * 32 * 64 * 64];   // deconv1 out
__device__ unsigned short g_wp [1843200];              // fragment-packed W, fp16 hi/lo interleaved

__device__ __forceinline__ unsigned short h16(float v) {
    return __half_as_ushort(__float2half(v));
}

// ---------------- fused init: zero h/hp + pack all 4 weight regions ----------------
// layout (unchanged): [tap][kc][ob][lane][hl][r][e], fp16; hl=0 hi, hl=1 lo residual
__global__ void init_all(const float* __restrict__ ewzr, const float* __restrict__ ewc,
                         const float* __restrict__ dwzr, const float* __restrict__ dwc) {
    long idx = (long)blockIdx.x * 256 + threadIdx.x;
    if (idx < 2097152) { g_h[idx] = 0.f; g_hp[idx] = 0; return; }
    idx -= 2097152;
    const float* w; int OC, IC, icoff, dofs;
    if (idx < 819200)       { w = ewzr; OC = 128; IC = 128; icoff = 0;  dofs = 0; }
    else if (idx < 1228800) { idx -= 819200;  w = ewc;  OC = 64;  IC = 128; icoff = 0;  dofs = 819200; }
    else if (idx < 1638400) { idx -= 1228800; w = dwzr; OC = 128; IC = 64;  icoff = 64; dofs = 1228800; }
    else if (idx < 1843200) { idx -= 1638400; w = dwc;  OC = 64;  IC = 64;  icoff = 64; dofs = 1638400; }
    else return;
    int KC = IC >> 4, NOB = OC >> 4;
    int e    = idx & 1;
    int r    = ((int)idx >> 1) & 3;
    int hl   = ((int)idx >> 3) & 1;
    int lane = ((int)idx >> 4) & 31;
    int v    = (int)idx >> 9;
    int ob   = v % NOB;
    int v2   = v / NOB;
    int kc   = v2 % KC;
    int tap  = v2 / KC;
    int g = lane >> 2, t = lane & 3;
    int oc = ob * 16 + g + 8 * (r & 1);
    int ic = kc * 16 + 2 * t + 8 * (r >> 1) + e;
    float val = w[(oc * 128 + icoff + ic) * 25 + tap];
    __half hi = __float2half(val);
    g_wp[dofs + idx] = hl ? h16(val - __half2float(hi)) : __half_as_ushort(hi);
}

// ---------------- mma helper (fp16 in, fp32 accum) ----------------
__device__ __forceinline__ void mma_f16(float (&d)[4], const uint4& a, const unsigned (&b)[2]) {
    asm volatile(
        "mma.sync.aligned.m16n8k16.row.col.f32.f16.f16.f32 "
        "{%0,%1,%2,%3}, {%4,%5,%6,%7}, {%8,%9}, {%0,%1,%2,%3};\n"
        : "+f"(d[0]), "+f"(d[1]), "+f"(d[2]), "+f"(d[3])
        : "r"(a.x), "r"(a.y), "r"(a.z), "r"(a.w), "r"(b[0]), "r"(b[1]));
}

// ---------------- GRU 5x5 conv via mma.sync fp16 (W split 2-term); IC in 64-ch halves ----------------
// mode: 0=enc zr (e2p ++ hp)  1=enc cand (e2p ++ rhp)  2=dec zr (hp)  3=dec cand (rhp)
// act_mode 0: sigmoid -> r-CTA writes g_rhp, z-CTA writes g_z; act_mode 1: tanh -> h update (+hs)
template <int NH>
__global__ __launch_bounds__(256, 2) void gru2(int t, int mode, int nob, int wofs,
                                               const float* __restrict__ bias,
                                               int act_mode, int write_hs) {
    extern __shared__ unsigned short Xs[];   // [288 px][72] fp16 bits

    int b   = blockIdx.x;
    int y0  = blockIdx.y * 4;
    int och = blockIdx.z;
    int tid = threadIdx.x;
    int w   = tid >> 5, lane = tid & 31;
    int g   = lane >> 2, tg = lane & 3;
    int mw  = w >> 2, nw = w & 3;

    const unsigned short* s0p;
    const unsigned short* s1p;
    if (mode <= 1) {
        s0p = g_e2p + (b * 10 + t) * 65536;
        s1p = (mode == 0 ? g_hp : g_rhp) + b * 65536;
    } else {
        s0p = (mode == 2 ? g_hp : g_rhp) + b * 65536;
        s1p = s0p;
    }

    float D[2][4][4];
#pragma unroll
    for (int mt = 0; mt < 2; mt++)
#pragma unroll
        for (int nt = 0; nt < 4; nt++)
#pragma unroll
            for (int i = 0; i < 4; i++) D[mt][nt][i] = 0.f;

    const uint4* pw = reinterpret_cast<const uint4*>(g_wp) + (wofs >> 3);
    const int KC = NH * 4;
    const int S1 = nob * 32;
    const int S2 = (KC - 3) * nob * 32;
    const int ob0 = och * 4 + mw * 2;

#pragma unroll 1
    for (int h = 0; h < NH; h++) {
        if (h) __syncthreads();
        // ---- stage 64-ch half: fp16 source -> [sy][sx][c] fp16 smem ----
        const unsigned short* base = (h == 0) ? s0p : s1p;
        int c = tid & 63;
#pragma unroll
        for (int it = 0; it < 2; it++) {
            int sy = (tid >> 6) | (it << 2);
            int yy = y0 - 2 + sy;
            bool rv = (unsigned)yy < 32u;
            const uint4* src = (const uint4*)(base + c * 1024 + yy * 32);
            uint4 q[4];
            if (rv) {
#pragma unroll
                for (int k2 = 0; k2 < 4; k2++) q[k2] = src[k2];
            } else {
#pragma unroll
                for (int k2 = 0; k2 < 4; k2++) q[k2] = make_uint4(0u, 0u, 0u, 0u);
            }
            const unsigned short* hv = (const unsigned short*)q;
            int rb = sy * 36;
#pragma unroll
            for (int sx = 0; sx < 36; sx++) {
                unsigned short v = (sx < 2 || sx >= 34) ? (unsigned short)0 : hv[sx - 2];
                Xs[(rb + sx) * 72 + c] = v;
            }
        }
        __syncthreads();

        // ---- MMA over taps x 4 k-chunks of this half: D += X*Wh + X*Wl ----
        int fb = (h * 4 * nob + ob0) * 32 + lane;
        uint4 ah[2], al[2];
#pragma unroll
        for (int mt = 0; mt < 2; mt++) {
            ah[mt] = pw[2 * (fb + mt * 32)];
            al[mt] = pw[2 * (fb + mt * 32) + 1];
        }
#pragma unroll 1
        for (int tap = 0; tap < 25; tap++) {
            int dy = tap / 5, dx = tap - 5 * dy;
            int rowbase = ((nw + dy) * 36 + dx) * 72;
#pragma unroll
            for (int kch = 0; kch < 4; kch++) {
                int fn = (tap == 24 && kch == 3) ? fb : fb + (kch < 3 ? S1 : S2);
                uint4 nah[2], nal[2];
#pragma unroll
                for (int mt = 0; mt < 2; mt++) {
                    nah[mt] = pw[2 * (fn + mt * 32)];
                    nal[mt] = pw[2 * (fn + mt * 32) + 1];
                }
                unsigned Bs[4][2];
#pragma unroll
                for (int nt = 0; nt < 4; nt++) {
                    int off = rowbase + (nt * 8 + g) * 72 + kch * 16 + 2 * tg;
                    Bs[nt][0] = *(const unsigned*)(Xs + off);
                    Bs[nt][1] = *(const unsigned*)(Xs + off + 8);
                }
#pragma unroll
                for (int mt = 0; mt < 2; mt++)
#pragma unroll
                    for (int nt = 0; nt < 4; nt++) mma_f16(D[mt][nt], ah[mt], Bs[nt]);
#pragma unroll
                for (int mt = 0; mt < 2; mt++)
#pragma unroll
                    for (int nt = 0; nt < 4; nt++) mma_f16(D[mt][nt], al[mt], Bs[nt]);
#pragma unroll
                for (int mt = 0; mt < 2; mt++) { ah[mt] = nah[mt]; al[mt] = nal[mt]; }
                fb = fn;
            }
        }
    }

    // ---- fused epilogue ----
    int y = y0 + nw;
#pragma unroll
    for (int mt = 0; mt < 2; mt++) {
#pragma unroll
        for (int ci2 = 0; ci2 < 2; ci2++) {
            int   ocG = och * 64 + mw * 32 + mt * 16 + g + 8 * ci2;
            float bv  = bias[ocG];
#pragma unroll
            for (int nt = 0; nt < 4; nt++) {
#pragma unroll
                for (int j = 0; j < 2; j++) {
                    float v  = D[mt][nt][ci2 * 2 + j] + bv;
                    int   x  = nt * 8 + 2 * tg + j;
                    int   px = y * 32 + x;
                    if (act_mode == 0) {
                        float s = 1.f / (1.f + expf(-v));
                        if (ocG < 64) {
                            int hi = (b * 64 + ocG) * 1024 + px;
                            g_rhp[hi] = h16(s * g_h[hi]);
                        } else {
                            g_z[(b * 64 + ocG - 64) * 1024 + px] = s;
                        }
                    } else {
                        float c  = tanhf(v);
                        int   hi = (b * 64 + ocG) * 1024 + px;
                        float z  = g_z[hi];
                        float hp = g_h[hi];
                        float hn = (1.f - z) * hp + z * c;
                        g_h[hi]  = hn;
                        g_hp[hi] = h16(hn);
                        if (write_hs) g_hs[t * 2097152 + hi] = hn;
                    }
                }
            }
        }
    }
}

// ---------------- encoder conv1: 1->16 ch, 3x3 s2 p1, 128->64, lrelu ----------------
__global__ __launch_bounds__(256) void enc_conv1(const float* __restrict__ x,
                                                 const float* __restrict__ w,
                                                 const float* __restrict__ bias) {
    __shared__ float sw[144], sb[16];
    int tid = threadIdx.x;
    if (tid < 144) sw[tid] = w[tid];
    if (tid < 16)  sb[tid] = bias[tid];
    __syncthreads();
    int n = blockIdx.x, p = blockIdx.y * 256 + tid;
    int oy = p >> 6, ox = p & 63;
    const float* xi = x + n * 16384;
    float win[9];
    int iy0 = 2 * oy - 1, ix0 = 2 * ox - 1;
#pragma unroll
    for (int ky = 0; ky < 3; ky++)
#pragma unroll
        for (int kx = 0; kx < 3; kx++) {
            int iy = iy0 + ky, ix = ix0 + kx;
            win[ky * 3 + kx] = ((unsigned)iy < 128u && (unsigned)ix < 128u) ? xi[iy * 128 + ix] : 0.f;
        }
#pragma unroll
    for (int oc = 0; oc < 16; oc++) {
        float a = sb[oc];
#pragma unroll
        for (int k = 0; k < 9; k++) a += sw[oc * 9 + k] * win[k];
        g_e1[(n * 16 + oc) * 4096 + p] = (a >= 0.f) ? a : 0.2f * a;
    }
}

// ---------------- encoder conv2: 16->64 ch, 3x3 s2 p1, 64->32, lrelu, emit fp16 ----------------
__global__ __launch_bounds__(256) void enc_conv2(const float* __restrict__ w,
                                                 const float* __restrict__ bias) {
    __shared__ float sw[9216];
    int tid = threadIdx.x;
    for (int i = tid; i < 9216; i += 256) sw[i] = w[i];
    __syncthreads();
    int n = blockIdx.x, p = blockIdx.y * 256 + tid;
    int oy = p >> 5, ox = p & 31;
    const float* in = g_e1 + n * 65536;
    float acc[64];
#pragma unroll
    for (int oc = 0; oc < 64; oc++) acc[oc] = bias[oc];
    int iy0 = 2 * oy - 1, ix0 = 2 * ox - 1;
#pragma unroll 1
    for (int ic = 0; ic < 16; ic++) {
        float win[9];
#pragma unroll
        for (int ky = 0; ky < 3; ky++)
#pragma unroll
            for (int kx = 0; kx < 3; kx++) {
                int iy = iy0 + ky, ix = ix0 + kx;
                win[ky * 3 + kx] = ((unsigned)iy < 64u && (unsigned)ix < 64u)
                                       ? in[ic * 4096 + iy * 64 + ix] : 0.f;
            }
#pragma unroll
        for (int oc = 0; oc < 64; oc++)
#pragma unroll
            for (int k = 0; k < 9; k++) acc[oc] += sw[(oc * 16 + ic) * 9 + k] * win[k];
    }
#pragma unroll
    for (int oc = 0; oc < 64; oc++) {
        float a = acc[oc];
        a = (a >= 0.f) ? a : 0.2f * a;
        g_e2p[(n * 64 + oc) * 1024 + p] = h16(a);
    }
}

// ---------------- deconv1: 64->32 ch, 4x4 lhs_dil 2 pad 2, 32->64, lrelu ----------------
__global__ __launch_bounds__(256) void deconv1(const float* __restrict__ w,
                                               const float* __restrict__ bias) {
    __shared__ float s_in[8192], s_w[512];
    int n = blockIdx.x, ocg = blockIdx.y, tid = threadIdx.x;
    int oy = tid >> 2, ox0 = (tid & 3) << 4;
    float acc[4][16];
#pragma unroll
    for (int i = 0; i < 4; i++)
#pragma unroll
        for (int j = 0; j < 16; j++) acc[i][j] = 0.f;
    int ky0 = oy & 1;
    int iyA = (oy + ky0 - 2) >> 1, iyB = iyA + 1;
    const float* in = g_hs + n * 65536;
    int ixbase = (ox0 >> 1) - 1;
#pragma unroll 1
    for (int cc = 0; cc < 8; cc++) {
        int ic0 = cc * 8;
        for (int idx = tid; idx < 8192; idx += 256) s_in[idx] = in[ic0 * 1024 + idx];
        for (int idx = tid; idx < 512; idx += 256) {
            int oc = idx >> 7, rem = idx & 127, ic = rem >> 4, k = rem & 15;
            s_w[idx] = w[((ocg * 4 + oc) * 64 + ic0 + ic) * 16 + k];
        }
        __syncthreads();
#pragma unroll 1
        for (int ic = 0; ic < 8; ic++) {
            float segA[10], segB[10];
#pragma unroll
            for (int m = 0; m < 10; m++) {
                int ix = ixbase + m;
                bool xok = (unsigned)ix < 32u;
                segA[m] = (xok && (unsigned)iyA < 32u) ? s_in[ic * 1024 + iyA * 32 + ix] : 0.f;
                segB[m] = (xok && (unsigned)iyB < 32u) ? s_in[ic * 1024 + iyB * 32 + ix] : 0.f;
            }
#pragma unroll
            for (int j = 0; j < 16; j++) {
                int kx0 = j & 1, mA = (j + kx0) >> 1, mB = mA + 1;
#pragma unroll
                for (int oc = 0; oc < 4; oc++) {
                    const float* wp = &s_w[(oc * 8 + ic) * 16];
                    acc[oc][j] += wp[ky0 * 4 + kx0] * segA[mA] + wp[ky0 * 4 + kx0 + 2] * segA[mB]
                                + wp[(ky0 + 2) * 4 + kx0] * segB[mA] + wp[(ky0 + 2) * 4 + kx0 + 2] * segB[mB];
                }
            }
        }
        __syncthreads();
    }
#pragma unroll
    for (int oc = 0; oc < 4; oc++) {
        int ocG = ocg * 4 + oc;
        float bv = bias[ocG];
#pragma unroll
        for (int j = 0; j < 16; j++) {
            float a = acc[oc][j] + bv;
            g_y1[(n * 32 + ocG) * 4096 + oy * 64 + ox0 + j] = (a >= 0.f) ? a : 0.2f * a;
        }
    }
}

// ---------------- deconv2: 32->1 ch, 4x4 lhs_dil 2 pad 2, 64->128, + transpose ----------------
__global__ __launch_bounds__(256) void deconv2(const float* __restrict__ w,
                                               const float* __restrict__ bias,
                                               float* __restrict__ out) {
    __shared__ float sw[512];
    int tid = threadIdx.x;
    for (int i = tid; i < 512; i += 256) sw[i] = w[i];
    __syncthreads();
    int n = blockIdx.x, p = blockIdx.y * 256 + tid;
    int oy = p >> 7, ox = p & 127;
    int ky0 = oy & 1, kx0 = ox & 1;
    int iyA = (oy + ky0 - 2) >> 1, iyB = iyA + 1;
    int ixA = (ox + kx0 - 2) >> 1, ixB = ixA + 1;
    bool yA = (unsigned)iyA < 64u, yB = (unsigned)iyB < 64u;
    bool xA = (unsigned)ixA < 64u, xB = (unsigned)ixB < 64u;
    const float* in = g_y1 + n * 131072;
    float acc = bias[0];
#pragma unroll 1
    for (int ic = 0; ic < 32; ic++) {
        const float* ip = in + ic * 4096;
        float vAA = (yA && xA) ? ip[iyA * 64 + ixA] : 0.f;
        float vAB = (yA && xB) ? ip[iyA * 64 + ixB] : 0.f;
        float vBA = (yB && xA) ? ip[iyB * 64 + ixA] : 0.f;
        float vBB = (yB && xB) ? ip[iyB * 64 + ixB] : 0.f;
        const float* wp = &sw[ic * 16];
        acc += wp[ky0 * 4 + kx0] * vAA + wp[ky0 * 4 + kx0 + 2] * vAB
             + wp[(ky0 + 2) * 4 + kx0] * vBA + wp[(ky0 + 2) * 4 + kx0 + 2] * vBB;
    }
    int t = n >> 5, b = n & 31;
    out[(b * 10 + t) * 16384 + p] = acc;
}

// ---------------- launch ----------------
extern "C" void kernel_launch(void* const* d_in, const int* in_sizes, int n_in,
                              void* d_out, int out_size) {
    const float* x           = (const float*)d_in[0];
    const float* enc_w1      = (const float*)d_in[1];
    const float* enc_b1      = (const float*)d_in[2];
    const float* enc_w2      = (const float*)d_in[3];
    const float* enc_b2      = (const float*)d_in[4];
    const float* enc_gru_wzr = (const float*)d_in[5];
    const float* enc_gru_bzr = (const float*)d_in[6];
    const float* enc_gru_wc  = (const float*)d_in[7];
    const float* enc_gru_bc  = (const float*)d_in[8];
    const float* dec_gru_wzr = (const float*)d_in[9];
    const float* dec_gru_bzr = (const float*)d_in[10];
    const float* dec_gru_wc  = (const float*)d_in[11];
    const float* dec_gru_bc  = (const float*)d_in[12];
    const float* dec_w1      = (const float*)d_in[13];
    const float* dec_b1      = (const float*)d_in[14];
    const float* dec_w2      = (const float*)d_in[15];
    const float* dec_b2      = (const float*)d_in[16];
    float* out = (float*)d_out;

    const int SMB = 288 * 72 * 2;   // 41472 B fp16 X tile
    cudaFuncSetAttribute(gru2<2>, cudaFuncAttributeMaxDynamicSharedMemorySize, SMB);
    cudaFuncSetAttribute(gru2<1>, cudaFuncAttributeMaxDynamicSharedMemorySize, SMB);

    init_all<<<(2097152 + 1843200 + 255) / 256, 256>>>(enc_gru_wzr, enc_gru_wc,
                                                       dec_gru_wzr, dec_gru_wc);   // #1
    enc_conv1<<<dim3(320, 16), 256>>>(x, enc_w1, enc_b1);                          // #2
    enc_conv2<<<dim3(320, 4), 256>>>(enc_w2, enc_b2);                              // #3

    for (int t = 0; t < 10; t++) {                                                 // #4,#5,#6(captured)...
        gru2<2><<<dim3(32, 8, 2), 256, SMB>>>(t, 0, 8, 0, enc_gru_bzr, 0, 0);
        gru2<2><<<dim3(32, 8, 1), 256, SMB>>>(t, 1, 4, 819200, enc_gru_bc, 1, 0);
    }
    for (int t = 0; t < 10; t++) {
        gru2<1><<<dim3(32, 8, 2), 256, SMB>>>(t, 2, 8, 1228800, dec_gru_bzr, 0, 0);
        gru2<1><<<dim3(32, 8, 1), 256, SMB>>>(t, 3, 4, 1638400, dec_gru_bc, 1, 1);
    }

    deconv1<<<dim3(320, 8), 256>>>(dec_w1, dec_b1);
    deconv2<<<dim3(320, 64), 256>>>(dec_w2, dec_b2, out);
}

// round 10
// speedup vs baseline: 6.9319x; 1.4352x over previous
#include <cuda_runtime.h>
#include <cuda_fp16.h>
#include <stdint.h>
#include <math.h>

#define BB 32
#define TT 10

// ---------------- scratch (device globals; no allocs allowed) ----------------
__device__ float          g_e1 [320 * 16 * 64 * 64];   // encoder conv1 out (fp32)
__device__ unsigned short g_e2p[320 * 64 * 1024];      // encoder conv2 out (fp16 bits)
__device__ float          g_h  [BB * 64 * 1024];       // GRU hidden (fp32 master)
__device__ unsigned short g_hp [BB * 64 * 1024];       // h (fp16 bits)
__device__ float          g_z  [BB * 64 * 1024];       // z gate (fp32)
__device__ unsigned short g_rhp[BB * 64 * 1024];       // r*h (fp16 bits)
__device__ float          g_hs [TT * BB * 64 * 1024];  // decoder hidden outputs (fp32)
__device__ float          g_y1 [320 * 32 * 64 * 64];   // deconv1 out
__device__ unsigned short g_wp [921600];               // fragment-packed W, fp16 (single term)

__device__ __forceinline__ unsigned short h16(float v) {
    return __half_as_ushort(__float2half(v));
}

// ---------------- fused init: zero h/hp + pack all 4 weight regions (fp16 single) ----------------
// layout: [tap][kc][ob][lane][r][e] fp16
__global__ void init_all(const float* __restrict__ ewzr, const float* __restrict__ ewc,
                         const float* __restrict__ dwzr, const float* __restrict__ dwc) {
    long idx = (long)blockIdx.x * 256 + threadIdx.x;
    if (idx < 2097152) { g_h[idx] = 0.f; g_hp[idx] = 0; return; }
    idx -= 2097152;
    const float* w; int OC, IC, icoff, dofs;
    if (idx < 409600)      { w = ewzr; OC = 128; IC = 128; icoff = 0;  dofs = 0; }
    else if (idx < 614400) { idx -= 409600; w = ewc;  OC = 64;  IC = 128; icoff = 0;  dofs = 409600; }
    else if (idx < 819200) { idx -= 614400; w = dwzr; OC = 128; IC = 64;  icoff = 64; dofs = 614400; }
    else if (idx < 921600) { idx -= 819200; w = dwc;  OC = 64;  IC = 64;  icoff = 64; dofs = 819200; }
    else return;
    int KC = IC >> 4, NOB = OC >> 4;
    int e    = idx & 1;
    int r    = ((int)idx >> 1) & 3;
    int lane = ((int)idx >> 3) & 31;
    int v    = (int)idx >> 8;
    int ob   = v % NOB;
    int v2   = v / NOB;
    int kc   = v2 % KC;
    int tap  = v2 / KC;
    int g = lane >> 2, t = lane & 3;
    int oc = ob * 16 + g + 8 * (r & 1);
    int ic = kc * 16 + 2 * t + 8 * (r >> 1) + e;
    g_wp[dofs + idx] = h16(w[(oc * 128 + icoff + ic) * 25 + tap]);
}

// ---------------- mma helper (fp16 in, fp32 accum) ----------------
__device__ __forceinline__ void mma_f16(float (&d)[4], const uint4& a, const unsigned (&b)[2]) {
    asm volatile(
        "mma.sync.aligned.m16n8k16.row.col.f32.f16.f16.f32 "
        "{%0,%1,%2,%3}, {%4,%5,%6,%7}, {%8,%9}, {%0,%1,%2,%3};\n"
        : "+f"(d[0]), "+f"(d[1]), "+f"(d[2]), "+f"(d[3])
        : "r"(a.x), "r"(a.y), "r"(a.z), "r"(a.w), "r"(b[0]), "r"(b[1]));
}

// ---------------- GRU 5x5 conv via mma.sync fp16 (single W term); IC in 64-ch halves ----------------
// mode: 0=enc zr (e2p ++ hp)  1=enc cand (e2p ++ rhp)  2=dec zr (hp)  3=dec cand (rhp)
// act_mode 0: sigmoid -> r-CTA writes g_rhp, z-CTA writes g_z; act_mode 1: tanh -> h update (+hs)
template <int NH>
__global__ __launch_bounds__(256, 2) void gru2(int t, int mode, int nob, int wofs,
                                               const float* __restrict__ bias,
                                               int act_mode, int write_hs) {
    extern __shared__ unsigned short Xs[];   // [288 px][72] fp16 bits

    int b   = blockIdx.x;
    int y0  = blockIdx.y * 4;
    int och = blockIdx.z;
    int tid = threadIdx.x;
    int w   = tid >> 5, lane = tid & 31;
    int g   = lane >> 2, tg = lane & 3;
    int mw  = w >> 2, nw = w & 3;

    const unsigned short* s0p;
    const unsigned short* s1p;
    if (mode <= 1) {
        s0p = g_e2p + (b * 10 + t) * 65536;
        s1p = (mode == 0 ? g_hp : g_rhp) + b * 65536;
    } else {
        s0p = (mode == 2 ? g_hp : g_rhp) + b * 65536;
        s1p = s0p;
    }

    float D[2][4][4];
#pragma unroll
    for (int mt = 0; mt < 2; mt++)
#pragma unroll
        for (int nt = 0; nt < 4; nt++)
#pragma unroll
            for (int i = 0; i < 4; i++) D[mt][nt][i] = 0.f;

    const uint4* pw = reinterpret_cast<const uint4*>(g_wp) + (wofs >> 3);
    const int KC = NH * 4;
    const int S1 = nob * 32;
    const int S2 = (KC - 3) * nob * 32;
    const int ob0 = och * 4 + mw * 2;

#pragma unroll 1
    for (int h = 0; h < NH; h++) {
        if (h) __syncthreads();
        // ---- stage 64-ch half: fp16 source -> [sy][sx][c] fp16 smem ----
        const unsigned short* base = (h == 0) ? s0p : s1p;
        int c = tid & 63;
#pragma unroll
        for (int it = 0; it < 2; it++) {
            int sy = (tid >> 6) | (it << 2);
            int yy = y0 - 2 + sy;
            bool rv = (unsigned)yy < 32u;
            const uint4* src = (const uint4*)(base + c * 1024 + yy * 32);
            uint4 q[4];
            if (rv) {
#pragma unroll
                for (int k2 = 0; k2 < 4; k2++) q[k2] = src[k2];
            } else {
#pragma unroll
                for (int k2 = 0; k2 < 4; k2++) q[k2] = make_uint4(0u, 0u, 0u, 0u);
            }
            const unsigned short* hv = (const unsigned short*)q;
            int rb = sy * 36;
#pragma unroll
            for (int sx = 0; sx < 36; sx++) {
                unsigned short v = (sx < 2 || sx >= 34) ? (unsigned short)0 : hv[sx - 2];
                Xs[(rb + sx) * 72 + c] = v;
            }
        }
        __syncthreads();

        // ---- MMA over taps x 4 k-chunks of this half: D += X*W ----
        int fb = (h * 4 * nob + ob0) * 32 + lane;
        uint4 ah[2];
#pragma unroll
        for (int mt = 0; mt < 2; mt++) ah[mt] = pw[fb + mt * 32];
#pragma unroll 1
        for (int tap = 0; tap < 25; tap++) {
            int dy = tap / 5, dx = tap - 5 * dy;
            int rowbase = ((nw + dy) * 36 + dx) * 72;
#pragma unroll
            for (int kch = 0; kch < 4; kch++) {
                int fn = (tap == 24 && kch == 3) ? fb : fb + (kch < 3 ? S1 : S2);
                uint4 nah[2];
#pragma unroll
                for (int mt = 0; mt < 2; mt++) nah[mt] = pw[fn + mt * 32];
                unsigned Bs[4][2];
#pragma unroll
                for (int nt = 0; nt < 4; nt++) {
                    int off = rowbase + (nt * 8 + g) * 72 + kch * 16 + 2 * tg;
                    Bs[nt][0] = *(const unsigned*)(Xs + off);
                    Bs[nt][1] = *(const unsigned*)(Xs + off + 8);
                }
#pragma unroll
                for (int mt = 0; mt < 2; mt++)
#pragma unroll
                    for (int nt = 0; nt < 4; nt++) mma_f16(D[mt][nt], ah[mt], Bs[nt]);
#pragma unroll
                for (int mt = 0; mt < 2; mt++) ah[mt] = nah[mt];
                fb = fn;
            }
        }
    }

    // ---- fused epilogue ----
    int y = y0 + nw;
#pragma unroll
    for (int mt = 0; mt < 2; mt++) {
#pragma unroll
        for (int ci2 = 0; ci2 < 2; ci2++) {
            int   ocG = och * 64 + mw * 32 + mt * 16 + g + 8 * ci2;
            float bv  = bias[ocG];
#pragma unroll
            for (int nt = 0; nt < 4; nt++) {
#pragma unroll
                for (int j = 0; j < 2; j++) {
                    float v  = D[mt][nt][ci2 * 2 + j] + bv;
                    int   x  = nt * 8 + 2 * tg + j;
                    int   px = y * 32 + x;
                    if (act_mode == 0) {
                        float s = 1.f / (1.f + expf(-v));
                        if (ocG < 64) {
                            int hi = (b * 64 + ocG) * 1024 + px;
                            g_rhp[hi] = h16(s * g_h[hi]);
                        } else {
                            g_z[(b * 64 + ocG - 64) * 1024 + px] = s;
                        }
                    } else {
                        float c  = tanhf(v);
                        int   hi = (b * 64 + ocG) * 1024 + px;
                        float z  = g_z[hi];
                        float hp = g_h[hi];
                        float hn = (1.f - z) * hp + z * c;
                        g_h[hi]  = hn;
                        g_hp[hi] = h16(hn);
                        if (write_hs) g_hs[t * 2097152 + hi] = hn;
                    }
                }
            }
        }
    }
}

// ---------------- encoder conv1: 1->16 ch, 3x3 s2 p1, 128->64, lrelu ----------------
__global__ __launch_bounds__(256) void enc_conv1(const float* __restrict__ x,
                                                 const float* __restrict__ w,
                                                 const float* __restrict__ bias) {
    __shared__ float sw[144], sb[16];
    int tid = threadIdx.x;
    if (tid < 144) sw[tid] = w[tid];
    if (tid < 16)  sb[tid] = bias[tid];
    __syncthreads();
    int n = blockIdx.x, p = blockIdx.y * 256 + tid;
    int oy = p >> 6, ox = p & 63;
    const float* xi = x + n * 16384;
    float win[9];
    int iy0 = 2 * oy - 1, ix0 = 2 * ox - 1;
#pragma unroll
    for (int ky = 0; ky < 3; ky++)
#pragma unroll
        for (int kx = 0; kx < 3; kx++) {
            int iy = iy0 + ky, ix = ix0 + kx;
            win[ky * 3 + kx] = ((unsigned)iy < 128u && (unsigned)ix < 128u) ? xi[iy * 128 + ix] : 0.f;
        }
#pragma unroll
    for (int oc = 0; oc < 16; oc++) {
        float a = sb[oc];
#pragma unroll
        for (int k = 0; k < 9; k++) a += sw[oc * 9 + k] * win[k];
        g_e1[(n * 16 + oc) * 4096 + p] = (a >= 0.f) ? a : 0.2f * a;
    }
}

// ---------------- encoder conv2: 16->64 ch, 3x3 s2 p1, 64->32, lrelu, emit fp16 ----------------
__global__ __launch_bounds__(256) void enc_conv2(const float* __restrict__ w,
                                                 const float* __restrict__ bias) {
    __shared__ float sw[9216];
    int tid = threadIdx.x;
    for (int i = tid; i < 9216; i += 256) sw[i] = w[i];
    __syncthreads();
    int n = blockIdx.x, p = blockIdx.y * 256 + tid;
    int oy = p >> 5, ox = p & 31;
    const float* in = g_e1 + n * 65536;
    float acc[64];
#pragma unroll
    for (int oc = 0; oc < 64; oc++) acc[oc] = bias[oc];
    int iy0 = 2 * oy - 1, ix0 = 2 * ox - 1;
#pragma unroll 1
    for (int ic = 0; ic < 16; ic++) {
        float win[9];
#pragma unroll
        for (int ky = 0; ky < 3; ky++)
#pragma unroll
            for (int kx = 0; kx < 3; kx++) {
                int iy = iy0 + ky, ix = ix0 + kx;
                win[ky * 3 + kx] = ((unsigned)iy < 64u && (unsigned)ix < 64u)
                                       ? in[ic * 4096 + iy * 64 + ix] : 0.f;
            }
#pragma unroll
        for (int oc = 0; oc < 64; oc++)
#pragma unroll
            for (int k = 0; k < 9; k++) acc[oc] += sw[(oc * 16 + ic) * 9 + k] * win[k];
    }
#pragma unroll
    for (int oc = 0; oc < 64; oc++) {
        float a = acc[oc];
        a = (a >= 0.f) ? a : 0.2f * a;
        g_e2p[(n * 64 + oc) * 1024 + p] = h16(a);
    }
}

// ---------------- deconv1: 64->32 ch, 4x4 lhs_dil 2 pad 2, 32->64, lrelu ----------------
__global__ __launch_bounds__(256) void deconv1(const float* __restrict__ w,
                                               const float* __restrict__ bias) {
    __shared__ float s_in[8192], s_w[512];
    int n = blockIdx.x, ocg = blockIdx.y, tid = threadIdx.x;
    int oy = tid >> 2, ox0 = (tid & 3) << 4;
    float acc[4][16];
#pragma unroll
    for (int i = 0; i < 4; i++)
#pragma unroll
        for (int j = 0; j < 16; j++) acc[i][j] = 0.f;
    int ky0 = oy & 1;
    int iyA = (oy + ky0 - 2) >> 1, iyB = iyA + 1;
    const float* in = g_hs + n * 65536;
    int ixbase = (ox0 >> 1) - 1;
#pragma unroll 1
    for (int cc = 0; cc < 8; cc++) {
        int ic0 = cc * 8;
        for (int idx = tid; idx < 8192; idx += 256) s_in[idx] = in[ic0 * 1024 + idx];
        for (int idx = tid; idx < 512; idx += 256) {
            int oc = idx >> 7, rem = idx & 127, ic = rem >> 4, k = rem & 15;
            s_w[idx] = w[((ocg * 4 + oc) * 64 + ic0 + ic) * 16 + k];
        }
        __syncthreads();
#pragma unroll 1
        for (int ic = 0; ic < 8; ic++) {
            float segA[10], segB[10];
#pragma unroll
            for (int m = 0; m < 10; m++) {
                int ix = ixbase + m;
                bool xok = (unsigned)ix < 32u;
                segA[m] = (xok && (unsigned)iyA < 32u) ? s_in[ic * 1024 + iyA * 32 + ix] : 0.f;
                segB[m] = (xok && (unsigned)iyB < 32u) ? s_in[ic * 1024 + iyB * 32 + ix] : 0.f;
            }
#pragma unroll
            for (int j = 0; j < 16; j++) {
                int kx0 = j & 1, mA = (j + kx0) >> 1, mB = mA + 1;
#pragma unroll
                for (int oc = 0; oc < 4; oc++) {
                    const float* wp = &s_w[(oc * 8 + ic) * 16];
                    acc[oc][j] += wp[ky0 * 4 + kx0] * segA[mA] + wp[ky0 * 4 + kx0 + 2] * segA[mB]
                                + wp[(ky0 + 2) * 4 + kx0] * segB[mA] + wp[(ky0 + 2) * 4 + kx0 + 2] * segB[mB];
                }
            }
        }
        __syncthreads();
    }
#pragma unroll
    for (int oc = 0; oc < 4; oc++) {
        int ocG = ocg * 4 + oc;
        float bv = bias[ocG];
#pragma unroll
        for (int j = 0; j < 16; j++) {
            float a = acc[oc][j] + bv;
            g_y1[(n * 32 + ocG) * 4096 + oy * 64 + ox0 + j] = (a >= 0.f) ? a : 0.2f * a;
        }
    }
}

// ---------------- deconv2: 32->1 ch, 4x4 lhs_dil 2 pad 2, 64->128, + transpose ----------------
__global__ __launch_bounds__(256) void deconv2(const float* __restrict__ w,
                                               const float* __restrict__ bias,
                                               float* __restrict__ out) {
    __shared__ float sw[512];
    int tid = threadIdx.x;
    for (int i = tid; i < 512; i += 256) sw[i] = w[i];
    __syncthreads();
    int n = blockIdx.x, p = blockIdx.y * 256 + tid;
    int oy = p >> 7, ox = p & 127;
    int ky0 = oy & 1, kx0 = ox & 1;
    int iyA = (oy + ky0 - 2) >> 1, iyB = iyA + 1;
    int ixA = (ox + kx0 - 2) >> 1, ixB = ixA + 1;
    bool yA = (unsigned)iyA < 64u, yB = (unsigned)iyB < 64u;
    bool xA = (unsigned)ixA < 64u, xB = (unsigned)ixB < 64u;
    const float* in = g_y1 + n * 131072;
    float acc = bias[0];
#pragma unroll 1
    for (int ic = 0; ic < 32; ic++) {
        const float* ip = in + ic * 4096;
        float vAA = (yA && xA) ? ip[iyA * 64 + ixA] : 0.f;
        float vAB = (yA && xB) ? ip[iyA * 64 + ixB] : 0.f;
        float vBA = (yB && xA) ? ip[iyB * 64 + ixA] : 0.f;
        float vBB = (yB && xB) ? ip[iyB * 64 + ixB] : 0.f;
        const float* wp = &sw[ic * 16];
        acc += wp[ky0 * 4 + kx0] * vAA + wp[ky0 * 4 + kx0 + 2] * vAB
             + wp[(ky0 + 2) * 4 + kx0] * vBA + wp[(ky0 + 2) * 4 + kx0 + 2] * vBB;
    }
    int t = n >> 5, b = n & 31;
    out[(b * 10 + t) * 16384 + p] = acc;
}

// ---------------- launch ----------------
extern "C" void kernel_launch(void* const* d_in, const int* in_sizes, int n_in,
                              void* d_out, int out_size) {
    const float* x           = (const float*)d_in[0];
    const float* enc_w1      = (const float*)d_in[1];
    const float* enc_b1      = (const float*)d_in[2];
    const float* enc_w2      = (const float*)d_in[3];
    const float* enc_b2      = (const float*)d_in[4];
    const float* enc_gru_wzr = (const float*)d_in[5];
    const float* enc_gru_bzr = (const float*)d_in[6];
    const float* enc_gru_wc  = (const float*)d_in[7];
    const float* enc_gru_bc  = (const float*)d_in[8];
    const float* dec_gru_wzr = (const float*)d_in[9];
    const float* dec_gru_bzr = (const float*)d_in[10];
    const float* dec_gru_wc  = (const float*)d_in[11];
    const float* dec_gru_bc  = (const float*)d_in[12];
    const float* dec_w1      = (const float*)d_in[13];
    const float* dec_b1      = (const float*)d_in[14];
    const float* dec_w2      = (const float*)d_in[15];
    const float* dec_b2      = (const float*)d_in[16];
    float* out = (float*)d_out;

    const int SMB = 288 * 72 * 2;   // 41472 B fp16 X tile
    cudaFuncSetAttribute(gru2<2>, cudaFuncAttributeMaxDynamicSharedMemorySize, SMB);
    cudaFuncSetAttribute(gru2<1>, cudaFuncAttributeMaxDynamicSharedMemorySize, SMB);

    init_all<<<(2097152 + 921600 + 255) / 256, 256>>>(enc_gru_wzr, enc_gru_wc,
                                                      dec_gru_wzr, dec_gru_wc);    // #1
    enc_conv1<<<dim3(320, 16), 256>>>(x, enc_w1, enc_b1);                          // #2
    enc_conv2<<<dim3(320, 4), 256>>>(enc_w2, enc_b2);                              // #3

    for (int t = 0; t < 10; t++) {                                                 // #4,#5,#6(captured)...
        gru2<2><<<dim3(32, 8, 2), 256, SMB>>>(t, 0, 8, 0, enc_gru_bzr, 0, 0);
        gru2<2><<<dim3(32, 8, 1), 256, SMB>>>(t, 1, 4, 409600, enc_gru_bc, 1, 0);
    }
    for (int t = 0; t < 10; t++) {
        gru2<1><<<dim3(32, 8, 2), 256, SMB>>>(t, 2, 8, 614400, dec_gru_bzr, 0, 0);
        gru2<1><<<dim3(32, 8, 1), 256, SMB>>>(t, 3, 4, 819200, dec_gru_bc, 1, 1);
    }

    deconv1<<<dim3(320, 8), 256>>>(dec_w1, dec_b1);
    deconv2<<<dim3(320, 64), 256>>>(dec_w2, dec_b2, out);
}

// round 11
// speedup vs baseline: 8.4523x; 1.2193x over previous
#include <cuda_runtime.h>
#include <cuda_fp16.h>
#include <stdint.h>
#include <math.h>

#define BB 32
#define TT 10

// ---------------- scratch (device globals; no allocs allowed) ----------------
__device__ float          g_e1 [320 * 16 * 64 * 64];   // encoder conv1 out (fp32)
__device__ unsigned short g_e2p[320 * 64 * 1024];      // encoder conv2 out (fp16 bits)
__device__ float          g_h  [BB * 64 * 1024];       // GRU hidden (fp32 master)
__device__ unsigned short g_hp [BB * 64 * 1024];       // h (fp16 bits)
__device__ float          g_z  [BB * 64 * 1024];       // z gate (fp32)
__device__ unsigned short g_rhp[BB * 64 * 1024];       // r*h (fp16 bits)
__device__ unsigned short g_hsp[TT * BB * 64 * 1024];  // decoder hidden outputs (fp16 bits)
__device__ float          g_y1 [320 * 32 * 64 * 64];   // deconv1 out (fp32)
__device__ __align__(16) unsigned short g_wp [921600]; // GRU W fragments, fp16
__device__ __align__(16) unsigned short g_wd1[32768];  // deconv1 W fragments, fp16

__device__ __forceinline__ unsigned short h16(float v) {
    return __half_as_ushort(__float2half(v));
}

// ---------------- fused init: zero h/hp + pack GRU weights + pack deconv1 weights ----------------
__global__ void init_all(const float* __restrict__ ewzr, const float* __restrict__ ewc,
                         const float* __restrict__ dwzr, const float* __restrict__ dwc,
                         const float* __restrict__ dw1) {
    long lidx = (long)blockIdx.x * 256 + threadIdx.x;
    if (lidx < 2097152) { g_h[lidx] = 0.f; g_hp[lidx] = 0; return; }
    int idx = (int)(lidx - 2097152);
    if (idx >= 921600) {
        // deconv1 weights: [p][tt][kc][ob][lane][r][e]
        int id = idx - 921600;
        if (id >= 32768) return;
        int e    = id & 1;
        int r    = (id >> 1) & 3;
        int lane = (id >> 3) & 31;
        int ob   = (id >> 8) & 1;
        int kc   = (id >> 9) & 3;
        int tt   = (id >> 11) & 3;
        int p    = (id >> 13) & 3;
        int g = lane >> 2, tg = lane & 3;
        int oc = ob * 16 + g + 8 * (r & 1);
        int ic = kc * 16 + 2 * tg + 8 * (r >> 1) + e;
        int a = p >> 1, bb = p & 1, jy = tt >> 1, jx = tt & 1;
        int kidx = (a + 2 * jy) * 4 + (bb + 2 * jx);
        g_wd1[id] = h16(dw1[(oc * 64 + ic) * 16 + kidx]);
        return;
    }
    const float* w; int OC, IC, icoff, dofs;
    if (idx < 409600)      { w = ewzr; OC = 128; IC = 128; icoff = 0;  dofs = 0; }
    else if (idx < 614400) { idx -= 409600; w = ewc;  OC = 64;  IC = 128; icoff = 0;  dofs = 409600; }
    else if (idx < 819200) { idx -= 614400; w = dwzr; OC = 128; IC = 64;  icoff = 64; dofs = 614400; }
    else                   { idx -= 819200; w = dwc;  OC = 64;  IC = 64;  icoff = 64; dofs = 819200; }
    int KC = IC >> 4, NOB = OC >> 4;
    int e    = idx & 1;
    int r    = (idx >> 1) & 3;
    int lane = (idx >> 3) & 31;
    int v    = idx >> 8;
    int ob   = v % NOB;
    int v2   = v / NOB;
    int kc   = v2 % KC;
    int tap  = v2 / KC;
    int g = lane >> 2, t = lane & 3;
    int oc = ob * 16 + g + 8 * (r & 1);
    int ic = kc * 16 + 2 * t + 8 * (r >> 1) + e;
    g_wp[dofs + idx] = h16(w[(oc * 128 + icoff + ic) * 25 + tap]);
}

// ---------------- mma helper (fp16 in, fp32 accum) ----------------
__device__ __forceinline__ void mma_f16(float (&d)[4], const uint4& a, const unsigned (&b)[2]) {
    asm volatile(
        "mma.sync.aligned.m16n8k16.row.col.f32.f16.f16.f32 "
        "{%0,%1,%2,%3}, {%4,%5,%6,%7}, {%8,%9}, {%0,%1,%2,%3};\n"
        : "+f"(d[0]), "+f"(d[1]), "+f"(d[2]), "+f"(d[3])
        : "r"(a.x), "r"(a.y), "r"(a.z), "r"(a.w), "r"(b[0]), "r"(b[1]));
}

#define LOADB(dst, rb, kch) do {                                        \
    _Pragma("unroll")                                                   \
    for (int nt_ = 0; nt_ < 4; nt_++) {                                 \
        int off_ = (rb) + (nt_ * 8 + g) * 72 + (kch) * 16 + 2 * tg;     \
        (dst)[nt_][0] = *(const unsigned*)(Xs + off_);                  \
        (dst)[nt_][1] = *(const unsigned*)(Xs + off_ + 8);              \
    } } while (0)

// ---------------- GRU 5x5 conv via mma.sync fp16; IC in 64-ch halves; B double-buffered ----------------
// mode: 0=enc zr (e2p ++ hp)  1=enc cand (e2p ++ rhp)  2=dec zr (hp)  3=dec cand (rhp)
// act_mode 0: sigmoid -> r->g_rhp, z->g_z; act_mode 1: tanh -> h update (+g_hsp)
template <int NH>
__global__ __launch_bounds__(256, 2) void gru2(int t, int mode, int nob, int wofs,
                                               const float* __restrict__ bias,
                                               int act_mode, int write_hs) {
    extern __shared__ unsigned short Xs[];   // [288 px][72] fp16 bits

    int b   = blockIdx.x;
    int y0  = blockIdx.y * 4;
    int och = blockIdx.z;
    int tid = threadIdx.x;
    int w   = tid >> 5, lane = tid & 31;
    int g   = lane >> 2, tg = lane & 3;
    int mw  = w >> 2, nw = w & 3;

    const unsigned short* s0p;
    const unsigned short* s1p;
    if (mode <= 1) {
        s0p = g_e2p + (b * 10 + t) * 65536;
        s1p = (mode == 0 ? g_hp : g_rhp) + b * 65536;
    } else {
        s0p = (mode == 2 ? g_hp : g_rhp) + b * 65536;
        s1p = s0p;
    }

    float D[2][4][4];
#pragma unroll
    for (int mt = 0; mt < 2; mt++)
#pragma unroll
        for (int nt = 0; nt < 4; nt++)
#pragma unroll
            for (int i = 0; i < 4; i++) D[mt][nt][i] = 0.f;

    const uint4* pw = reinterpret_cast<const uint4*>(g_wp) + (wofs >> 3);
    const int KC = NH * 4;
    const int S1 = nob * 32;
    const int S2 = (KC - 3) * nob * 32;
    const int ob0 = och * 4 + mw * 2;

#pragma unroll 1
    for (int h = 0; h < NH; h++) {
        if (h) __syncthreads();
        // ---- stage 64-ch half ----
        const unsigned short* base = (h == 0) ? s0p : s1p;
        int c = tid & 63;
#pragma unroll
        for (int it = 0; it < 2; it++) {
            int sy = (tid >> 6) | (it << 2);
            int yy = y0 - 2 + sy;
            bool rv = (unsigned)yy < 32u;
            const uint4* src = (const uint4*)(base + c * 1024 + yy * 32);
            uint4 q[4];
            if (rv) {
#pragma unroll
                for (int k2 = 0; k2 < 4; k2++) q[k2] = src[k2];
            } else {
#pragma unroll
                for (int k2 = 0; k2 < 4; k2++) q[k2] = make_uint4(0u, 0u, 0u, 0u);
            }
            const unsigned short* hv = (const unsigned short*)q;
            int rb = sy * 36;
#pragma unroll
            for (int sx = 0; sx < 36; sx++) {
                unsigned short v = (sx < 2 || sx >= 34) ? (unsigned short)0 : hv[sx - 2];
                Xs[(rb + sx) * 72 + c] = v;
            }
        }
        __syncthreads();

        // ---- MMA: taps x 4 kch, B double-buffered ----
        int fb = (h * 4 * nob + ob0) * 32 + lane;
        uint4 ah[2];
#pragma unroll
        for (int mt = 0; mt < 2; mt++) ah[mt] = pw[fb + mt * 32];
        unsigned Bp[2][4][2];
        LOADB(Bp[0], (nw * 36) * 72, 0);
#pragma unroll 1
        for (int tap = 0; tap < 25; tap++) {
            int dy = tap / 5, dx = tap - 5 * dy;
            int rowbase = ((nw + dy) * 36 + dx) * 72;
            int tapn = (tap < 24) ? tap + 1 : 24;
            int dyn = tapn / 5, dxn = tapn - 5 * dyn;
            int rowbasen = ((nw + dyn) * 36 + dxn) * 72;
#pragma unroll
            for (int kch = 0; kch < 4; kch++) {
                int fn = (tap == 24 && kch == 3) ? fb : fb + (kch < 3 ? S1 : S2);
                uint4 nah[2];
#pragma unroll
                for (int mt = 0; mt < 2; mt++) nah[mt] = pw[fn + mt * 32];
                if (kch < 3) { LOADB(Bp[(kch + 1) & 1], rowbase, kch + 1); }
                else         { LOADB(Bp[0], rowbasen, 0); }
#pragma unroll
                for (int mt = 0; mt < 2; mt++)
#pragma unroll
                    for (int nt = 0; nt < 4; nt++) mma_f16(D[mt][nt], ah[mt], Bp[kch & 1][nt]);
#pragma unroll
                for (int mt = 0; mt < 2; mt++) ah[mt] = nah[mt];
                fb = fn;
            }
        }
    }

    // ---- fused epilogue ----
    int y = y0 + nw;
#pragma unroll
    for (int mt = 0; mt < 2; mt++) {
#pragma unroll
        for (int ci2 = 0; ci2 < 2; ci2++) {
            int   ocG = och * 64 + mw * 32 + mt * 16 + g + 8 * ci2;
            float bv  = bias[ocG];
#pragma unroll
            for (int nt = 0; nt < 4; nt++) {
#pragma unroll
                for (int j = 0; j < 2; j++) {
                    float v  = D[mt][nt][ci2 * 2 + j] + bv;
                    int   x  = nt * 8 + 2 * tg + j;
                    int   px = y * 32 + x;
                    if (act_mode == 0) {
                        float s = 1.f / (1.f + expf(-v));
                        if (ocG < 64) {
                            int hi = (b * 64 + ocG) * 1024 + px;
                            g_rhp[hi] = h16(s * g_h[hi]);
                        } else {
                            g_z[(b * 64 + ocG - 64) * 1024 + px] = s;
                        }
                    } else {
                        float c  = tanhf(v);
                        int   hi = (b * 64 + ocG) * 1024 + px;
                        float z  = g_z[hi];
                        float hp = g_h[hi];
                        float hn = (1.f - z) * hp + z * c;
                        g_h[hi]  = hn;
                        g_hp[hi] = h16(hn);
                        if (write_hs) g_hsp[t * 2097152 + hi] = h16(hn);
                    }
                }
            }
        }
    }
}

// ---------------- deconv1 via mma.sync fp16: 64->32, 4x4 lhs_dil 2 pad 2, as 4 parity 2x2 convs ----------------
// CTA: (n image, 4-row strip of 32x32 input grid), 128 threads = 4 warps (nw=row).
__global__ __launch_bounds__(128) void deconv1_tc(const float* __restrict__ bias) {
    __shared__ unsigned short Xs[6 * 34 * 72];   // [tile row][tile col][64 ch]
    int n   = blockIdx.x;                        // t*32+b
    int y0  = blockIdx.y * 4;
    int tid = threadIdx.x;
    int w   = tid >> 5, lane = tid & 31;
    int g   = lane >> 2, tg = lane & 3;
    int nw  = w;

    // ---- stage input tile: rows y0-1 .. y0+4, cols -1..32, 64 ch fp16 ----
    const unsigned short* in = g_hsp + n * 65536;
    {
        int c = tid & 63, half = tid >> 6;
#pragma unroll
        for (int rr = 0; rr < 3; rr++) {
            int row = half + rr * 2;             // 0..5
            int yy = y0 - 1 + row;
            bool rv = (unsigned)yy < 32u;
            const uint4* src = (const uint4*)(in + c * 1024 + yy * 32);
            uint4 q[4];
            if (rv) {
#pragma unroll
                for (int k2 = 0; k2 < 4; k2++) q[k2] = src[k2];
            } else {
#pragma unroll
                for (int k2 = 0; k2 < 4; k2++) q[k2] = make_uint4(0u, 0u, 0u, 0u);
            }
            const unsigned short* hv = (const unsigned short*)q;
            int rb = row * 34;
            Xs[rb * 72 + c] = 0;
            Xs[(rb + 33) * 72 + c] = 0;
#pragma unroll
            for (int x = 0; x < 32; x++) Xs[(rb + 1 + x) * 72 + c] = hv[x];
        }
    }
    __syncthreads();

    const uint4* wd = reinterpret_cast<const uint4*>(g_wd1);

#pragma unroll 1
    for (int p = 0; p < 4; p++) {
        int a = p >> 1, bp = p & 1;
        float D[2][4][4];
#pragma unroll
        for (int mt = 0; mt < 2; mt++)
#pragma unroll
            for (int nt = 0; nt < 4; nt++)
#pragma unroll
                for (int i = 0; i < 4; i++) D[mt][nt][i] = 0.f;

#pragma unroll
        for (int tt = 0; tt < 4; tt++) {
            int jy = tt >> 1, jx = tt & 1;
            int rowbase = ((nw + a + jy) * 34 + (bp + jx)) * 72;
#pragma unroll
            for (int kc = 0; kc < 4; kc++) {
                uint4 a0 = wd[((((p * 4 + tt) * 4 + kc) * 2 + 0) * 32) + lane];
                uint4 a1 = wd[((((p * 4 + tt) * 4 + kc) * 2 + 1) * 32) + lane];
                unsigned Bs[4][2];
#pragma unroll
                for (int nt = 0; nt < 4; nt++) {
                    int off = rowbase + (nt * 8 + g) * 72 + kc * 16 + 2 * tg;
                    Bs[nt][0] = *(const unsigned*)(Xs + off);
                    Bs[nt][1] = *(const unsigned*)(Xs + off + 8);
                }
#pragma unroll
                for (int nt = 0; nt < 4; nt++) {
                    mma_f16(D[0][nt], a0, Bs[nt]);
                    mma_f16(D[1][nt], a1, Bs[nt]);
                }
            }
        }

        // epilogue for this parity
        int oy = 2 * (y0 + nw) + a;
#pragma unroll
        for (int mt = 0; mt < 2; mt++) {
#pragma unroll
            for (int ci2 = 0; ci2 < 2; ci2++) {
                int oc = mt * 16 + g + 8 * ci2;
                float bv = bias[oc];
#pragma unroll
                for (int nt = 0; nt < 4; nt++) {
#pragma unroll
                    for (int j = 0; j < 2; j++) {
                        float v = D[mt][nt][ci2 * 2 + j] + bv;
                        v = (v >= 0.f) ? v : 0.2f * v;
                        int ox = 2 * (nt * 8 + 2 * tg + j) + bp;
                        g_y1[(n * 32 + oc) * 4096 + oy * 64 + ox] = v;
                    }
                }
            }
        }
    }
}

// ---------------- encoder conv1: 1->16, 3x3 s2 p1, lrelu ----------------
__global__ __launch_bounds__(256) void enc_conv1(const float* __restrict__ x,
                                                 const float* __restrict__ w,
                                                 const float* __restrict__ bias) {
    __shared__ float sw[144], sb[16];
    int tid = threadIdx.x;
    if (tid < 144) sw[tid] = w[tid];
    if (tid < 16)  sb[tid] = bias[tid];
    __syncthreads();
    int n = blockIdx.x, p = blockIdx.y * 256 + tid;
    int oy = p >> 6, ox = p & 63;
    const float* xi = x + n * 16384;
    float win[9];
    int iy0 = 2 * oy - 1, ix0 = 2 * ox - 1;
#pragma unroll
    for (int ky = 0; ky < 3; ky++)
#pragma unroll
        for (int kx = 0; kx < 3; kx++) {
            int iy = iy0 + ky, ix = ix0 + kx;
            win[ky * 3 + kx] = ((unsigned)iy < 128u && (unsigned)ix < 128u) ? xi[iy * 128 + ix] : 0.f;
        }
#pragma unroll
    for (int oc = 0; oc < 16; oc++) {
        float a = sb[oc];
#pragma unroll
        for (int k = 0; k < 9; k++) a += sw[oc * 9 + k] * win[k];
        g_e1[(n * 16 + oc) * 4096 + p] = (a >= 0.f) ? a : 0.2f * a;
    }
}

// ---------------- encoder conv2: 16->64, 3x3 s2 p1, lrelu, emit fp16 ----------------
__global__ __launch_bounds__(256) void enc_conv2(const float* __restrict__ w,
                                                 const float* __restrict__ bias) {
    __shared__ float sw[9216];
    int tid = threadIdx.x;
    for (int i = tid; i < 9216; i += 256) sw[i] = w[i];
    __syncthreads();
    int n = blockIdx.x, p = blockIdx.y * 256 + tid;
    int oy = p >> 5, ox = p & 31;
    const float* in = g_e1 + n * 65536;
    float acc[64];
#pragma unroll
    for (int oc = 0; oc < 64; oc++) acc[oc] = bias[oc];
    int iy0 = 2 * oy - 1, ix0 = 2 * ox - 1;
#pragma unroll 1
    for (int ic = 0; ic < 16; ic++) {
        float win[9];
#pragma unroll
        for (int ky = 0; ky < 3; ky++)
#pragma unroll
            for (int kx = 0; kx < 3; kx++) {
                int iy = iy0 + ky, ix = ix0 + kx;
                win[ky * 3 + kx] = ((unsigned)iy < 64u && (unsigned)ix < 64u)
                                       ? in[ic * 4096 + iy * 64 + ix] : 0.f;
            }
#pragma unroll
        for (int oc = 0; oc < 64; oc++)
#pragma unroll
            for (int k = 0; k < 9; k++) acc[oc] += sw[(oc * 16 + ic) * 9 + k] * win[k];
    }
#pragma unroll
    for (int oc = 0; oc < 64; oc++) {
        float a = acc[oc];
        a = (a >= 0.f) ? a : 0.2f * a;
        g_e2p[(n * 64 + oc) * 1024 + p] = h16(a);
    }
}

// ---------------- deconv2: 32->1, 4x4 lhs_dil 2 pad 2, + transpose ----------------
__global__ __launch_bounds__(256) void deconv2(const float* __restrict__ w,
                                               const float* __restrict__ bias,
                                               float* __restrict__ out) {
    __shared__ float sw[512];
    int tid = threadIdx.x;
    for (int i = tid; i < 512; i += 256) sw[i] = w[i];
    __syncthreads();
    int n = blockIdx.x, p = blockIdx.y * 256 + tid;
    int oy = p >> 7, ox = p & 127;
    int ky0 = oy & 1, kx0 = ox & 1;
    int iyA = (oy + ky0 - 2) >> 1, iyB = iyA + 1;
    int ixA = (ox + kx0 - 2) >> 1, ixB = ixA + 1;
    bool yA = (unsigned)iyA < 64u, yB = (unsigned)iyB < 64u;
    bool xA = (unsigned)ixA < 64u, xB = (unsigned)ixB < 64u;
    const float* in = g_y1 + n * 131072;
    float acc = bias[0];
#pragma unroll 1
    for (int ic = 0; ic < 32; ic++) {
        const float* ip = in + ic * 4096;
        float vAA = (yA && xA) ? ip[iyA * 64 + ixA] : 0.f;
        float vAB = (yA && xB) ? ip[iyA * 64 + ixB] : 0.f;
        float vBA = (yB && xA) ? ip[iyB * 64 + ixA] : 0.f;
        float vBB = (yB && xB) ? ip[iyB * 64 + ixB] : 0.f;
        const float* wp = &sw[ic * 16];
        acc += wp[ky0 * 4 + kx0] * vAA + wp[ky0 * 4 + kx0 + 2] * vAB
             + wp[(ky0 + 2) * 4 + kx0] * vBA + wp[(ky0 + 2) * 4 + kx0 + 2] * vBB;
    }
    int t = n >> 5, b = n & 31;
    out[(b * 10 + t) * 16384 + p] = acc;
}

// ---------------- launch ----------------
extern "C" void kernel_launch(void* const* d_in, const int* in_sizes, int n_in,
                              void* d_out, int out_size) {
    const float* x           = (const float*)d_in[0];
    const float* enc_w1      = (const float*)d_in[1];
    const float* enc_b1      = (const float*)d_in[2];
    const float* enc_w2      = (const float*)d_in[3];
    const float* enc_b2      = (const float*)d_in[4];
    const float* enc_gru_wzr = (const float*)d_in[5];
    const float* enc_gru_bzr = (const float*)d_in[6];
    const float* enc_gru_wc  = (const float*)d_in[7];
    const float* enc_gru_bc  = (const float*)d_in[8];
    const float* dec_gru_wzr = (const float*)d_in[9];
    const float* dec_gru_bzr = (const float*)d_in[10];
    const float* dec_gru_wc  = (const float*)d_in[11];
    const float* dec_gru_bc  = (const float*)d_in[12];
    const float* dec_w1      = (const float*)d_in[13];
    const float* dec_b1      = (const float*)d_in[14];
    const float* dec_w2      = (const float*)d_in[15];
    const float* dec_b2      = (const float*)d_in[16];
    float* out = (float*)d_out;

    const int SMB = 288 * 72 * 2;   // 41472 B fp16 X tile
    cudaFuncSetAttribute(gru2<2>, cudaFuncAttributeMaxDynamicSharedMemorySize, SMB);
    cudaFuncSetAttribute(gru2<1>, cudaFuncAttributeMaxDynamicSharedMemorySize, SMB);

    init_all<<<(2097152 + 921600 + 32768 + 255) / 256, 256>>>(
        enc_gru_wzr, enc_gru_wc, dec_gru_wzr, dec_gru_wc, dec_w1);            // #1
    enc_conv1<<<dim3(320, 16), 256>>>(x, enc_w1, enc_b1);                     // #2
    enc_conv2<<<dim3(320, 4), 256>>>(enc_w2, enc_b2);                         // #3

    for (int t = 0; t < 10; t++) {                                            // #4,#5,#6(captured)...
        gru2<2><<<dim3(32, 8, 2), 256, SMB>>>(t, 0, 8, 0, enc_gru_bzr, 0, 0);
        gru2<2><<<dim3(32, 8, 1), 256, SMB>>>(t, 1, 4, 409600, enc_gru_bc, 1, 0);
    }
    for (int t = 0; t < 10; t++) {
        gru2<1><<<dim3(32, 8, 2), 256, SMB>>>(t, 2, 8, 614400, dec_gru_bzr, 0, 0);
        gru2<1><<<dim3(32, 8, 1), 256, SMB>>>(t, 3, 4, 819200, dec_gru_bc, 1, 1);
    }

    deconv1_tc<<<dim3(320, 8), 128>>>(dec_b1);
    deconv2<<<dim3(320, 64), 256>>>(dec_w2, dec_b2, out);
}